// round 1
// baseline (speedup 1.0000x reference)
#include <cuda_runtime.h>
#include <math.h>

#define N_  768
#define A_  768
#define S_  384
#define P_  128
#define H_  16
#define D_  48
#define NN  (N_*N_)

// ---------------- scratch (no allocations allowed) ----------------
__device__ float d_sn [N_*S_];
__device__ float d_an [N_*A_];
__device__ float d_g1 [N_*A_];
__device__ float d_g2 [N_*A_];
__device__ float d_a2 [N_*A_];
__device__ float d_q  [N_*A_];
__device__ float d_k  [N_*A_];
__device__ float d_v  [N_*A_];
__device__ float d_gt [N_*A_];          // sigmoid(a2 @ Wg)
__device__ float d_bias[H_*NN];         // [H][N][N]  (37.7 MB)
__device__ float d_o  [N_*A_];
__device__ float d_gate[N_*A_];         // sigmoid(s @ Wout + bout)

// ---------------- row LayerNorm ----------------
template<int COLS>
__global__ __launch_bounds__(256) void ln_kernel(const float* __restrict__ x,
                                                 const float* __restrict__ w,
                                                 float* __restrict__ y) {
    int row = blockIdx.x;
    const float* xr = x + (size_t)row * COLS;
    float s = 0.f, s2 = 0.f;
    for (int c = threadIdx.x; c < COLS; c += blockDim.x) {
        float v = xr[c]; s += v; s2 += v * v;
    }
    __shared__ float red[64];
    #pragma unroll
    for (int o = 16; o; o >>= 1) {
        s  += __shfl_xor_sync(0xffffffffu, s,  o);
        s2 += __shfl_xor_sync(0xffffffffu, s2, o);
    }
    int wid = threadIdx.x >> 5, lid = threadIdx.x & 31;
    if (lid == 0) { red[wid] = s; red[wid + 32] = s2; }
    __syncthreads();
    if (wid == 0) {
        s  = (lid < 8) ? red[lid]      : 0.f;
        s2 = (lid < 8) ? red[lid + 32] : 0.f;
        #pragma unroll
        for (int o = 4; o; o >>= 1) {
            s  += __shfl_xor_sync(0xffffffffu, s,  o);
            s2 += __shfl_xor_sync(0xffffffffu, s2, o);
        }
        if (lid == 0) { red[0] = s; red[1] = s2; }
    }
    __syncthreads();
    float mean = red[0] * (1.f / COLS);
    float var  = red[1] * (1.f / COLS) - mean * mean;
    float rs   = rsqrtf(var + 1e-5f);
    float* yr = y + (size_t)row * COLS;
    for (int c = threadIdx.x; c < COLS; c += blockDim.x) {
        float v = (xr[c] - mean) * rs;
        if (w) v *= w[c];
        yr[c] = v;
    }
}

// ---------------- a2 = sigmoid_gate * a_n + shift ----------------
__global__ void a2_kernel(const float* __restrict__ g1, const float* __restrict__ an,
                          const float* __restrict__ g2, float* __restrict__ a2) {
    int i = blockIdx.x * blockDim.x + threadIdx.x;
    if (i < N_ * A_) a2[i] = g1[i] * an[i] + g2[i];
}

// ---------------- tiled SGEMM with fused epilogues ----------------
// EPI: 0=none 1=+bias 2=sigmoid(x+bias) 3=sigmoid(x) 4=x*C2
template<int EPI>
__global__ __launch_bounds__(256) void gemm_kernel(const float* __restrict__ A,
                                                   const float* __restrict__ B,
                                                   float* __restrict__ C,
                                                   int M, int Nn, int K,
                                                   const float* __restrict__ bias,
                                                   const float* __restrict__ C2) {
    __shared__ __align__(16) float As[16][64];
    __shared__ __align__(16) float Bs[16][64];
    int m0 = blockIdx.y * 64, n0 = blockIdx.x * 64;
    int tid = threadIdx.x;
    int tx = tid & 15, ty = tid >> 4;

    int am = tid >> 2, ak = (tid & 3) * 4;   // A: 64 rows x 16 cols, float4 per thread
    int bk = tid >> 4, bn = (tid & 15) * 4;  // B: 16 rows x 64 cols

    float acc[4][4];
    #pragma unroll
    for (int i = 0; i < 4; i++)
        #pragma unroll
        for (int j = 0; j < 4; j++) acc[i][j] = 0.f;

    for (int kt = 0; kt < K; kt += 16) {
        const float4 av = *(const float4*)(A + (size_t)(m0 + am) * K + kt + ak);
        As[ak + 0][am] = av.x; As[ak + 1][am] = av.y;
        As[ak + 2][am] = av.z; As[ak + 3][am] = av.w;
        const float4 bv = *(const float4*)(B + (size_t)(kt + bk) * Nn + n0 + bn);
        *(float4*)&Bs[bk][bn] = bv;
        __syncthreads();
        #pragma unroll
        for (int kk = 0; kk < 16; kk++) {
            float af[4], bf[4];
            #pragma unroll
            for (int i = 0; i < 4; i++) af[i] = As[kk][ty * 4 + i];
            #pragma unroll
            for (int j = 0; j < 4; j++) bf[j] = Bs[kk][tx * 4 + j];
            #pragma unroll
            for (int i = 0; i < 4; i++)
                #pragma unroll
                for (int j = 0; j < 4; j++) acc[i][j] += af[i] * bf[j];
        }
        __syncthreads();
    }
    #pragma unroll
    for (int i = 0; i < 4; i++) {
        int row = m0 + ty * 4 + i;
        #pragma unroll
        for (int j = 0; j < 4; j++) {
            int col = n0 + tx * 4 + j;
            float v = acc[i][j];
            if (EPI == 1) v += bias[col];
            if (EPI == 2) v = 1.f / (1.f + __expf(-(v + bias[col])));
            if (EPI == 3) v = 1.f / (1.f + __expf(-v));
            if (EPI == 4) v *= C2[(size_t)row * Nn + col];
            C[(size_t)row * Nn + col] = v;
        }
    }
}

// ---------------- pair bias: LN(P=128) + proj(128->16) + beta ----------------
// one warp per (i,j); 8 warps/block cover 8 consecutive j (sector-friendly writes)
__global__ __launch_bounds__(256) void pairbias_kernel(const float* __restrict__ pair,
                                                       const float* __restrict__ beta,
                                                       const float* __restrict__ w,
                                                       const float* __restrict__ b,
                                                       const float* __restrict__ Wb,
                                                       float* __restrict__ bias) {
    __shared__ float sw[P_], sb[P_], sWb[P_ * H_];
    for (int i = threadIdx.x; i < P_; i += blockDim.x) { sw[i] = w[i]; sb[i] = b[i]; }
    for (int i = threadIdx.x; i < P_ * H_; i += blockDim.x) sWb[i] = Wb[i];
    __syncthreads();

    int warp = threadIdx.x >> 5, lane = threadIdx.x & 31;
    int p = blockIdx.x * 8 + warp;               // pair index < 768*768
    int i = p / N_, j = p - i * N_;

    const float4 x4 = *(const float4*)(pair + (size_t)p * P_ + lane * 4);
    float xs[4] = {x4.x, x4.y, x4.z, x4.w};
    float s = 0.f, s2 = 0.f;
    #pragma unroll
    for (int t = 0; t < 4; t++) { s += xs[t]; s2 += xs[t] * xs[t]; }
    #pragma unroll
    for (int o = 16; o; o >>= 1) {
        s  += __shfl_xor_sync(0xffffffffu, s,  o);
        s2 += __shfl_xor_sync(0xffffffffu, s2, o);
    }
    float mean = s * (1.f / P_);
    float var  = s2 * (1.f / P_) - mean * mean;
    float rs   = rsqrtf(var + 1e-5f);

    float acc[H_];
    #pragma unroll
    for (int h = 0; h < H_; h++) acc[h] = 0.f;
    #pragma unroll
    for (int t = 0; t < 4; t++) {
        int c = lane * 4 + t;
        float yv = (xs[t] - mean) * rs * sw[c] + sb[c];
        #pragma unroll
        for (int h = 0; h < H_; h++) acc[h] += yv * sWb[c * H_ + h];
    }
    #pragma unroll
    for (int h = 0; h < H_; h++)
        #pragma unroll
        for (int o = 16; o; o >>= 1)
            acc[h] += __shfl_xor_sync(0xffffffffu, acc[h], o);

    float bv = beta[(size_t)i * N_ + j];
    if (lane < H_)
        bias[(size_t)lane * NN + (size_t)i * N_ + j] = acc[lane] + bv;
}

// ---------------- flash attention (fp32, D=48), gate fused ----------------
__global__ __launch_bounds__(256) void attn_kernel(const float* __restrict__ q,
                                                   const float* __restrict__ k,
                                                   const float* __restrict__ v,
                                                   const float* __restrict__ bias,
                                                   const float* __restrict__ g,
                                                   float* __restrict__ o) {
    __shared__ float Qs[64][D_];
    __shared__ float KPs[64][65];   // K tile (48 cols) reused as P tile (64 cols)
    __shared__ float Vs[64][D_];
    int h  = blockIdx.y;
    int q0 = blockIdx.x * 64;
    int tid = threadIdx.x, tx = tid & 15, ty = tid >> 4;

    for (int idx = tid; idx < 64 * D_; idx += 256) {
        int r = idx / D_, d = idx % D_;
        Qs[r][d] = q[(size_t)(q0 + r) * A_ + h * D_ + d];
    }

    float m_i[4], l_i[4], acc[4][3];
    #pragma unroll
    for (int i = 0; i < 4; i++) {
        m_i[i] = -1e30f; l_i[i] = 0.f;
        #pragma unroll
        for (int j = 0; j < 3; j++) acc[i][j] = 0.f;
    }
    const float scale = rsqrtf((float)D_);

    for (int j0 = 0; j0 < N_; j0 += 64) {
        __syncthreads();   // previous PV done (and first-iter Q loaded)
        for (int idx = tid; idx < 64 * D_; idx += 256) {
            int r = idx / D_, d = idx % D_;
            KPs[r][d] = k[(size_t)(j0 + r) * A_ + h * D_ + d];
            Vs[r][d]  = v[(size_t)(j0 + r) * A_ + h * D_ + d];
        }
        __syncthreads();

        float sc[4][4];
        #pragma unroll
        for (int i = 0; i < 4; i++)
            #pragma unroll
            for (int j = 0; j < 4; j++) sc[i][j] = 0.f;
        #pragma unroll 8
        for (int d = 0; d < D_; d++) {
            float aq[4], bk[4];
            #pragma unroll
            for (int i = 0; i < 4; i++) aq[i] = Qs[ty * 4 + i][d];
            #pragma unroll
            for (int j = 0; j < 4; j++) bk[j] = KPs[tx * 4 + j][d];
            #pragma unroll
            for (int i = 0; i < 4; i++)
                #pragma unroll
                for (int j = 0; j < 4; j++) sc[i][j] += aq[i] * bk[j];
        }
        #pragma unroll
        for (int i = 0; i < 4; i++) {
            const float4 b4 = *(const float4*)(bias + (size_t)h * NN
                                + (size_t)(q0 + ty * 4 + i) * N_ + j0 + tx * 4);
            sc[i][0] = sc[i][0] * scale + b4.x;
            sc[i][1] = sc[i][1] * scale + b4.y;
            sc[i][2] = sc[i][2] * scale + b4.z;
            sc[i][3] = sc[i][3] * scale + b4.w;
        }
        __syncthreads();   // done reading K tile before overwriting with P

        #pragma unroll
        for (int i = 0; i < 4; i++) {
            float mx = fmaxf(fmaxf(sc[i][0], sc[i][1]), fmaxf(sc[i][2], sc[i][3]));
            #pragma unroll
            for (int o2 = 8; o2; o2 >>= 1)
                mx = fmaxf(mx, __shfl_xor_sync(0xffffffffu, mx, o2));
            float mnew = fmaxf(m_i[i], mx);
            float corr = __expf(m_i[i] - mnew);
            float rsum = 0.f;
            #pragma unroll
            for (int j = 0; j < 4; j++) { sc[i][j] = __expf(sc[i][j] - mnew); rsum += sc[i][j]; }
            #pragma unroll
            for (int o2 = 8; o2; o2 >>= 1)
                rsum += __shfl_xor_sync(0xffffffffu, rsum, o2);
            l_i[i] = l_i[i] * corr + rsum;
            m_i[i] = mnew;
            #pragma unroll
            for (int j = 0; j < 3; j++) acc[i][j] *= corr;
            #pragma unroll
            for (int j = 0; j < 4; j++) KPs[ty * 4 + i][tx * 4 + j] = sc[i][j];
        }
        __syncthreads();

        #pragma unroll 4
        for (int c = 0; c < 64; c++) {
            float vv[3];
            #pragma unroll
            for (int j = 0; j < 3; j++) vv[j] = Vs[c][tx * 3 + j];
            #pragma unroll
            for (int i = 0; i < 4; i++) {
                float pp = KPs[ty * 4 + i][c];
                #pragma unroll
                for (int j = 0; j < 3; j++) acc[i][j] += pp * vv[j];
            }
        }
    }

    #pragma unroll
    for (int i = 0; i < 4; i++) {
        float inv = 1.f / l_i[i];
        int row = q0 + ty * 4 + i;
        #pragma unroll
        for (int j = 0; j < 3; j++) {
            int d = tx * 3 + j;
            float gv = g[(size_t)row * A_ + h * D_ + d];
            o[(size_t)row * A_ + h * D_ + d] = acc[i][j] * inv * gv;
        }
    }
}

// ---------------- launch ----------------
extern "C" void kernel_launch(void* const* d_in, const int* in_sizes, int n_in,
                              void* d_out, int out_size) {
    const float* a       = (const float*)d_in[0];
    const float* s       = (const float*)d_in[1];
    const float* pair    = (const float*)d_in[2];
    const float* beta    = (const float*)d_in[3];
    const float* ln_s_w  = (const float*)d_in[4];
    const float* gamma_w = (const float*)d_in[5];
    const float* gamma_b = (const float*)d_in[6];
    const float* shift_w = (const float*)d_in[7];
    const float* Wq      = (const float*)d_in[8];
    const float* bq      = (const float*)d_in[9];
    const float* Wk      = (const float*)d_in[10];
    const float* Wv      = (const float*)d_in[11];
    const float* ln_p_w  = (const float*)d_in[12];
    const float* ln_p_b  = (const float*)d_in[13];
    const float* Wb      = (const float*)d_in[14];
    const float* Wg      = (const float*)d_in[15];
    const float* Wp      = (const float*)d_in[16];
    const float* Wout    = (const float*)d_in[17];
    const float* bout    = (const float*)d_in[18];
    float* out = (float*)d_out;

    float *p_sn, *p_an, *p_g1, *p_g2, *p_a2, *p_q, *p_k, *p_v, *p_gt, *p_bias, *p_o, *p_gate;
    cudaGetSymbolAddress((void**)&p_sn,   d_sn);
    cudaGetSymbolAddress((void**)&p_an,   d_an);
    cudaGetSymbolAddress((void**)&p_g1,   d_g1);
    cudaGetSymbolAddress((void**)&p_g2,   d_g2);
    cudaGetSymbolAddress((void**)&p_a2,   d_a2);
    cudaGetSymbolAddress((void**)&p_q,    d_q);
    cudaGetSymbolAddress((void**)&p_k,    d_k);
    cudaGetSymbolAddress((void**)&p_v,    d_v);
    cudaGetSymbolAddress((void**)&p_gt,   d_gt);
    cudaGetSymbolAddress((void**)&p_bias, d_bias);
    cudaGetSymbolAddress((void**)&p_o,    d_o);
    cudaGetSymbolAddress((void**)&p_gate, d_gate);

    dim3 g12(A_ / 64, N_ / 64);

    ln_kernel<S_><<<N_, 256>>>(s, ln_s_w, p_sn);
    ln_kernel<A_><<<N_, 256>>>(a, nullptr, p_an);
    gemm_kernel<2><<<g12, 256>>>(p_sn, gamma_w, p_g1, N_, A_, S_, gamma_b, nullptr);
    gemm_kernel<0><<<g12, 256>>>(p_sn, shift_w, p_g2, N_, A_, S_, nullptr, nullptr);
    a2_kernel<<<(N_ * A_ + 255) / 256, 256>>>(p_g1, p_an, p_g2, p_a2);
    gemm_kernel<1><<<g12, 256>>>(p_a2, Wq, p_q, N_, A_, A_, bq, nullptr);
    gemm_kernel<0><<<g12, 256>>>(p_a2, Wk, p_k, N_, A_, A_, nullptr, nullptr);
    gemm_kernel<0><<<g12, 256>>>(p_a2, Wv, p_v, N_, A_, A_, nullptr, nullptr);
    gemm_kernel<3><<<g12, 256>>>(p_a2, Wg, p_gt, N_, A_, A_, nullptr, nullptr);
    pairbias_kernel<<<NN / 8, 256>>>(pair, beta, ln_p_w, ln_p_b, Wb, p_bias);
    dim3 ga(N_ / 64, H_);
    attn_kernel<<<ga, 256>>>(p_q, p_k, p_v, p_bias, p_gt, p_o);
    gemm_kernel<2><<<g12, 256>>>(s, Wout, p_gate, N_, A_, S_, bout, nullptr);
    gemm_kernel<4><<<g12, 256>>>(p_o, Wp, out, N_, A_, A_, nullptr, p_gate);
}

// round 2
// speedup vs baseline: 3.2500x; 3.2500x over previous
#include <cuda_runtime.h>
#include <math.h>

#define N_  768
#define A_  768
#define S_  384
#define P_  128
#define H_  16
#define D_  48
#define NN  (N_*N_)

// ---------------- scratch (no allocations allowed) ----------------
__device__ float d_sn [N_*S_];
__device__ float d_an [N_*A_];
__device__ float d_g1 [N_*A_];
__device__ float d_g2 [N_*A_];
__device__ float d_a2 [N_*A_];
__device__ float d_q  [N_*A_];
__device__ float d_k  [N_*A_];
__device__ float d_v  [N_*A_];
__device__ float d_gt [N_*A_];          // sigmoid(a2 @ Wg)
__device__ float d_bias[H_*NN];         // [H][N][N]  (37.7 MB)
__device__ float d_o  [N_*A_];
__device__ float d_gate[N_*A_];         // sigmoid(s @ Wout + bout)

// ---------------- row LayerNorm ----------------
template<int COLS>
__global__ __launch_bounds__(256) void ln_kernel(const float* __restrict__ x,
                                                 const float* __restrict__ w,
                                                 float* __restrict__ y) {
    int row = blockIdx.x;
    const float* xr = x + (size_t)row * COLS;
    float s = 0.f, s2 = 0.f;
    for (int c = threadIdx.x; c < COLS; c += blockDim.x) {
        float v = xr[c]; s += v; s2 += v * v;
    }
    __shared__ float red[64];
    #pragma unroll
    for (int o = 16; o; o >>= 1) {
        s  += __shfl_xor_sync(0xffffffffu, s,  o);
        s2 += __shfl_xor_sync(0xffffffffu, s2, o);
    }
    int wid = threadIdx.x >> 5, lid = threadIdx.x & 31;
    if (lid == 0) { red[wid] = s; red[wid + 32] = s2; }
    __syncthreads();
    if (wid == 0) {
        s  = (lid < 8) ? red[lid]      : 0.f;
        s2 = (lid < 8) ? red[lid + 32] : 0.f;
        #pragma unroll
        for (int o = 4; o; o >>= 1) {
            s  += __shfl_xor_sync(0xffffffffu, s,  o);
            s2 += __shfl_xor_sync(0xffffffffu, s2, o);
        }
        if (lid == 0) { red[0] = s; red[1] = s2; }
    }
    __syncthreads();
    float mean = red[0] * (1.f / COLS);
    float var  = red[1] * (1.f / COLS) - mean * mean;
    float rs   = rsqrtf(var + 1e-5f);
    float* yr = y + (size_t)row * COLS;
    for (int c = threadIdx.x; c < COLS; c += blockDim.x) {
        float v = (xr[c] - mean) * rs;
        if (w) v *= w[c];
        yr[c] = v;
    }
}

// ---------------- a2 = sigmoid_gate * a_n + shift ----------------
__global__ void a2_kernel(const float* __restrict__ g1, const float* __restrict__ an,
                          const float* __restrict__ g2, float* __restrict__ a2) {
    int i = blockIdx.x * blockDim.x + threadIdx.x;
    if (i < N_ * A_) a2[i] = g1[i] * an[i] + g2[i];
}

// ---------------- tiled SGEMM with fused epilogues ----------------
// EPI: 0=none 1=+bias 2=sigmoid(x+bias) 3=sigmoid(x) 4=x*C2
template<int EPI>
__global__ __launch_bounds__(256) void gemm_kernel(const float* __restrict__ A,
                                                   const float* __restrict__ B,
                                                   float* __restrict__ C,
                                                   int M, int Nn, int K,
                                                   const float* __restrict__ bias,
                                                   const float* __restrict__ C2) {
    __shared__ __align__(16) float As[16][64];
    __shared__ __align__(16) float Bs[16][64];
    int m0 = blockIdx.y * 64, n0 = blockIdx.x * 64;
    int tid = threadIdx.x;
    int tx = tid & 15, ty = tid >> 4;

    int am = tid >> 2, ak = (tid & 3) * 4;   // A: 64 rows x 16 cols, float4 per thread
    int bk = tid >> 4, bn = (tid & 15) * 4;  // B: 16 rows x 64 cols

    float acc[4][4];
    #pragma unroll
    for (int i = 0; i < 4; i++)
        #pragma unroll
        for (int j = 0; j < 4; j++) acc[i][j] = 0.f;

    float4 av = *(const float4*)(A + (size_t)(m0 + am) * K + ak);
    float4 bv = *(const float4*)(B + (size_t)bk * Nn + n0 + bn);

    for (int kt = 0; kt < K; kt += 16) {
        As[ak + 0][am] = av.x; As[ak + 1][am] = av.y;
        As[ak + 2][am] = av.z; As[ak + 3][am] = av.w;
        *(float4*)&Bs[bk][bn] = bv;
        __syncthreads();
        if (kt + 16 < K) {
            av = *(const float4*)(A + (size_t)(m0 + am) * K + kt + 16 + ak);
            bv = *(const float4*)(B + (size_t)(kt + 16 + bk) * Nn + n0 + bn);
        }
        #pragma unroll
        for (int kk = 0; kk < 16; kk++) {
            float4 af = *(const float4*)&As[kk][ty * 4];
            float4 bf = *(const float4*)&Bs[kk][tx * 4];
            float a4[4] = {af.x, af.y, af.z, af.w};
            float b4[4] = {bf.x, bf.y, bf.z, bf.w};
            #pragma unroll
            for (int i = 0; i < 4; i++)
                #pragma unroll
                for (int j = 0; j < 4; j++) acc[i][j] += a4[i] * b4[j];
        }
        __syncthreads();
    }
    #pragma unroll
    for (int i = 0; i < 4; i++) {
        int row = m0 + ty * 4 + i;
        #pragma unroll
        for (int j = 0; j < 4; j++) {
            int col = n0 + tx * 4 + j;
            float v = acc[i][j];
            if (EPI == 1) v += bias[col];
            if (EPI == 2) v = 1.f / (1.f + __expf(-(v + bias[col])));
            if (EPI == 3) v = 1.f / (1.f + __expf(-v));
            if (EPI == 4) v *= C2[(size_t)row * Nn + col];
            C[(size_t)row * Nn + col] = v;
        }
    }
}

// ---------------- pair bias: LN(P=128) + proj(128->16) + beta ----------------
// persistent blocks; Wb in registers (no smem conflicts); 31-shuffle head reduce
__global__ __launch_bounds__(256) void pairbias_kernel(const float* __restrict__ pair,
                                                       const float* __restrict__ beta,
                                                       const float* __restrict__ w,
                                                       const float* __restrict__ b,
                                                       const float* __restrict__ Wb,
                                                       float* __restrict__ bias) {
    int lane = threadIdx.x & 31, warp = threadIdx.x >> 5;
    int c0 = lane * 4;

    // per-lane register copies (uniform across blocks; hits L1/L2)
    float wreg[4], breg[4], wb[4][H_];
    #pragma unroll
    for (int t = 0; t < 4; t++) {
        wreg[t] = __ldg(w + c0 + t);
        breg[t] = __ldg(b + c0 + t);
        #pragma unroll
        for (int h = 0; h < H_; h++)
            wb[t][h] = __ldg(Wb + (c0 + t) * H_ + h);
    }

    int stride = gridDim.x * 8;
    int p = blockIdx.x * 8 + warp;
    float4 x4 = make_float4(0.f, 0.f, 0.f, 0.f);
    if (p < NN) x4 = *(const float4*)(pair + (size_t)p * P_ + c0);

    for (; p < NN; p += stride) {
        int pn = p + stride;
        float4 nx4 = make_float4(0.f, 0.f, 0.f, 0.f);
        if (pn < NN) nx4 = *(const float4*)(pair + (size_t)pn * P_ + c0);
        float bv = __ldg(beta + p);

        float xs[4] = {x4.x, x4.y, x4.z, x4.w};
        float s = 0.f, s2 = 0.f;
        #pragma unroll
        for (int t = 0; t < 4; t++) { s += xs[t]; s2 += xs[t] * xs[t]; }
        #pragma unroll
        for (int o = 16; o; o >>= 1) {
            s  += __shfl_xor_sync(0xffffffffu, s,  o);
            s2 += __shfl_xor_sync(0xffffffffu, s2, o);
        }
        float mean = s * (1.f / P_);
        float var  = s2 * (1.f / P_) - mean * mean;
        float rs   = rsqrtf(var + 1e-5f);

        float acc[H_];
        #pragma unroll
        for (int h = 0; h < H_; h++) acc[h] = 0.f;
        #pragma unroll
        for (int t = 0; t < 4; t++) {
            float yv = (xs[t] - mean) * rs * wreg[t] + breg[t];
            #pragma unroll
            for (int h = 0; h < H_; h++) acc[h] += yv * wb[t][h];
        }

        // packed reduction: 16 values across 32 lanes in 31 shuffles.
        // after it, lane L holds head (L & 15) in acc[0].
        #pragma unroll
        for (int h = 0; h < 16; h++) acc[h] += __shfl_xor_sync(0xffffffffu, acc[h], 16);
        #pragma unroll
        for (int h = 0; h < 8; h++) {
            float lo = acc[h], hi = acc[h + 8];
            float send = (lane & 8) ? lo : hi;
            float got = __shfl_xor_sync(0xffffffffu, send, 8);
            acc[h] = ((lane & 8) ? hi : lo) + got;
        }
        #pragma unroll
        for (int h = 0; h < 4; h++) {
            float lo = acc[h], hi = acc[h + 4];
            float send = (lane & 4) ? lo : hi;
            float got = __shfl_xor_sync(0xffffffffu, send, 4);
            acc[h] = ((lane & 4) ? hi : lo) + got;
        }
        #pragma unroll
        for (int h = 0; h < 2; h++) {
            float lo = acc[h], hi = acc[h + 2];
            float send = (lane & 2) ? lo : hi;
            float got = __shfl_xor_sync(0xffffffffu, send, 2);
            acc[h] = ((lane & 2) ? hi : lo) + got;
        }
        {
            float lo = acc[0], hi = acc[1];
            float send = (lane & 1) ? lo : hi;
            float got = __shfl_xor_sync(0xffffffffu, send, 1);
            acc[0] = ((lane & 1) ? hi : lo) + got;
        }

        if (lane < H_)
            bias[(size_t)lane * NN + p] = acc[0] + bv;
        x4 = nx4;
    }
}

// ---------------- flash attention (fp32, D=48), gate fused ----------------
// dyn smem: Qs[64][52] Ks[64][52] Vs[64][52] Ps[64][64]
#define QS(r,c) smQ[(r)*52+(c)]
#define KS(r,c) smK[(r)*52+(c)]
#define VS(r,c) smV[(r)*52+(c)]
#define PS(r,c) smP[(r)*64+(c)]
#define ATTN_SMEM ((3*64*52 + 64*64)*4)

__global__ __launch_bounds__(256) void attn_kernel(const float* __restrict__ q,
                                                   const float* __restrict__ k,
                                                   const float* __restrict__ v,
                                                   const float* __restrict__ bias,
                                                   const float* __restrict__ g,
                                                   float* __restrict__ o) {
    extern __shared__ float sm[];
    float* smQ = sm;
    float* smK = sm + 64 * 52;
    float* smV = sm + 2 * 64 * 52;
    float* smP = sm + 3 * 64 * 52;

    int h  = blockIdx.y;
    int q0 = blockIdx.x * 64;
    int tid = threadIdx.x, tx = tid & 15, ty = tid >> 4;
    int dx = tx * 3;

    // load Q tile (row-major, float4, conflict-free)
    #pragma unroll
    for (int it = 0; it < 3; it++) {
        int idx = tid + it * 256;
        int r = idx / 12, c4 = idx % 12;
        float4 v4 = *(const float4*)(q + (size_t)(q0 + r) * A_ + h * D_ + c4 * 4);
        *(float4*)&QS(r, c4 * 4) = v4;
    }

    float m_i[4], l_i[4], acc[4][3];
    #pragma unroll
    for (int i = 0; i < 4; i++) {
        m_i[i] = -1e30f; l_i[i] = 0.f;
        #pragma unroll
        for (int j = 0; j < 3; j++) acc[i][j] = 0.f;
    }
    const float scale = 0.144337567f;   // 1/sqrt(48)

    for (int j0 = 0; j0 < N_; j0 += 64) {
        __syncthreads();   // prev PV done (and Q fill on first iter)
        #pragma unroll
        for (int it = 0; it < 3; it++) {
            int idx = tid + it * 256;
            int r = idx / 12, c4 = idx % 12;
            float4 kv4 = *(const float4*)(k + (size_t)(j0 + r) * A_ + h * D_ + c4 * 4);
            *(float4*)&KS(r, c4 * 4) = kv4;
            float4 vv4 = *(const float4*)(v + (size_t)(j0 + r) * A_ + h * D_ + c4 * 4);
            *(float4*)&VS(r, c4 * 4) = vv4;
        }
        __syncthreads();

        // QK^T dot products: q-rows ty*4+i, k-cols tx+16*j (bank-friendly)
        float sc[4][4];
        #pragma unroll
        for (int i = 0; i < 4; i++)
            #pragma unroll
            for (int j = 0; j < 4; j++) sc[i][j] = 0.f;

        #pragma unroll
        for (int d4 = 0; d4 < 12; d4++) {
            float qm[4][4], km[4][4];
            #pragma unroll
            for (int i = 0; i < 4; i++) {
                float4 t4 = *(const float4*)&QS(ty * 4 + i, d4 * 4);
                qm[i][0] = t4.x; qm[i][1] = t4.y; qm[i][2] = t4.z; qm[i][3] = t4.w;
            }
            #pragma unroll
            for (int j = 0; j < 4; j++) {
                float4 t4 = *(const float4*)&KS(tx + 16 * j, d4 * 4);
                km[j][0] = t4.x; km[j][1] = t4.y; km[j][2] = t4.z; km[j][3] = t4.w;
            }
            #pragma unroll
            for (int dd = 0; dd < 4; dd++)
                #pragma unroll
                for (int i = 0; i < 4; i++)
                    #pragma unroll
                    for (int j = 0; j < 4; j++)
                        sc[i][j] += qm[i][dd] * km[j][dd];
        }

        // add bias
        #pragma unroll
        for (int i = 0; i < 4; i++) {
            const float* bp = bias + (size_t)h * NN + (size_t)(q0 + ty * 4 + i) * N_ + j0;
            #pragma unroll
            for (int j = 0; j < 4; j++)
                sc[i][j] = sc[i][j] * scale + __ldg(bp + tx + 16 * j);
        }

        // online softmax, write P
        #pragma unroll
        for (int i = 0; i < 4; i++) {
            float mx = fmaxf(fmaxf(sc[i][0], sc[i][1]), fmaxf(sc[i][2], sc[i][3]));
            #pragma unroll
            for (int o2 = 8; o2; o2 >>= 1)
                mx = fmaxf(mx, __shfl_xor_sync(0xffffffffu, mx, o2));
            float mnew = fmaxf(m_i[i], mx);
            float corr = __expf(m_i[i] - mnew);
            m_i[i] = mnew;
            float rsum = 0.f;
            #pragma unroll
            for (int j = 0; j < 4; j++) { sc[i][j] = __expf(sc[i][j] - mnew); rsum += sc[i][j]; }
            #pragma unroll
            for (int o2 = 8; o2; o2 >>= 1)
                rsum += __shfl_xor_sync(0xffffffffu, rsum, o2);
            l_i[i] = l_i[i] * corr + rsum;
            #pragma unroll
            for (int j = 0; j < 3; j++) acc[i][j] *= corr;
            #pragma unroll
            for (int j = 0; j < 4; j++) PS(ty * 4 + i, tx + 16 * j) = sc[i][j];
        }
        __syncthreads();

        // PV: acc[i][j] += sum_c P[i][c] * V[c][dx+j]
        #pragma unroll 4
        for (int c4 = 0; c4 < 16; c4++) {
            float pm[4][4];
            #pragma unroll
            for (int i = 0; i < 4; i++) {
                float4 t4 = *(const float4*)&PS(ty * 4 + i, c4 * 4);
                pm[i][0] = t4.x; pm[i][1] = t4.y; pm[i][2] = t4.z; pm[i][3] = t4.w;
            }
            #pragma unroll
            for (int cc = 0; cc < 4; cc++) {
                float vv[3];
                #pragma unroll
                for (int j = 0; j < 3; j++) vv[j] = VS(c4 * 4 + cc, dx + j);
                #pragma unroll
                for (int i = 0; i < 4; i++)
                    #pragma unroll
                    for (int j = 0; j < 3; j++) acc[i][j] += pm[i][cc] * vv[j];
            }
        }
    }

    #pragma unroll
    for (int i = 0; i < 4; i++) {
        float inv = 1.f / l_i[i];
        int row = q0 + ty * 4 + i;
        #pragma unroll
        for (int j = 0; j < 3; j++) {
            int d = dx + j;
            float gv = g[(size_t)row * A_ + h * D_ + d];
            o[(size_t)row * A_ + h * D_ + d] = acc[i][j] * inv * gv;
        }
    }
}

// ---------------- launch ----------------
extern "C" void kernel_launch(void* const* d_in, const int* in_sizes, int n_in,
                              void* d_out, int out_size) {
    const float* a       = (const float*)d_in[0];
    const float* s       = (const float*)d_in[1];
    const float* pair    = (const float*)d_in[2];
    const float* beta    = (const float*)d_in[3];
    const float* ln_s_w  = (const float*)d_in[4];
    const float* gamma_w = (const float*)d_in[5];
    const float* gamma_b = (const float*)d_in[6];
    const float* shift_w = (const float*)d_in[7];
    const float* Wq      = (const float*)d_in[8];
    const float* bq      = (const float*)d_in[9];
    const float* Wk      = (const float*)d_in[10];
    const float* Wv      = (const float*)d_in[11];
    const float* ln_p_w  = (const float*)d_in[12];
    const float* ln_p_b  = (const float*)d_in[13];
    const float* Wb      = (const float*)d_in[14];
    const float* Wg      = (const float*)d_in[15];
    const float* Wp      = (const float*)d_in[16];
    const float* Wout    = (const float*)d_in[17];
    const float* bout    = (const float*)d_in[18];
    float* out = (float*)d_out;

    float *p_sn, *p_an, *p_g1, *p_g2, *p_a2, *p_q, *p_k, *p_v, *p_gt, *p_bias, *p_o, *p_gate;
    cudaGetSymbolAddress((void**)&p_sn,   d_sn);
    cudaGetSymbolAddress((void**)&p_an,   d_an);
    cudaGetSymbolAddress((void**)&p_g1,   d_g1);
    cudaGetSymbolAddress((void**)&p_g2,   d_g2);
    cudaGetSymbolAddress((void**)&p_a2,   d_a2);
    cudaGetSymbolAddress((void**)&p_q,    d_q);
    cudaGetSymbolAddress((void**)&p_k,    d_k);
    cudaGetSymbolAddress((void**)&p_v,    d_v);
    cudaGetSymbolAddress((void**)&p_gt,   d_gt);
    cudaGetSymbolAddress((void**)&p_bias, d_bias);
    cudaGetSymbolAddress((void**)&p_o,    d_o);
    cudaGetSymbolAddress((void**)&p_gate, d_gate);

    cudaFuncSetAttribute(attn_kernel, cudaFuncAttributeMaxDynamicSharedMemorySize, ATTN_SMEM);

    dim3 g12(A_ / 64, N_ / 64);

    pairbias_kernel<<<296, 256>>>(pair, beta, ln_p_w, ln_p_b, Wb, p_bias);
    ln_kernel<S_><<<N_, 256>>>(s, ln_s_w, p_sn);
    ln_kernel<A_><<<N_, 256>>>(a, nullptr, p_an);
    gemm_kernel<2><<<g12, 256>>>(p_sn, gamma_w, p_g1, N_, A_, S_, gamma_b, nullptr);
    gemm_kernel<0><<<g12, 256>>>(p_sn, shift_w, p_g2, N_, A_, S_, nullptr, nullptr);
    a2_kernel<<<(N_ * A_ + 255) / 256, 256>>>(p_g1, p_an, p_g2, p_a2);
    gemm_kernel<1><<<g12, 256>>>(p_a2, Wq, p_q, N_, A_, A_, bq, nullptr);
    gemm_kernel<0><<<g12, 256>>>(p_a2, Wk, p_k, N_, A_, A_, nullptr, nullptr);
    gemm_kernel<0><<<g12, 256>>>(p_a2, Wv, p_v, N_, A_, A_, nullptr, nullptr);
    gemm_kernel<3><<<g12, 256>>>(p_a2, Wg, p_gt, N_, A_, A_, nullptr, nullptr);
    dim3 ga(N_ / 64, H_);
    attn_kernel<<<ga, 256, ATTN_SMEM>>>(p_q, p_k, p_v, p_bias, p_gt, p_o);
    gemm_kernel<2><<<g12, 256>>>(s, Wout, p_gate, N_, A_, S_, bout, nullptr);
    gemm_kernel<4><<<g12, 256>>>(p_o, Wp, out, N_, A_, A_, nullptr, p_gate);
}

// round 3
// speedup vs baseline: 4.5688x; 1.4058x over previous
#include <cuda_runtime.h>
#include <math.h>
#include <stdint.h>

#define N_  768
#define A_  768
#define S_  384
#define P_  128
#define H_  16
#define D_  48
#define NN  (N_*N_)

// ---------------- scratch (no allocations allowed) ----------------
__device__ float d_sn [N_*S_];
__device__ float d_an [N_*A_];
__device__ float d_a2 [N_*A_];
__device__ float d_q  [N_*A_];
__device__ float d_k  [N_*A_];
__device__ float d_v  [N_*A_];
__device__ float d_gt [N_*A_];          // sigmoid(a2 @ Wg)
__device__ float d_bias[H_*NN];         // [H][N][N]  (37.7 MB)
__device__ float d_o  [N_*A_];
__device__ float d_gate[N_*A_];         // sigmoid(s @ Wout + bout)

// ---------------- helpers ----------------
__device__ __forceinline__ uint32_t f2tf(float f) {
    uint32_t u;
    asm("cvt.rna.tf32.f32 %0, %1;" : "=r"(u) : "f"(f));
    return u;
}
__device__ __forceinline__ void mma_tf32(float* c, const uint32_t* a, const uint32_t* b) {
    asm volatile("mma.sync.aligned.m16n8k8.row.col.f32.tf32.tf32.f32 "
                 "{%0,%1,%2,%3}, {%4,%5,%6,%7}, {%8,%9}, {%0,%1,%2,%3};"
                 : "+f"(c[0]), "+f"(c[1]), "+f"(c[2]), "+f"(c[3])
                 : "r"(a[0]), "r"(a[1]), "r"(a[2]), "r"(a[3]), "r"(b[0]), "r"(b[1]));
}
__device__ __forceinline__ float sigm(float x) { return 1.f / (1.f + __expf(-x)); }

// ---------------- row LayerNorm ----------------
template<int COLS>
__global__ __launch_bounds__(256) void ln_kernel(const float* __restrict__ x,
                                                 const float* __restrict__ w,
                                                 float* __restrict__ y) {
    int row = blockIdx.x;
    const float* xr = x + (size_t)row * COLS;
    float s = 0.f, s2 = 0.f;
    for (int c = threadIdx.x; c < COLS; c += blockDim.x) {
        float v = xr[c]; s += v; s2 += v * v;
    }
    __shared__ float red[64];
    #pragma unroll
    for (int o = 16; o; o >>= 1) {
        s  += __shfl_xor_sync(0xffffffffu, s,  o);
        s2 += __shfl_xor_sync(0xffffffffu, s2, o);
    }
    int wid = threadIdx.x >> 5, lid = threadIdx.x & 31;
    if (lid == 0) { red[wid] = s; red[wid + 32] = s2; }
    __syncthreads();
    if (wid == 0) {
        s  = (lid < 8) ? red[lid]      : 0.f;
        s2 = (lid < 8) ? red[lid + 32] : 0.f;
        #pragma unroll
        for (int o = 4; o; o >>= 1) {
            s  += __shfl_xor_sync(0xffffffffu, s,  o);
            s2 += __shfl_xor_sync(0xffffffffu, s2, o);
        }
        if (lid == 0) { red[0] = s; red[1] = s2; }
    }
    __syncthreads();
    float mean = red[0] * (1.f / COLS);
    float var  = red[1] * (1.f / COLS) - mean * mean;
    float rs   = rsqrtf(var + 1e-5f);
    float* yr = y + (size_t)row * COLS;
    for (int c = threadIdx.x; c < COLS; c += blockDim.x) {
        float v = (xr[c] - mean) * rs;
        if (w) v *= w[c];
        yr[c] = v;
    }
}

// ============ TF32 GEMM core macros (64x64 tile, BK=32, 256 thr) ============
// smem: As[64][36] (m-major, bank=4g+t conflict-free), Bs[32][72] (k-major, bank=8t+g)

// ---------------- generic tf32 GEMM with epilogues ----------------
// EPI: 1=+bias 2=sigmoid(x+bias) 4=x*C2
template<int EPI>
__global__ __launch_bounds__(256) void gemm_tf32(const float* __restrict__ A,
                                                 const float* __restrict__ B,
                                                 float* __restrict__ C,
                                                 int K, int Nn,
                                                 const float* __restrict__ bias,
                                                 const float* __restrict__ C2) {
    __shared__ uint32_t As[64][36];
    __shared__ uint32_t Bs[32][72];
    int m0 = blockIdx.y * 64, n0 = blockIdx.x * 64;
    int tid = threadIdx.x, lane = tid & 31, warp = tid >> 5;
    int wm = (warp & 3) * 16, wn = (warp >> 2) * 32;
    int g = lane >> 2, t = lane & 3;

    int am = tid >> 3, akq = tid & 7;    // A: rows am, am+32 ; k-float4 akq
    int bk = tid >> 4, bn4 = tid & 15;   // B: k-rows bk, bk+16 ; n-float4 bn4

    float4 pa[2], pb[2];
    #pragma unroll
    for (int it = 0; it < 2; it++) {
        pa[it] = *(const float4*)(A + (size_t)(m0 + am + it * 32) * K + akq * 4);
        pb[it] = *(const float4*)(B + (size_t)(bk + it * 16) * Nn + n0 + bn4 * 4);
    }

    float acc[4][4];
    #pragma unroll
    for (int i = 0; i < 4; i++)
        #pragma unroll
        for (int j = 0; j < 4; j++) acc[i][j] = 0.f;

    for (int kt = 0; kt < K; kt += 32) {
        __syncthreads();
        #pragma unroll
        for (int it = 0; it < 2; it++) {
            uint32_t* ap = &As[am + it * 32][akq * 4];
            ap[0] = f2tf(pa[it].x); ap[1] = f2tf(pa[it].y);
            ap[2] = f2tf(pa[it].z); ap[3] = f2tf(pa[it].w);
            uint32_t* bp = &Bs[bk + it * 16][bn4 * 4];
            bp[0] = f2tf(pb[it].x); bp[1] = f2tf(pb[it].y);
            bp[2] = f2tf(pb[it].z); bp[3] = f2tf(pb[it].w);
        }
        __syncthreads();
        if (kt + 32 < K) {
            #pragma unroll
            for (int it = 0; it < 2; it++) {
                pa[it] = *(const float4*)(A + (size_t)(m0 + am + it * 32) * K + kt + 32 + akq * 4);
                pb[it] = *(const float4*)(B + (size_t)(kt + 32 + bk + it * 16) * Nn + n0 + bn4 * 4);
            }
        }
        #pragma unroll
        for (int k8 = 0; k8 < 32; k8 += 8) {
            uint32_t a[4] = {As[wm + g][k8 + t],     As[wm + g + 8][k8 + t],
                             As[wm + g][k8 + t + 4], As[wm + g + 8][k8 + t + 4]};
            #pragma unroll
            for (int nt = 0; nt < 4; nt++) {
                uint32_t b[2] = {Bs[k8 + t][wn + nt * 8 + g], Bs[k8 + t + 4][wn + nt * 8 + g]};
                mma_tf32(acc[nt], a, b);
            }
        }
    }
    #pragma unroll
    for (int nt = 0; nt < 4; nt++) {
        int col = n0 + wn + nt * 8 + t * 2;
        #pragma unroll
        for (int half = 0; half < 2; half++) {
            int row = m0 + wm + g + half * 8;
            float v0 = acc[nt][half * 2 + 0], v1 = acc[nt][half * 2 + 1];
            if (EPI == 1) { v0 += bias[col]; v1 += bias[col + 1]; }
            if (EPI == 2) { v0 = sigm(v0 + bias[col]); v1 = sigm(v1 + bias[col + 1]); }
            if (EPI == 4) { v0 *= C2[(size_t)row * Nn + col]; v1 *= C2[(size_t)row * Nn + col + 1]; }
            C[(size_t)row * Nn + col]     = v0;
            C[(size_t)row * Nn + col + 1] = v1;
        }
    }
}

// ---------------- fused AdaLN: a2 = sigmoid(sn@gamma_w + gb)*an + sn@shift_w ----
__global__ __launch_bounds__(256) void adaln_tf32(const float* __restrict__ SN,
                                                  const float* __restrict__ Wgam,
                                                  const float* __restrict__ gb,
                                                  const float* __restrict__ Wsh,
                                                  const float* __restrict__ AN,
                                                  float* __restrict__ A2) {
    __shared__ uint32_t As[64][36];
    __shared__ uint32_t B1s[32][72];
    __shared__ uint32_t B2s[32][72];
    const int K = S_, Nn = A_;
    int m0 = blockIdx.y * 64, n0 = blockIdx.x * 64;
    int tid = threadIdx.x, lane = tid & 31, warp = tid >> 5;
    int wm = (warp & 3) * 16, wn = (warp >> 2) * 32;
    int g = lane >> 2, t = lane & 3;

    int am = tid >> 3, akq = tid & 7;
    int bk = tid >> 4, bn4 = tid & 15;

    float4 pa[2], pb1[2], pb2[2];
    #pragma unroll
    for (int it = 0; it < 2; it++) {
        pa[it]  = *(const float4*)(SN   + (size_t)(m0 + am + it * 32) * K + akq * 4);
        pb1[it] = *(const float4*)(Wgam + (size_t)(bk + it * 16) * Nn + n0 + bn4 * 4);
        pb2[it] = *(const float4*)(Wsh  + (size_t)(bk + it * 16) * Nn + n0 + bn4 * 4);
    }
    float acc1[4][4], acc2[4][4];
    #pragma unroll
    for (int i = 0; i < 4; i++)
        #pragma unroll
        for (int j = 0; j < 4; j++) { acc1[i][j] = 0.f; acc2[i][j] = 0.f; }

    for (int kt = 0; kt < K; kt += 32) {
        __syncthreads();
        #pragma unroll
        for (int it = 0; it < 2; it++) {
            uint32_t* ap = &As[am + it * 32][akq * 4];
            ap[0] = f2tf(pa[it].x); ap[1] = f2tf(pa[it].y);
            ap[2] = f2tf(pa[it].z); ap[3] = f2tf(pa[it].w);
            uint32_t* b1 = &B1s[bk + it * 16][bn4 * 4];
            b1[0] = f2tf(pb1[it].x); b1[1] = f2tf(pb1[it].y);
            b1[2] = f2tf(pb1[it].z); b1[3] = f2tf(pb1[it].w);
            uint32_t* b2 = &B2s[bk + it * 16][bn4 * 4];
            b2[0] = f2tf(pb2[it].x); b2[1] = f2tf(pb2[it].y);
            b2[2] = f2tf(pb2[it].z); b2[3] = f2tf(pb2[it].w);
        }
        __syncthreads();
        if (kt + 32 < K) {
            #pragma unroll
            for (int it = 0; it < 2; it++) {
                pa[it]  = *(const float4*)(SN   + (size_t)(m0 + am + it * 32) * K + kt + 32 + akq * 4);
                pb1[it] = *(const float4*)(Wgam + (size_t)(kt + 32 + bk + it * 16) * Nn + n0 + bn4 * 4);
                pb2[it] = *(const float4*)(Wsh  + (size_t)(kt + 32 + bk + it * 16) * Nn + n0 + bn4 * 4);
            }
        }
        #pragma unroll
        for (int k8 = 0; k8 < 32; k8 += 8) {
            uint32_t a[4] = {As[wm + g][k8 + t],     As[wm + g + 8][k8 + t],
                             As[wm + g][k8 + t + 4], As[wm + g + 8][k8 + t + 4]};
            #pragma unroll
            for (int nt = 0; nt < 4; nt++) {
                uint32_t b1[2] = {B1s[k8 + t][wn + nt * 8 + g], B1s[k8 + t + 4][wn + nt * 8 + g]};
                mma_tf32(acc1[nt], a, b1);
                uint32_t b2[2] = {B2s[k8 + t][wn + nt * 8 + g], B2s[k8 + t + 4][wn + nt * 8 + g]};
                mma_tf32(acc2[nt], a, b2);
            }
        }
    }
    #pragma unroll
    for (int nt = 0; nt < 4; nt++) {
        int col = n0 + wn + nt * 8 + t * 2;
        #pragma unroll
        for (int half = 0; half < 2; half++) {
            int row = m0 + wm + g + half * 8;
            #pragma unroll
            for (int e = 0; e < 2; e++) {
                float gv = sigm(acc1[nt][half * 2 + e] + gb[col + e]);
                float a2 = gv * AN[(size_t)row * Nn + col + e] + acc2[nt][half * 2 + e];
                A2[(size_t)row * Nn + col + e] = a2;
            }
        }
    }
}

// ---------------- fused QKVG: one launch, z selects weight/epilogue ----------
__global__ __launch_bounds__(256) void qkvg_tf32(const float* __restrict__ A2,
                                                 const float* __restrict__ Wq,
                                                 const float* __restrict__ bq,
                                                 const float* __restrict__ Wk,
                                                 const float* __restrict__ Wv,
                                                 const float* __restrict__ Wg,
                                                 float* __restrict__ oq, float* __restrict__ ok,
                                                 float* __restrict__ ov, float* __restrict__ og) {
    __shared__ uint32_t As[64][36];
    __shared__ uint32_t Bs[32][72];
    const int K = A_, Nn = A_;
    int z = blockIdx.z;
    const float* B = (z == 0) ? Wq : (z == 1) ? Wk : (z == 2) ? Wv : Wg;
    float* C = (z == 0) ? oq : (z == 1) ? ok : (z == 2) ? ov : og;

    int m0 = blockIdx.y * 64, n0 = blockIdx.x * 64;
    int tid = threadIdx.x, lane = tid & 31, warp = tid >> 5;
    int wm = (warp & 3) * 16, wn = (warp >> 2) * 32;
    int g = lane >> 2, t = lane & 3;
    int am = tid >> 3, akq = tid & 7;
    int bk = tid >> 4, bn4 = tid & 15;

    float4 pa[2], pb[2];
    #pragma unroll
    for (int it = 0; it < 2; it++) {
        pa[it] = *(const float4*)(A2 + (size_t)(m0 + am + it * 32) * K + akq * 4);
        pb[it] = *(const float4*)(B + (size_t)(bk + it * 16) * Nn + n0 + bn4 * 4);
    }
    float acc[4][4];
    #pragma unroll
    for (int i = 0; i < 4; i++)
        #pragma unroll
        for (int j = 0; j < 4; j++) acc[i][j] = 0.f;

    for (int kt = 0; kt < K; kt += 32) {
        __syncthreads();
        #pragma unroll
        for (int it = 0; it < 2; it++) {
            uint32_t* ap = &As[am + it * 32][akq * 4];
            ap[0] = f2tf(pa[it].x); ap[1] = f2tf(pa[it].y);
            ap[2] = f2tf(pa[it].z); ap[3] = f2tf(pa[it].w);
            uint32_t* bp = &Bs[bk + it * 16][bn4 * 4];
            bp[0] = f2tf(pb[it].x); bp[1] = f2tf(pb[it].y);
            bp[2] = f2tf(pb[it].z); bp[3] = f2tf(pb[it].w);
        }
        __syncthreads();
        if (kt + 32 < K) {
            #pragma unroll
            for (int it = 0; it < 2; it++) {
                pa[it] = *(const float4*)(A2 + (size_t)(m0 + am + it * 32) * K + kt + 32 + akq * 4);
                pb[it] = *(const float4*)(B + (size_t)(kt + 32 + bk + it * 16) * Nn + n0 + bn4 * 4);
            }
        }
        #pragma unroll
        for (int k8 = 0; k8 < 32; k8 += 8) {
            uint32_t a[4] = {As[wm + g][k8 + t],     As[wm + g + 8][k8 + t],
                             As[wm + g][k8 + t + 4], As[wm + g + 8][k8 + t + 4]};
            #pragma unroll
            for (int nt = 0; nt < 4; nt++) {
                uint32_t b[2] = {Bs[k8 + t][wn + nt * 8 + g], Bs[k8 + t + 4][wn + nt * 8 + g]};
                mma_tf32(acc[nt], a, b);
            }
        }
    }
    #pragma unroll
    for (int nt = 0; nt < 4; nt++) {
        int col = n0 + wn + nt * 8 + t * 2;
        #pragma unroll
        for (int half = 0; half < 2; half++) {
            int row = m0 + wm + g + half * 8;
            #pragma unroll
            for (int e = 0; e < 2; e++) {
                float v = acc[nt][half * 2 + e];
                if (z == 0) v += bq[col + e];
                if (z == 3) v = sigm(v);
                C[(size_t)row * Nn + col + e] = v;
            }
        }
    }
}

// ---------------- pair bias: LN(P=128) + proj(128->16) + beta ----------------
__global__ __launch_bounds__(256) void pairbias_kernel(const float* __restrict__ pair,
                                                       const float* __restrict__ beta,
                                                       const float* __restrict__ w,
                                                       const float* __restrict__ b,
                                                       const float* __restrict__ Wb,
                                                       float* __restrict__ bias) {
    int lane = threadIdx.x & 31, warp = threadIdx.x >> 5;
    int c0 = lane * 4;

    float wreg[4], breg[4], wb[4][H_];
    #pragma unroll
    for (int t = 0; t < 4; t++) {
        wreg[t] = __ldg(w + c0 + t);
        breg[t] = __ldg(b + c0 + t);
        #pragma unroll
        for (int h = 0; h < H_; h++)
            wb[t][h] = __ldg(Wb + (c0 + t) * H_ + h);
    }

    int stride = gridDim.x * 8;
    int p = blockIdx.x * 8 + warp;
    float4 x4 = make_float4(0.f, 0.f, 0.f, 0.f);
    if (p < NN) x4 = *(const float4*)(pair + (size_t)p * P_ + c0);

    for (; p < NN; p += stride) {
        int pn = p + stride;
        float4 nx4 = make_float4(0.f, 0.f, 0.f, 0.f);
        if (pn < NN) nx4 = *(const float4*)(pair + (size_t)pn * P_ + c0);
        float bv = __ldg(beta + p);

        float xs[4] = {x4.x, x4.y, x4.z, x4.w};
        float s = 0.f, s2 = 0.f;
        #pragma unroll
        for (int t = 0; t < 4; t++) { s += xs[t]; s2 += xs[t] * xs[t]; }
        #pragma unroll
        for (int o = 16; o; o >>= 1) {
            s  += __shfl_xor_sync(0xffffffffu, s,  o);
            s2 += __shfl_xor_sync(0xffffffffu, s2, o);
        }
        float mean = s * (1.f / P_);
        float var  = s2 * (1.f / P_) - mean * mean;
        float rs   = rsqrtf(var + 1e-5f);

        float acc[H_];
        #pragma unroll
        for (int h = 0; h < H_; h++) acc[h] = 0.f;
        #pragma unroll
        for (int t = 0; t < 4; t++) {
            float yv = (xs[t] - mean) * rs * wreg[t] + breg[t];
            #pragma unroll
            for (int h = 0; h < H_; h++) acc[h] += yv * wb[t][h];
        }

        #pragma unroll
        for (int h = 0; h < 16; h++) acc[h] += __shfl_xor_sync(0xffffffffu, acc[h], 16);
        #pragma unroll
        for (int h = 0; h < 8; h++) {
            float lo = acc[h], hi = acc[h + 8];
            float send = (lane & 8) ? lo : hi;
            float got = __shfl_xor_sync(0xffffffffu, send, 8);
            acc[h] = ((lane & 8) ? hi : lo) + got;
        }
        #pragma unroll
        for (int h = 0; h < 4; h++) {
            float lo = acc[h], hi = acc[h + 4];
            float send = (lane & 4) ? lo : hi;
            float got = __shfl_xor_sync(0xffffffffu, send, 4);
            acc[h] = ((lane & 4) ? hi : lo) + got;
        }
        #pragma unroll
        for (int h = 0; h < 2; h++) {
            float lo = acc[h], hi = acc[h + 2];
            float send = (lane & 2) ? lo : hi;
            float got = __shfl_xor_sync(0xffffffffu, send, 2);
            acc[h] = ((lane & 2) ? hi : lo) + got;
        }
        {
            float lo = acc[0], hi = acc[1];
            float send = (lane & 1) ? lo : hi;
            float got = __shfl_xor_sync(0xffffffffu, send, 1);
            acc[0] = ((lane & 1) ? hi : lo) + got;
        }

        if (lane < H_)
            bias[(size_t)lane * NN + p] = acc[0] + bv;
        x4 = nx4;
    }
}

// ---------------- flash attention (fp32, D=48), gate fused ----------------
#define QS(r,c) smQ[(r)*52+(c)]
#define KS(r,c) smK[(r)*52+(c)]
#define VS(r,c) smV[(r)*52+(c)]
#define PS(r,c) smP[(r)*64+(c)]
#define ATTN_SMEM ((3*64*52 + 64*64)*4)

__global__ __launch_bounds__(256) void attn_kernel(const float* __restrict__ q,
                                                   const float* __restrict__ k,
                                                   const float* __restrict__ v,
                                                   const float* __restrict__ bias,
                                                   const float* __restrict__ g,
                                                   float* __restrict__ o) {
    extern __shared__ float sm[];
    float* smQ = sm;
    float* smK = sm + 64 * 52;
    float* smV = sm + 2 * 64 * 52;
    float* smP = sm + 3 * 64 * 52;

    int h  = blockIdx.y;
    int q0 = blockIdx.x * 64;
    int tid = threadIdx.x, tx = tid & 15, ty = tid >> 4;
    int dx = tx * 3;

    #pragma unroll
    for (int it = 0; it < 3; it++) {
        int idx = tid + it * 256;
        int r = idx / 12, c4 = idx % 12;
        float4 v4 = *(const float4*)(q + (size_t)(q0 + r) * A_ + h * D_ + c4 * 4);
        *(float4*)&QS(r, c4 * 4) = v4;
    }

    float m_i[4], l_i[4], acc[4][3];
    #pragma unroll
    for (int i = 0; i < 4; i++) {
        m_i[i] = -1e30f; l_i[i] = 0.f;
        #pragma unroll
        for (int j = 0; j < 3; j++) acc[i][j] = 0.f;
    }
    const float scale = 0.144337567f;

    for (int j0 = 0; j0 < N_; j0 += 64) {
        __syncthreads();
        #pragma unroll
        for (int it = 0; it < 3; it++) {
            int idx = tid + it * 256;
            int r = idx / 12, c4 = idx % 12;
            float4 kv4 = *(const float4*)(k + (size_t)(j0 + r) * A_ + h * D_ + c4 * 4);
            *(float4*)&KS(r, c4 * 4) = kv4;
            float4 vv4 = *(const float4*)(v + (size_t)(j0 + r) * A_ + h * D_ + c4 * 4);
            *(float4*)&VS(r, c4 * 4) = vv4;
        }
        __syncthreads();

        float sc[4][4];
        #pragma unroll
        for (int i = 0; i < 4; i++)
            #pragma unroll
            for (int j = 0; j < 4; j++) sc[i][j] = 0.f;

        #pragma unroll
        for (int d4 = 0; d4 < 12; d4++) {
            float qm[4][4], km[4][4];
            #pragma unroll
            for (int i = 0; i < 4; i++) {
                float4 t4 = *(const float4*)&QS(ty * 4 + i, d4 * 4);
                qm[i][0] = t4.x; qm[i][1] = t4.y; qm[i][2] = t4.z; qm[i][3] = t4.w;
            }
            #pragma unroll
            for (int j = 0; j < 4; j++) {
                float4 t4 = *(const float4*)&KS(tx + 16 * j, d4 * 4);
                km[j][0] = t4.x; km[j][1] = t4.y; km[j][2] = t4.z; km[j][3] = t4.w;
            }
            #pragma unroll
            for (int dd = 0; dd < 4; dd++)
                #pragma unroll
                for (int i = 0; i < 4; i++)
                    #pragma unroll
                    for (int j = 0; j < 4; j++)
                        sc[i][j] += qm[i][dd] * km[j][dd];
        }

        #pragma unroll
        for (int i = 0; i < 4; i++) {
            const float* bp = bias + (size_t)h * NN + (size_t)(q0 + ty * 4 + i) * N_ + j0;
            #pragma unroll
            for (int j = 0; j < 4; j++)
                sc[i][j] = sc[i][j] * scale + __ldg(bp + tx + 16 * j);
        }

        #pragma unroll
        for (int i = 0; i < 4; i++) {
            float mx = fmaxf(fmaxf(sc[i][0], sc[i][1]), fmaxf(sc[i][2], sc[i][3]));
            #pragma unroll
            for (int o2 = 8; o2; o2 >>= 1)
                mx = fmaxf(mx, __shfl_xor_sync(0xffffffffu, mx, o2));
            float mnew = fmaxf(m_i[i], mx);
            float corr = __expf(m_i[i] - mnew);
            m_i[i] = mnew;
            float rsum = 0.f;
            #pragma unroll
            for (int j = 0; j < 4; j++) { sc[i][j] = __expf(sc[i][j] - mnew); rsum += sc[i][j]; }
            #pragma unroll
            for (int o2 = 8; o2; o2 >>= 1)
                rsum += __shfl_xor_sync(0xffffffffu, rsum, o2);
            l_i[i] = l_i[i] * corr + rsum;
            #pragma unroll
            for (int j = 0; j < 3; j++) acc[i][j] *= corr;
            #pragma unroll
            for (int j = 0; j < 4; j++) PS(ty * 4 + i, tx + 16 * j) = sc[i][j];
        }
        __syncthreads();

        #pragma unroll 4
        for (int c4 = 0; c4 < 16; c4++) {
            float pm[4][4];
            #pragma unroll
            for (int i = 0; i < 4; i++) {
                float4 t4 = *(const float4*)&PS(ty * 4 + i, c4 * 4);
                pm[i][0] = t4.x; pm[i][1] = t4.y; pm[i][2] = t4.z; pm[i][3] = t4.w;
            }
            #pragma unroll
            for (int cc = 0; cc < 4; cc++) {
                float vv[3];
                #pragma unroll
                for (int j = 0; j < 3; j++) vv[j] = VS(c4 * 4 + cc, dx + j);
                #pragma unroll
                for (int i = 0; i < 4; i++)
                    #pragma unroll
                    for (int j = 0; j < 3; j++) acc[i][j] += pm[i][cc] * vv[j];
            }
        }
    }

    #pragma unroll
    for (int i = 0; i < 4; i++) {
        float inv = 1.f / l_i[i];
        int row = q0 + ty * 4 + i;
        #pragma unroll
        for (int j = 0; j < 3; j++) {
            int d = dx + j;
            float gv = g[(size_t)row * A_ + h * D_ + d];
            o[(size_t)row * A_ + h * D_ + d] = acc[i][j] * inv * gv;
        }
    }
}

// ---------------- launch ----------------
extern "C" void kernel_launch(void* const* d_in, const int* in_sizes, int n_in,
                              void* d_out, int out_size) {
    const float* a       = (const float*)d_in[0];
    const float* s       = (const float*)d_in[1];
    const float* pair    = (const float*)d_in[2];
    const float* beta    = (const float*)d_in[3];
    const float* ln_s_w  = (const float*)d_in[4];
    const float* gamma_w = (const float*)d_in[5];
    const float* gamma_b = (const float*)d_in[6];
    const float* shift_w = (const float*)d_in[7];
    const float* Wq      = (const float*)d_in[8];
    const float* bq      = (const float*)d_in[9];
    const float* Wk      = (const float*)d_in[10];
    const float* Wv      = (const float*)d_in[11];
    const float* ln_p_w  = (const float*)d_in[12];
    const float* ln_p_b  = (const float*)d_in[13];
    const float* Wb      = (const float*)d_in[14];
    const float* Wg      = (const float*)d_in[15];
    const float* Wp      = (const float*)d_in[16];
    const float* Wout    = (const float*)d_in[17];
    const float* bout    = (const float*)d_in[18];
    float* out = (float*)d_out;

    float *p_sn, *p_an, *p_a2, *p_q, *p_k, *p_v, *p_gt, *p_bias, *p_o, *p_gate;
    cudaGetSymbolAddress((void**)&p_sn,   d_sn);
    cudaGetSymbolAddress((void**)&p_an,   d_an);
    cudaGetSymbolAddress((void**)&p_a2,   d_a2);
    cudaGetSymbolAddress((void**)&p_q,    d_q);
    cudaGetSymbolAddress((void**)&p_k,    d_k);
    cudaGetSymbolAddress((void**)&p_v,    d_v);
    cudaGetSymbolAddress((void**)&p_gt,   d_gt);
    cudaGetSymbolAddress((void**)&p_bias, d_bias);
    cudaGetSymbolAddress((void**)&p_o,    d_o);
    cudaGetSymbolAddress((void**)&p_gate, d_gate);

    cudaFuncSetAttribute(attn_kernel, cudaFuncAttributeMaxDynamicSharedMemorySize, ATTN_SMEM);

    dim3 g2(A_ / 64, N_ / 64);          // 12 x 12
    dim3 gz(A_ / 64, N_ / 64, 4);       // QKVG

    pairbias_kernel<<<296, 256>>>(pair, beta, ln_p_w, ln_p_b, Wb, p_bias);
    ln_kernel<S_><<<N_, 256>>>(s, ln_s_w, p_sn);
    ln_kernel<A_><<<N_, 256>>>(a, nullptr, p_an);
    adaln_tf32<<<g2, 256>>>(p_sn, gamma_w, gamma_b, shift_w, p_an, p_a2);
    qkvg_tf32<<<gz, 256>>>(p_a2, Wq, bq, Wk, Wv, Wg, p_q, p_k, p_v, p_gt);
    gemm_tf32<2><<<g2, 256>>>(s, Wout, p_gate, S_, A_, bout, nullptr);
    dim3 ga(N_ / 64, H_);
    attn_kernel<<<ga, 256, ATTN_SMEM>>>(p_q, p_k, p_v, p_bias, p_gt, p_o);
    gemm_tf32<4><<<g2, 256>>>(p_o, Wp, out, A_, A_, nullptr, p_gate);
}

// round 4
// speedup vs baseline: 4.8889x; 1.0701x over previous
#include <cuda_runtime.h>
#include <math.h>
#include <stdint.h>

#define N_  768
#define A_  768
#define S_  384
#define P_  128
#define H_  16
#define D_  48
#define NN  (N_*N_)

// ---------------- scratch (no allocations allowed) ----------------
__device__ float d_sn [N_*S_];
__device__ float d_an [N_*A_];
__device__ float d_a2 [N_*A_];
__device__ float d_q  [N_*A_];
__device__ float d_k  [N_*A_];
__device__ float d_v  [N_*A_];
__device__ float d_gt [N_*A_];          // sigmoid(a2 @ Wg)
__device__ float d_bias[H_*NN];         // [H][N][N]  (37.7 MB)
__device__ float d_o  [N_*A_];
__device__ float d_gate[N_*A_];         // sigmoid(s @ Wout + bout)

// ---------------- helpers ----------------
__device__ __forceinline__ uint32_t f2tf(float f) {
    uint32_t u;
    asm("cvt.rna.tf32.f32 %0, %1;" : "=r"(u) : "f"(f));
    return u;
}
__device__ __forceinline__ void mma_tf32(float* c, const uint32_t* a, const uint32_t* b) {
    asm volatile("mma.sync.aligned.m16n8k8.row.col.f32.tf32.tf32.f32 "
                 "{%0,%1,%2,%3}, {%4,%5,%6,%7}, {%8,%9}, {%0,%1,%2,%3};"
                 : "+f"(c[0]), "+f"(c[1]), "+f"(c[2]), "+f"(c[3])
                 : "r"(a[0]), "r"(a[1]), "r"(a[2]), "r"(a[3]), "r"(b[0]), "r"(b[1]));
}
__device__ __forceinline__ float sigm(float x) { return 1.f / (1.f + __expf(-x)); }

// ---------------- row LayerNorm ----------------
template<int COLS>
__global__ __launch_bounds__(256) void ln_kernel(const float* __restrict__ x,
                                                 const float* __restrict__ w,
                                                 float* __restrict__ y) {
    int row = blockIdx.x;
    const float* xr = x + (size_t)row * COLS;
    float s = 0.f, s2 = 0.f;
    for (int c = threadIdx.x; c < COLS; c += blockDim.x) {
        float v = xr[c]; s += v; s2 += v * v;
    }
    __shared__ float red[64];
    #pragma unroll
    for (int o = 16; o; o >>= 1) {
        s  += __shfl_xor_sync(0xffffffffu, s,  o);
        s2 += __shfl_xor_sync(0xffffffffu, s2, o);
    }
    int wid = threadIdx.x >> 5, lid = threadIdx.x & 31;
    if (lid == 0) { red[wid] = s; red[wid + 32] = s2; }
    __syncthreads();
    if (wid == 0) {
        s  = (lid < 8) ? red[lid]      : 0.f;
        s2 = (lid < 8) ? red[lid + 32] : 0.f;
        #pragma unroll
        for (int o = 4; o; o >>= 1) {
            s  += __shfl_xor_sync(0xffffffffu, s,  o);
            s2 += __shfl_xor_sync(0xffffffffu, s2, o);
        }
        if (lid == 0) { red[0] = s; red[1] = s2; }
    }
    __syncthreads();
    float mean = red[0] * (1.f / COLS);
    float var  = red[1] * (1.f / COLS) - mean * mean;
    float rs   = rsqrtf(var + 1e-5f);
    float* yr = y + (size_t)row * COLS;
    for (int c = threadIdx.x; c < COLS; c += blockDim.x) {
        float v = (xr[c] - mean) * rs;
        if (w) v *= w[c];
        yr[c] = v;
    }
}

// ---------------- generic tf32 GEMM with epilogues ----------------
// EPI: 1=+bias 2=sigmoid(x+bias) 4=x*C2
template<int EPI>
__global__ __launch_bounds__(256) void gemm_tf32(const float* __restrict__ A,
                                                 const float* __restrict__ B,
                                                 float* __restrict__ C,
                                                 int K, int Nn,
                                                 const float* __restrict__ bias,
                                                 const float* __restrict__ C2) {
    __shared__ uint32_t As[64][36];
    __shared__ uint32_t Bs[32][72];
    int m0 = blockIdx.y * 64, n0 = blockIdx.x * 64;
    int tid = threadIdx.x, lane = tid & 31, warp = tid >> 5;
    int wm = (warp & 3) * 16, wn = (warp >> 2) * 32;
    int g = lane >> 2, t = lane & 3;

    int am = tid >> 3, akq = tid & 7;
    int bk = tid >> 4, bn4 = tid & 15;

    float4 pa[2], pb[2];
    #pragma unroll
    for (int it = 0; it < 2; it++) {
        pa[it] = *(const float4*)(A + (size_t)(m0 + am + it * 32) * K + akq * 4);
        pb[it] = *(const float4*)(B + (size_t)(bk + it * 16) * Nn + n0 + bn4 * 4);
    }

    float acc[4][4];
    #pragma unroll
    for (int i = 0; i < 4; i++)
        #pragma unroll
        for (int j = 0; j < 4; j++) acc[i][j] = 0.f;

    for (int kt = 0; kt < K; kt += 32) {
        __syncthreads();
        #pragma unroll
        for (int it = 0; it < 2; it++) {
            uint32_t* ap = &As[am + it * 32][akq * 4];
            ap[0] = f2tf(pa[it].x); ap[1] = f2tf(pa[it].y);
            ap[2] = f2tf(pa[it].z); ap[3] = f2tf(pa[it].w);
            uint32_t* bp = &Bs[bk + it * 16][bn4 * 4];
            bp[0] = f2tf(pb[it].x); bp[1] = f2tf(pb[it].y);
            bp[2] = f2tf(pb[it].z); bp[3] = f2tf(pb[it].w);
        }
        __syncthreads();
        if (kt + 32 < K) {
            #pragma unroll
            for (int it = 0; it < 2; it++) {
                pa[it] = *(const float4*)(A + (size_t)(m0 + am + it * 32) * K + kt + 32 + akq * 4);
                pb[it] = *(const float4*)(B + (size_t)(kt + 32 + bk + it * 16) * Nn + n0 + bn4 * 4);
            }
        }
        #pragma unroll
        for (int k8 = 0; k8 < 32; k8 += 8) {
            uint32_t a[4] = {As[wm + g][k8 + t],     As[wm + g + 8][k8 + t],
                             As[wm + g][k8 + t + 4], As[wm + g + 8][k8 + t + 4]};
            #pragma unroll
            for (int nt = 0; nt < 4; nt++) {
                uint32_t b[2] = {Bs[k8 + t][wn + nt * 8 + g], Bs[k8 + t + 4][wn + nt * 8 + g]};
                mma_tf32(acc[nt], a, b);
            }
        }
    }
    #pragma unroll
    for (int nt = 0; nt < 4; nt++) {
        int col = n0 + wn + nt * 8 + t * 2;
        #pragma unroll
        for (int half = 0; half < 2; half++) {
            int row = m0 + wm + g + half * 8;
            float v0 = acc[nt][half * 2 + 0], v1 = acc[nt][half * 2 + 1];
            if (EPI == 1) { v0 += bias[col]; v1 += bias[col + 1]; }
            if (EPI == 2) { v0 = sigm(v0 + bias[col]); v1 = sigm(v1 + bias[col + 1]); }
            if (EPI == 4) { v0 *= C2[(size_t)row * Nn + col]; v1 *= C2[(size_t)row * Nn + col + 1]; }
            C[(size_t)row * Nn + col]     = v0;
            C[(size_t)row * Nn + col + 1] = v1;
        }
    }
}

// ---------------- fused AdaLN ----------------
__global__ __launch_bounds__(256) void adaln_tf32(const float* __restrict__ SN,
                                                  const float* __restrict__ Wgam,
                                                  const float* __restrict__ gb,
                                                  const float* __restrict__ Wsh,
                                                  const float* __restrict__ AN,
                                                  float* __restrict__ A2) {
    __shared__ uint32_t As[64][36];
    __shared__ uint32_t B1s[32][72];
    __shared__ uint32_t B2s[32][72];
    const int K = S_, Nn = A_;
    int m0 = blockIdx.y * 64, n0 = blockIdx.x * 64;
    int tid = threadIdx.x, lane = tid & 31, warp = tid >> 5;
    int wm = (warp & 3) * 16, wn = (warp >> 2) * 32;
    int g = lane >> 2, t = lane & 3;

    int am = tid >> 3, akq = tid & 7;
    int bk = tid >> 4, bn4 = tid & 15;

    float4 pa[2], pb1[2], pb2[2];
    #pragma unroll
    for (int it = 0; it < 2; it++) {
        pa[it]  = *(const float4*)(SN   + (size_t)(m0 + am + it * 32) * K + akq * 4);
        pb1[it] = *(const float4*)(Wgam + (size_t)(bk + it * 16) * Nn + n0 + bn4 * 4);
        pb2[it] = *(const float4*)(Wsh  + (size_t)(bk + it * 16) * Nn + n0 + bn4 * 4);
    }
    float acc1[4][4], acc2[4][4];
    #pragma unroll
    for (int i = 0; i < 4; i++)
        #pragma unroll
        for (int j = 0; j < 4; j++) { acc1[i][j] = 0.f; acc2[i][j] = 0.f; }

    for (int kt = 0; kt < K; kt += 32) {
        __syncthreads();
        #pragma unroll
        for (int it = 0; it < 2; it++) {
            uint32_t* ap = &As[am + it * 32][akq * 4];
            ap[0] = f2tf(pa[it].x); ap[1] = f2tf(pa[it].y);
            ap[2] = f2tf(pa[it].z); ap[3] = f2tf(pa[it].w);
            uint32_t* b1 = &B1s[bk + it * 16][bn4 * 4];
            b1[0] = f2tf(pb1[it].x); b1[1] = f2tf(pb1[it].y);
            b1[2] = f2tf(pb1[it].z); b1[3] = f2tf(pb1[it].w);
            uint32_t* b2 = &B2s[bk + it * 16][bn4 * 4];
            b2[0] = f2tf(pb2[it].x); b2[1] = f2tf(pb2[it].y);
            b2[2] = f2tf(pb2[it].z); b2[3] = f2tf(pb2[it].w);
        }
        __syncthreads();
        if (kt + 32 < K) {
            #pragma unroll
            for (int it = 0; it < 2; it++) {
                pa[it]  = *(const float4*)(SN   + (size_t)(m0 + am + it * 32) * K + kt + 32 + akq * 4);
                pb1[it] = *(const float4*)(Wgam + (size_t)(kt + 32 + bk + it * 16) * Nn + n0 + bn4 * 4);
                pb2[it] = *(const float4*)(Wsh  + (size_t)(kt + 32 + bk + it * 16) * Nn + n0 + bn4 * 4);
            }
        }
        #pragma unroll
        for (int k8 = 0; k8 < 32; k8 += 8) {
            uint32_t a[4] = {As[wm + g][k8 + t],     As[wm + g + 8][k8 + t],
                             As[wm + g][k8 + t + 4], As[wm + g + 8][k8 + t + 4]};
            #pragma unroll
            for (int nt = 0; nt < 4; nt++) {
                uint32_t b1[2] = {B1s[k8 + t][wn + nt * 8 + g], B1s[k8 + t + 4][wn + nt * 8 + g]};
                mma_tf32(acc1[nt], a, b1);
                uint32_t b2[2] = {B2s[k8 + t][wn + nt * 8 + g], B2s[k8 + t + 4][wn + nt * 8 + g]};
                mma_tf32(acc2[nt], a, b2);
            }
        }
    }
    #pragma unroll
    for (int nt = 0; nt < 4; nt++) {
        int col = n0 + wn + nt * 8 + t * 2;
        #pragma unroll
        for (int half = 0; half < 2; half++) {
            int row = m0 + wm + g + half * 8;
            #pragma unroll
            for (int e = 0; e < 2; e++) {
                float gv = sigm(acc1[nt][half * 2 + e] + gb[col + e]);
                float a2 = gv * AN[(size_t)row * Nn + col + e] + acc2[nt][half * 2 + e];
                A2[(size_t)row * Nn + col + e] = a2;
            }
        }
    }
}

// ---------------- fused QKVG ----------------
__global__ __launch_bounds__(256) void qkvg_tf32(const float* __restrict__ A2,
                                                 const float* __restrict__ Wq,
                                                 const float* __restrict__ bq,
                                                 const float* __restrict__ Wk,
                                                 const float* __restrict__ Wv,
                                                 const float* __restrict__ Wg,
                                                 float* __restrict__ oq, float* __restrict__ ok,
                                                 float* __restrict__ ov, float* __restrict__ og) {
    __shared__ uint32_t As[64][36];
    __shared__ uint32_t Bs[32][72];
    const int K = A_, Nn = A_;
    int z = blockIdx.z;
    const float* B = (z == 0) ? Wq : (z == 1) ? Wk : (z == 2) ? Wv : Wg;
    float* C = (z == 0) ? oq : (z == 1) ? ok : (z == 2) ? ov : og;

    int m0 = blockIdx.y * 64, n0 = blockIdx.x * 64;
    int tid = threadIdx.x, lane = tid & 31, warp = tid >> 5;
    int wm = (warp & 3) * 16, wn = (warp >> 2) * 32;
    int g = lane >> 2, t = lane & 3;
    int am = tid >> 3, akq = tid & 7;
    int bk = tid >> 4, bn4 = tid & 15;

    float4 pa[2], pb[2];
    #pragma unroll
    for (int it = 0; it < 2; it++) {
        pa[it] = *(const float4*)(A2 + (size_t)(m0 + am + it * 32) * K + akq * 4);
        pb[it] = *(const float4*)(B + (size_t)(bk + it * 16) * Nn + n0 + bn4 * 4);
    }
    float acc[4][4];
    #pragma unroll
    for (int i = 0; i < 4; i++)
        #pragma unroll
        for (int j = 0; j < 4; j++) acc[i][j] = 0.f;

    for (int kt = 0; kt < K; kt += 32) {
        __syncthreads();
        #pragma unroll
        for (int it = 0; it < 2; it++) {
            uint32_t* ap = &As[am + it * 32][akq * 4];
            ap[0] = f2tf(pa[it].x); ap[1] = f2tf(pa[it].y);
            ap[2] = f2tf(pa[it].z); ap[3] = f2tf(pa[it].w);
            uint32_t* bp = &Bs[bk + it * 16][bn4 * 4];
            bp[0] = f2tf(pb[it].x); bp[1] = f2tf(pb[it].y);
            bp[2] = f2tf(pb[it].z); bp[3] = f2tf(pb[it].w);
        }
        __syncthreads();
        if (kt + 32 < K) {
            #pragma unroll
            for (int it = 0; it < 2; it++) {
                pa[it] = *(const float4*)(A2 + (size_t)(m0 + am + it * 32) * K + kt + 32 + akq * 4);
                pb[it] = *(const float4*)(B + (size_t)(kt + 32 + bk + it * 16) * Nn + n0 + bn4 * 4);
            }
        }
        #pragma unroll
        for (int k8 = 0; k8 < 32; k8 += 8) {
            uint32_t a[4] = {As[wm + g][k8 + t],     As[wm + g + 8][k8 + t],
                             As[wm + g][k8 + t + 4], As[wm + g + 8][k8 + t + 4]};
            #pragma unroll
            for (int nt = 0; nt < 4; nt++) {
                uint32_t b[2] = {Bs[k8 + t][wn + nt * 8 + g], Bs[k8 + t + 4][wn + nt * 8 + g]};
                mma_tf32(acc[nt], a, b);
            }
        }
    }
    #pragma unroll
    for (int nt = 0; nt < 4; nt++) {
        int col = n0 + wn + nt * 8 + t * 2;
        #pragma unroll
        for (int half = 0; half < 2; half++) {
            int row = m0 + wm + g + half * 8;
            #pragma unroll
            for (int e = 0; e < 2; e++) {
                float v = acc[nt][half * 2 + e];
                if (z == 0) v += bq[col + e];
                if (z == 3) v = sigm(v);
                C[(size_t)row * Nn + col + e] = v;
            }
        }
    }
}

// ---------------- pair bias: LN(P=128) + proj(128->16) + beta ----------------
__global__ __launch_bounds__(256) void pairbias_kernel(const float* __restrict__ pair,
                                                       const float* __restrict__ beta,
                                                       const float* __restrict__ w,
                                                       const float* __restrict__ b,
                                                       const float* __restrict__ Wb,
                                                       float* __restrict__ bias) {
    int lane = threadIdx.x & 31, warp = threadIdx.x >> 5;
    int c0 = lane * 4;

    float wreg[4], breg[4], wb[4][H_];
    #pragma unroll
    for (int t = 0; t < 4; t++) {
        wreg[t] = __ldg(w + c0 + t);
        breg[t] = __ldg(b + c0 + t);
        #pragma unroll
        for (int h = 0; h < H_; h++)
            wb[t][h] = __ldg(Wb + (c0 + t) * H_ + h);
    }

    int stride = gridDim.x * 8;
    int p = blockIdx.x * 8 + warp;
    float4 x4 = make_float4(0.f, 0.f, 0.f, 0.f);
    if (p < NN) x4 = *(const float4*)(pair + (size_t)p * P_ + c0);

    for (; p < NN; p += stride) {
        int pn = p + stride;
        float4 nx4 = make_float4(0.f, 0.f, 0.f, 0.f);
        if (pn < NN) nx4 = *(const float4*)(pair + (size_t)pn * P_ + c0);
        float bv = __ldg(beta + p);

        float xs[4] = {x4.x, x4.y, x4.z, x4.w};
        float s = 0.f, s2 = 0.f;
        #pragma unroll
        for (int t = 0; t < 4; t++) { s += xs[t]; s2 += xs[t] * xs[t]; }
        #pragma unroll
        for (int o = 16; o; o >>= 1) {
            s  += __shfl_xor_sync(0xffffffffu, s,  o);
            s2 += __shfl_xor_sync(0xffffffffu, s2, o);
        }
        float mean = s * (1.f / P_);
        float var  = s2 * (1.f / P_) - mean * mean;
        float rs   = rsqrtf(var + 1e-5f);

        float acc[H_];
        #pragma unroll
        for (int h = 0; h < H_; h++) acc[h] = 0.f;
        #pragma unroll
        for (int t = 0; t < 4; t++) {
            float yv = (xs[t] - mean) * rs * wreg[t] + breg[t];
            #pragma unroll
            for (int h = 0; h < H_; h++) acc[h] += yv * wb[t][h];
        }

        #pragma unroll
        for (int h = 0; h < 16; h++) acc[h] += __shfl_xor_sync(0xffffffffu, acc[h], 16);
        #pragma unroll
        for (int h = 0; h < 8; h++) {
            float lo = acc[h], hi = acc[h + 8];
            float send = (lane & 8) ? lo : hi;
            float got = __shfl_xor_sync(0xffffffffu, send, 8);
            acc[h] = ((lane & 8) ? hi : lo) + got;
        }
        #pragma unroll
        for (int h = 0; h < 4; h++) {
            float lo = acc[h], hi = acc[h + 4];
            float send = (lane & 4) ? lo : hi;
            float got = __shfl_xor_sync(0xffffffffu, send, 4);
            acc[h] = ((lane & 4) ? hi : lo) + got;
        }
        #pragma unroll
        for (int h = 0; h < 2; h++) {
            float lo = acc[h], hi = acc[h + 2];
            float send = (lane & 2) ? lo : hi;
            float got = __shfl_xor_sync(0xffffffffu, send, 2);
            acc[h] = ((lane & 2) ? hi : lo) + got;
        }
        {
            float lo = acc[0], hi = acc[1];
            float send = (lane & 1) ? lo : hi;
            float got = __shfl_xor_sync(0xffffffffu, send, 1);
            acc[0] = ((lane & 1) ? hi : lo) + got;
        }

        if (lane < H_)
            bias[(size_t)lane * NN + p] = acc[0] + bv;
        x4 = nx4;
    }
}

// ---------------- flash attention (tf32 mma), gate fused ----------------
// 4 warps, each owns 16 q-rows x full 64-key tile -> warp-local softmax.
// smem strides chosen conflict-free per fragment pattern:
//   Q,K stride 52 (bank 20g+t), V stride 56 (bank 24t+g), P stride 68 (bank 4g+t)
#define AQ(r,c) smQ[(r)*52+(c)]
#define AK(r,c) smK[(r)*52+(c)]
#define AV(r,c) smV[(r)*56+(c)]
#define AP(r,c) smP[(r)*68+(c)]
#define ATTN_SMEM (64*(52+52+56+68)*4)

__global__ __launch_bounds__(128) void attn_tf32(const float* __restrict__ q,
                                                 const float* __restrict__ k,
                                                 const float* __restrict__ v,
                                                 const float* __restrict__ bias,
                                                 const float* __restrict__ gt,
                                                 float* __restrict__ o) {
    extern __shared__ uint32_t sm[];
    uint32_t* smQ = sm;
    uint32_t* smK = smQ + 64 * 52;
    uint32_t* smV = smK + 64 * 52;
    uint32_t* smP = smV + 64 * 56;

    int h  = blockIdx.y;
    int q0 = blockIdx.x * 64;
    int tid = threadIdx.x, lane = tid & 31, warp = tid >> 5;
    int g = lane >> 2, t = lane & 3;
    int wm = warp * 16;

    // load Q tile (64 x 48) as tf32
    #pragma unroll
    for (int it = 0; it < 6; it++) {
        int idx = tid + it * 128;
        int r = idx / 12, c4 = idx % 12;
        float4 v4 = *(const float4*)(q + (size_t)(q0 + r) * A_ + h * D_ + c4 * 4);
        AQ(r, c4 * 4 + 0) = f2tf(v4.x); AQ(r, c4 * 4 + 1) = f2tf(v4.y);
        AQ(r, c4 * 4 + 2) = f2tf(v4.z); AQ(r, c4 * 4 + 3) = f2tf(v4.w);
    }

    float m0 = -1e30f, m1 = -1e30f, l0 = 0.f, l1 = 0.f;
    float oacc[6][4];
    #pragma unroll
    for (int dt = 0; dt < 6; dt++)
        #pragma unroll
        for (int e = 0; e < 4; e++) oacc[dt][e] = 0.f;

    const float scale = 0.144337567f;   // 1/sqrt(48)

    for (int j0 = 0; j0 < N_; j0 += 64) {
        __syncthreads();
        #pragma unroll
        for (int it = 0; it < 6; it++) {
            int idx = tid + it * 128;
            int r = idx / 12, c4 = idx % 12;
            float4 kv = *(const float4*)(k + (size_t)(j0 + r) * A_ + h * D_ + c4 * 4);
            AK(r, c4 * 4 + 0) = f2tf(kv.x); AK(r, c4 * 4 + 1) = f2tf(kv.y);
            AK(r, c4 * 4 + 2) = f2tf(kv.z); AK(r, c4 * 4 + 3) = f2tf(kv.w);
            float4 vv = *(const float4*)(v + (size_t)(j0 + r) * A_ + h * D_ + c4 * 4);
            AV(r, c4 * 4 + 0) = f2tf(vv.x); AV(r, c4 * 4 + 1) = f2tf(vv.y);
            AV(r, c4 * 4 + 2) = f2tf(vv.z); AV(r, c4 * 4 + 3) = f2tf(vv.w);
        }
        __syncthreads();

        // S = Q K^T  (warp: 16 rows x 64 keys)
        float sacc[8][4];
        #pragma unroll
        for (int nt = 0; nt < 8; nt++)
            #pragma unroll
            for (int e = 0; e < 4; e++) sacc[nt][e] = 0.f;

        #pragma unroll
        for (int k8 = 0; k8 < 48; k8 += 8) {
            uint32_t a[4] = {AQ(wm + g, k8 + t),     AQ(wm + g + 8, k8 + t),
                             AQ(wm + g, k8 + t + 4), AQ(wm + g + 8, k8 + t + 4)};
            #pragma unroll
            for (int nt = 0; nt < 8; nt++) {
                uint32_t b[2] = {AK(nt * 8 + g, k8 + t), AK(nt * 8 + g, k8 + t + 4)};
                mma_tf32(sacc[nt], a, b);
            }
        }

        // bias + scale at accumulator positions
        const float* bp0 = bias + (size_t)h * NN + (size_t)(q0 + wm + g) * N_ + j0;
        const float* bp1 = bp0 + 8 * N_;
        #pragma unroll
        for (int nt = 0; nt < 8; nt++) {
            int c = nt * 8 + 2 * t;
            sacc[nt][0] = sacc[nt][0] * scale + __ldg(bp0 + c);
            sacc[nt][1] = sacc[nt][1] * scale + __ldg(bp0 + c + 1);
            sacc[nt][2] = sacc[nt][2] * scale + __ldg(bp1 + c);
            sacc[nt][3] = sacc[nt][3] * scale + __ldg(bp1 + c + 1);
        }

        // online softmax (rows wm+g and wm+g+8; quad-local reduction)
        float mx0 = -1e30f, mx1 = -1e30f;
        #pragma unroll
        for (int nt = 0; nt < 8; nt++) {
            mx0 = fmaxf(mx0, fmaxf(sacc[nt][0], sacc[nt][1]));
            mx1 = fmaxf(mx1, fmaxf(sacc[nt][2], sacc[nt][3]));
        }
        mx0 = fmaxf(mx0, __shfl_xor_sync(0xffffffffu, mx0, 1));
        mx0 = fmaxf(mx0, __shfl_xor_sync(0xffffffffu, mx0, 2));
        mx1 = fmaxf(mx1, __shfl_xor_sync(0xffffffffu, mx1, 1));
        mx1 = fmaxf(mx1, __shfl_xor_sync(0xffffffffu, mx1, 2));
        float mn0 = fmaxf(m0, mx0), mn1 = fmaxf(m1, mx1);
        float cr0 = __expf(m0 - mn0), cr1 = __expf(m1 - mn1);
        m0 = mn0; m1 = mn1;

        float s0 = 0.f, s1 = 0.f;
        #pragma unroll
        for (int nt = 0; nt < 8; nt++) {
            float p00 = __expf(sacc[nt][0] - mn0);
            float p01 = __expf(sacc[nt][1] - mn0);
            float p10 = __expf(sacc[nt][2] - mn1);
            float p11 = __expf(sacc[nt][3] - mn1);
            s0 += p00 + p01; s1 += p10 + p11;
            int c = nt * 8 + 2 * t;
            AP(wm + g, c)         = f2tf(p00);
            AP(wm + g, c + 1)     = f2tf(p01);
            AP(wm + g + 8, c)     = f2tf(p10);
            AP(wm + g + 8, c + 1) = f2tf(p11);
        }
        s0 += __shfl_xor_sync(0xffffffffu, s0, 1);
        s0 += __shfl_xor_sync(0xffffffffu, s0, 2);
        s1 += __shfl_xor_sync(0xffffffffu, s1, 1);
        s1 += __shfl_xor_sync(0xffffffffu, s1, 2);
        l0 = l0 * cr0 + s0;
        l1 = l1 * cr1 + s1;

        #pragma unroll
        for (int dt = 0; dt < 6; dt++) {
            oacc[dt][0] *= cr0; oacc[dt][1] *= cr0;
            oacc[dt][2] *= cr1; oacc[dt][3] *= cr1;
        }
        __syncwarp();

        // O += P V  (warp-private P)
        #pragma unroll
        for (int k8 = 0; k8 < 64; k8 += 8) {
            uint32_t a[4] = {AP(wm + g, k8 + t),     AP(wm + g + 8, k8 + t),
                             AP(wm + g, k8 + t + 4), AP(wm + g + 8, k8 + t + 4)};
            #pragma unroll
            for (int dt = 0; dt < 6; dt++) {
                uint32_t b[2] = {AV(k8 + t, dt * 8 + g), AV(k8 + t + 4, dt * 8 + g)};
                mma_tf32(oacc[dt], a, b);
            }
        }
    }

    // epilogue: normalize + gate
    float inv0 = 1.f / l0, inv1 = 1.f / l1;
    int r0 = q0 + wm + g, r1 = r0 + 8;
    #pragma unroll
    for (int dt = 0; dt < 6; dt++) {
        int d = dt * 8 + 2 * t;
        size_t i00 = (size_t)r0 * A_ + h * D_ + d;
        size_t i10 = (size_t)r1 * A_ + h * D_ + d;
        o[i00]     = oacc[dt][0] * inv0 * gt[i00];
        o[i00 + 1] = oacc[dt][1] * inv0 * gt[i00 + 1];
        o[i10]     = oacc[dt][2] * inv1 * gt[i10];
        o[i10 + 1] = oacc[dt][3] * inv1 * gt[i10 + 1];
    }
}

// ---------------- launch ----------------
extern "C" void kernel_launch(void* const* d_in, const int* in_sizes, int n_in,
                              void* d_out, int out_size) {
    const float* a       = (const float*)d_in[0];
    const float* s       = (const float*)d_in[1];
    const float* pair    = (const float*)d_in[2];
    const float* beta    = (const float*)d_in[3];
    const float* ln_s_w  = (const float*)d_in[4];
    const float* gamma_w = (const float*)d_in[5];
    const float* gamma_b = (const float*)d_in[6];
    const float* shift_w = (const float*)d_in[7];
    const float* Wq      = (const float*)d_in[8];
    const float* bq      = (const float*)d_in[9];
    const float* Wk      = (const float*)d_in[10];
    const float* Wv      = (const float*)d_in[11];
    const float* ln_p_w  = (const float*)d_in[12];
    const float* ln_p_b  = (const float*)d_in[13];
    const float* Wb      = (const float*)d_in[14];
    const float* Wg      = (const float*)d_in[15];
    const float* Wp      = (const float*)d_in[16];
    const float* Wout    = (const float*)d_in[17];
    const float* bout    = (const float*)d_in[18];
    float* out = (float*)d_out;

    float *p_sn, *p_an, *p_a2, *p_q, *p_k, *p_v, *p_gt, *p_bias, *p_o, *p_gate;
    cudaGetSymbolAddress((void**)&p_sn,   d_sn);
    cudaGetSymbolAddress((void**)&p_an,   d_an);
    cudaGetSymbolAddress((void**)&p_a2,   d_a2);
    cudaGetSymbolAddress((void**)&p_q,    d_q);
    cudaGetSymbolAddress((void**)&p_k,    d_k);
    cudaGetSymbolAddress((void**)&p_v,    d_v);
    cudaGetSymbolAddress((void**)&p_gt,   d_gt);
    cudaGetSymbolAddress((void**)&p_bias, d_bias);
    cudaGetSymbolAddress((void**)&p_o,    d_o);
    cudaGetSymbolAddress((void**)&p_gate, d_gate);

    cudaFuncSetAttribute(attn_tf32, cudaFuncAttributeMaxDynamicSharedMemorySize, ATTN_SMEM);

    dim3 g2(A_ / 64, N_ / 64);          // 12 x 12
    dim3 gz(A_ / 64, N_ / 64, 4);       // QKVG

    pairbias_kernel<<<592, 256>>>(pair, beta, ln_p_w, ln_p_b, Wb, p_bias);
    ln_kernel<S_><<<N_, 256>>>(s, ln_s_w, p_sn);
    ln_kernel<A_><<<N_, 256>>>(a, nullptr, p_an);
    adaln_tf32<<<g2, 256>>>(p_sn, gamma_w, gamma_b, shift_w, p_an, p_a2);
    qkvg_tf32<<<gz, 256>>>(p_a2, Wq, bq, Wk, Wv, Wg, p_q, p_k, p_v, p_gt);
    gemm_tf32<2><<<g2, 256>>>(s, Wout, p_gate, S_, A_, bout, nullptr);
    dim3 ga(N_ / 64, H_);
    attn_tf32<<<ga, 128, ATTN_SMEM>>>(p_q, p_k, p_v, p_bias, p_gt, p_o);
    gemm_tf32<4><<<g2, 256>>>(p_o, Wp, out, A_, A_, nullptr, p_gate);
}

// round 6
// speedup vs baseline: 6.4289x; 1.3150x over previous
#include <cuda_runtime.h>
#include <math.h>
#include <stdint.h>

#define N_  768
#define A_  768
#define S_  384
#define P_  128
#define H_  16
#define D_  48
#define NN  (N_*N_)

// ---------------- scratch (no allocations allowed) ----------------
__device__ float d_sn [N_*S_];
__device__ float d_an [N_*A_];
__device__ float d_a2 [N_*A_];
__device__ float d_q  [N_*A_];
__device__ float d_k  [N_*A_];
__device__ float d_v  [N_*A_];
__device__ float d_gt [N_*A_];          // sigmoid(a2 @ Wg)
__device__ float d_bias[H_*NN];         // [H][N][N]  (37.7 MB)
__device__ float d_o  [N_*A_];
__device__ float d_gate[N_*A_];         // sigmoid(s @ Wout + bout)

// ---------------- helpers ----------------
__device__ __forceinline__ uint32_t f2tf(float f) {
    uint32_t u;
    asm("cvt.rna.tf32.f32 %0, %1;" : "=r"(u) : "f"(f));
    return u;
}
__device__ __forceinline__ void mma_tf32(float* c, const uint32_t* a, const uint32_t* b) {
    asm volatile("mma.sync.aligned.m16n8k8.row.col.f32.tf32.tf32.f32 "
                 "{%0,%1,%2,%3}, {%4,%5,%6,%7}, {%8,%9}, {%0,%1,%2,%3};"
                 : "+f"(c[0]), "+f"(c[1]), "+f"(c[2]), "+f"(c[3])
                 : "r"(a[0]), "r"(a[1]), "r"(a[2]), "r"(a[3]), "r"(b[0]), "r"(b[1]));
}
__device__ __forceinline__ float sigm(float x) { return 1.f / (1.f + __expf(-x)); }

// ---------------- merged row LayerNorm (s and a in one launch) ----------------
__global__ __launch_bounds__(256) void ln2_kernel(const float* __restrict__ sx,
                                                  const float* __restrict__ lnw,
                                                  float* __restrict__ sny,
                                                  const float* __restrict__ ax,
                                                  float* __restrict__ any) {
    const float* x; const float* w; float* y; int COLS;
    if (blockIdx.y == 0) { x = sx; w = lnw;     y = sny; COLS = S_; }
    else                 { x = ax; w = nullptr; y = any; COLS = A_; }
    int row = blockIdx.x;
    const float* xr = x + (size_t)row * COLS;
    float s = 0.f, s2 = 0.f;
    for (int c = threadIdx.x; c < COLS; c += blockDim.x) {
        float v = xr[c]; s += v; s2 += v * v;
    }
    __shared__ float red[64];
    #pragma unroll
    for (int o = 16; o; o >>= 1) {
        s  += __shfl_xor_sync(0xffffffffu, s,  o);
        s2 += __shfl_xor_sync(0xffffffffu, s2, o);
    }
    int wid = threadIdx.x >> 5, lid = threadIdx.x & 31;
    if (lid == 0) { red[wid] = s; red[wid + 32] = s2; }
    __syncthreads();
    if (wid == 0) {
        s  = (lid < 8) ? red[lid]      : 0.f;
        s2 = (lid < 8) ? red[lid + 32] : 0.f;
        #pragma unroll
        for (int o = 4; o; o >>= 1) {
            s  += __shfl_xor_sync(0xffffffffu, s,  o);
            s2 += __shfl_xor_sync(0xffffffffu, s2, o);
        }
        if (lid == 0) { red[0] = s; red[1] = s2; }
    }
    __syncthreads();
    float mean = red[0] / COLS;
    float var  = red[1] / COLS - mean * mean;
    float rs   = rsqrtf(var + 1e-5f);
    float* yr = y + (size_t)row * COLS;
    for (int c = threadIdx.x; c < COLS; c += blockDim.x) {
        float v = (xr[c] - mean) * rs;
        if (w) v *= w[c];
        yr[c] = v;
    }
}

// ---------------- generic tf32 GEMM with epilogues ----------------
// EPI: 1=+bias 2=sigmoid(x+bias) 4=x*C2
template<int EPI>
__global__ __launch_bounds__(256) void gemm_tf32(const float* __restrict__ A,
                                                 const float* __restrict__ B,
                                                 float* __restrict__ C,
                                                 int K, int Nn,
                                                 const float* __restrict__ bias,
                                                 const float* __restrict__ C2) {
    __shared__ __align__(16) uint32_t As[64][36];
    __shared__ __align__(16) uint32_t Bs[32][72];
    int m0 = blockIdx.y * 64, n0 = blockIdx.x * 64;
    int tid = threadIdx.x, lane = tid & 31, warp = tid >> 5;
    int wm = (warp & 3) * 16, wn = (warp >> 2) * 32;
    int g = lane >> 2, t = lane & 3;

    int am = tid >> 3, akq = tid & 7;
    int bk = tid >> 4, bn4 = tid & 15;

    float4 pa[2], pb[2];
    #pragma unroll
    for (int it = 0; it < 2; it++) {
        pa[it] = *(const float4*)(A + (size_t)(m0 + am + it * 32) * K + akq * 4);
        pb[it] = *(const float4*)(B + (size_t)(bk + it * 16) * Nn + n0 + bn4 * 4);
    }

    float acc[4][4];
    #pragma unroll
    for (int i = 0; i < 4; i++)
        #pragma unroll
        for (int j = 0; j < 4; j++) acc[i][j] = 0.f;

    for (int kt = 0; kt < K; kt += 32) {
        __syncthreads();
        #pragma unroll
        for (int it = 0; it < 2; it++) {
            uint32_t* ap = &As[am + it * 32][akq * 4];
            ap[0] = f2tf(pa[it].x); ap[1] = f2tf(pa[it].y);
            ap[2] = f2tf(pa[it].z); ap[3] = f2tf(pa[it].w);
            uint32_t* bp = &Bs[bk + it * 16][bn4 * 4];
            bp[0] = f2tf(pb[it].x); bp[1] = f2tf(pb[it].y);
            bp[2] = f2tf(pb[it].z); bp[3] = f2tf(pb[it].w);
        }
        __syncthreads();
        if (kt + 32 < K) {
            #pragma unroll
            for (int it = 0; it < 2; it++) {
                pa[it] = *(const float4*)(A + (size_t)(m0 + am + it * 32) * K + kt + 32 + akq * 4);
                pb[it] = *(const float4*)(B + (size_t)(kt + 32 + bk + it * 16) * Nn + n0 + bn4 * 4);
            }
        }
        #pragma unroll
        for (int k8 = 0; k8 < 32; k8 += 8) {
            uint32_t a[4] = {As[wm + g][k8 + t],     As[wm + g + 8][k8 + t],
                             As[wm + g][k8 + t + 4], As[wm + g + 8][k8 + t + 4]};
            #pragma unroll
            for (int nt = 0; nt < 4; nt++) {
                uint32_t b[2] = {Bs[k8 + t][wn + nt * 8 + g], Bs[k8 + t + 4][wn + nt * 8 + g]};
                mma_tf32(acc[nt], a, b);
            }
        }
    }
    #pragma unroll
    for (int nt = 0; nt < 4; nt++) {
        int col = n0 + wn + nt * 8 + t * 2;
        #pragma unroll
        for (int half = 0; half < 2; half++) {
            int row = m0 + wm + g + half * 8;
            float v0 = acc[nt][half * 2 + 0], v1 = acc[nt][half * 2 + 1];
            if (EPI == 1) { v0 += bias[col]; v1 += bias[col + 1]; }
            if (EPI == 2) { v0 = sigm(v0 + bias[col]); v1 = sigm(v1 + bias[col + 1]); }
            if (EPI == 4) { v0 *= C2[(size_t)row * Nn + col]; v1 *= C2[(size_t)row * Nn + col + 1]; }
            C[(size_t)row * Nn + col]     = v0;
            C[(size_t)row * Nn + col + 1] = v1;
        }
    }
}

// ---------------- fused AdaLN ----------------
__global__ __launch_bounds__(256) void adaln_tf32(const float* __restrict__ SN,
                                                  const float* __restrict__ Wgam,
                                                  const float* __restrict__ gb,
                                                  const float* __restrict__ Wsh,
                                                  const float* __restrict__ AN,
                                                  float* __restrict__ A2) {
    __shared__ __align__(16) uint32_t As[64][36];
    __shared__ __align__(16) uint32_t B1s[32][72];
    __shared__ __align__(16) uint32_t B2s[32][72];
    const int K = S_, Nn = A_;
    int m0 = blockIdx.y * 64, n0 = blockIdx.x * 64;
    int tid = threadIdx.x, lane = tid & 31, warp = tid >> 5;
    int wm = (warp & 3) * 16, wn = (warp >> 2) * 32;
    int g = lane >> 2, t = lane & 3;

    int am = tid >> 3, akq = tid & 7;
    int bk = tid >> 4, bn4 = tid & 15;

    float4 pa[2], pb1[2], pb2[2];
    #pragma unroll
    for (int it = 0; it < 2; it++) {
        pa[it]  = *(const float4*)(SN   + (size_t)(m0 + am + it * 32) * K + akq * 4);
        pb1[it] = *(const float4*)(Wgam + (size_t)(bk + it * 16) * Nn + n0 + bn4 * 4);
        pb2[it] = *(const float4*)(Wsh  + (size_t)(bk + it * 16) * Nn + n0 + bn4 * 4);
    }
    float acc1[4][4], acc2[4][4];
    #pragma unroll
    for (int i = 0; i < 4; i++)
        #pragma unroll
        for (int j = 0; j < 4; j++) { acc1[i][j] = 0.f; acc2[i][j] = 0.f; }

    for (int kt = 0; kt < K; kt += 32) {
        __syncthreads();
        #pragma unroll
        for (int it = 0; it < 2; it++) {
            uint32_t* ap = &As[am + it * 32][akq * 4];
            ap[0] = f2tf(pa[it].x); ap[1] = f2tf(pa[it].y);
            ap[2] = f2tf(pa[it].z); ap[3] = f2tf(pa[it].w);
            uint32_t* b1 = &B1s[bk + it * 16][bn4 * 4];
            b1[0] = f2tf(pb1[it].x); b1[1] = f2tf(pb1[it].y);
            b1[2] = f2tf(pb1[it].z); b1[3] = f2tf(pb1[it].w);
            uint32_t* b2 = &B2s[bk + it * 16][bn4 * 4];
            b2[0] = f2tf(pb2[it].x); b2[1] = f2tf(pb2[it].y);
            b2[2] = f2tf(pb2[it].z); b2[3] = f2tf(pb2[it].w);
        }
        __syncthreads();
        if (kt + 32 < K) {
            #pragma unroll
            for (int it = 0; it < 2; it++) {
                pa[it]  = *(const float4*)(SN   + (size_t)(m0 + am + it * 32) * K + kt + 32 + akq * 4);
                pb1[it] = *(const float4*)(Wgam + (size_t)(kt + 32 + bk + it * 16) * Nn + n0 + bn4 * 4);
                pb2[it] = *(const float4*)(Wsh  + (size_t)(kt + 32 + bk + it * 16) * Nn + n0 + bn4 * 4);
            }
        }
        #pragma unroll
        for (int k8 = 0; k8 < 32; k8 += 8) {
            uint32_t a[4] = {As[wm + g][k8 + t],     As[wm + g + 8][k8 + t],
                             As[wm + g][k8 + t + 4], As[wm + g + 8][k8 + t + 4]};
            #pragma unroll
            for (int nt = 0; nt < 4; nt++) {
                uint32_t b1[2] = {B1s[k8 + t][wn + nt * 8 + g], B1s[k8 + t + 4][wn + nt * 8 + g]};
                mma_tf32(acc1[nt], a, b1);
                uint32_t b2[2] = {B2s[k8 + t][wn + nt * 8 + g], B2s[k8 + t + 4][wn + nt * 8 + g]};
                mma_tf32(acc2[nt], a, b2);
            }
        }
    }
    #pragma unroll
    for (int nt = 0; nt < 4; nt++) {
        int col = n0 + wn + nt * 8 + t * 2;
        #pragma unroll
        for (int half = 0; half < 2; half++) {
            int row = m0 + wm + g + half * 8;
            #pragma unroll
            for (int e = 0; e < 2; e++) {
                float gv = sigm(acc1[nt][half * 2 + e] + gb[col + e]);
                float a2 = gv * AN[(size_t)row * Nn + col + e] + acc2[nt][half * 2 + e];
                A2[(size_t)row * Nn + col + e] = a2;
            }
        }
    }
}

// ---------------- fused QKVG ----------------
__global__ __launch_bounds__(256) void qkvg_tf32(const float* __restrict__ A2,
                                                 const float* __restrict__ Wq,
                                                 const float* __restrict__ bq,
                                                 const float* __restrict__ Wk,
                                                 const float* __restrict__ Wv,
                                                 const float* __restrict__ Wg,
                                                 float* __restrict__ oq, float* __restrict__ ok,
                                                 float* __restrict__ ov, float* __restrict__ og) {
    __shared__ __align__(16) uint32_t As[64][36];
    __shared__ __align__(16) uint32_t Bs[32][72];
    const int K = A_, Nn = A_;
    int z = blockIdx.z;
    const float* B = (z == 0) ? Wq : (z == 1) ? Wk : (z == 2) ? Wv : Wg;
    float* C = (z == 0) ? oq : (z == 1) ? ok : (z == 2) ? ov : og;

    int m0 = blockIdx.y * 64, n0 = blockIdx.x * 64;
    int tid = threadIdx.x, lane = tid & 31, warp = tid >> 5;
    int wm = (warp & 3) * 16, wn = (warp >> 2) * 32;
    int g = lane >> 2, t = lane & 3;
    int am = tid >> 3, akq = tid & 7;
    int bk = tid >> 4, bn4 = tid & 15;

    float4 pa[2], pb[2];
    #pragma unroll
    for (int it = 0; it < 2; it++) {
        pa[it] = *(const float4*)(A2 + (size_t)(m0 + am + it * 32) * K + akq * 4);
        pb[it] = *(const float4*)(B + (size_t)(bk + it * 16) * Nn + n0 + bn4 * 4);
    }
    float acc[4][4];
    #pragma unroll
    for (int i = 0; i < 4; i++)
        #pragma unroll
        for (int j = 0; j < 4; j++) acc[i][j] = 0.f;

    for (int kt = 0; kt < K; kt += 32) {
        __syncthreads();
        #pragma unroll
        for (int it = 0; it < 2; it++) {
            uint32_t* ap = &As[am + it * 32][akq * 4];
            ap[0] = f2tf(pa[it].x); ap[1] = f2tf(pa[it].y);
            ap[2] = f2tf(pa[it].z); ap[3] = f2tf(pa[it].w);
            uint32_t* bp = &Bs[bk + it * 16][bn4 * 4];
            bp[0] = f2tf(pb[it].x); bp[1] = f2tf(pb[it].y);
            bp[2] = f2tf(pb[it].z); bp[3] = f2tf(pb[it].w);
        }
        __syncthreads();
        if (kt + 32 < K) {
            #pragma unroll
            for (int it = 0; it < 2; it++) {
                pa[it] = *(const float4*)(A2 + (size_t)(m0 + am + it * 32) * K + kt + 32 + akq * 4);
                pb[it] = *(const float4*)(B + (size_t)(kt + 32 + bk + it * 16) * Nn + n0 + bn4 * 4);
            }
        }
        #pragma unroll
        for (int k8 = 0; k8 < 32; k8 += 8) {
            uint32_t a[4] = {As[wm + g][k8 + t],     As[wm + g + 8][k8 + t],
                             As[wm + g][k8 + t + 4], As[wm + g + 8][k8 + t + 4]};
            #pragma unroll
            for (int nt = 0; nt < 4; nt++) {
                uint32_t b[2] = {Bs[k8 + t][wn + nt * 8 + g], Bs[k8 + t + 4][wn + nt * 8 + g]};
                mma_tf32(acc[nt], a, b);
            }
        }
    }
    #pragma unroll
    for (int nt = 0; nt < 4; nt++) {
        int col = n0 + wn + nt * 8 + t * 2;
        #pragma unroll
        for (int half = 0; half < 2; half++) {
            int row = m0 + wm + g + half * 8;
            #pragma unroll
            for (int e = 0; e < 2; e++) {
                float v = acc[nt][half * 2 + e];
                if (z == 0) v += bq[col + e];
                if (z == 3) v = sigm(v);
                C[(size_t)row * Nn + col + e] = v;
            }
        }
    }
}

// ---------------- pair bias via tensor cores ----------------
// block: 64 pairs, 256 threads = 8 warps.
// LN stats in regs (4 thr/row, quad shuffles); normalized rows staged tf32 in
// As (stride 140: STS.128 and A-fragment conflict-free); Wb in Bs (stride 24).
// mma stage: warp w -> rows (w&3)*16 + {g,g+8}, head half (w>>2)*8. 16 mma/warp.
__global__ __launch_bounds__(256) void pairbias_mma(const float* __restrict__ pair,
                                                    const float* __restrict__ beta,
                                                    const float* __restrict__ w,
                                                    const float* __restrict__ b,
                                                    const float* __restrict__ Wb,
                                                    float* __restrict__ bias) {
    __shared__ __align__(16) uint32_t As[64 * 140];
    __shared__ __align__(16) uint32_t Bs[128 * 24];

    int tid = threadIdx.x, lane = tid & 31, warp = tid >> 5;
    int r  = tid >> 2;        // row in tile 0..63
    int pq = tid & 3;         // quarter of row
    int p0 = blockIdx.x * 64;

    // Wb -> Bs
    for (int i = tid; i < P_ * H_; i += 256) {
        int kk = i >> 4, nn = i & 15;
        Bs[kk * 24 + nn] = f2tf(__ldg(Wb + i));
    }

    // load my 4x8 floats of row r: cols 8*pq + 32*j + e
    const float* row = pair + (size_t)(p0 + r) * P_;
    float4 u[4][2];
    float s = 0.f, s2 = 0.f;
    #pragma unroll
    for (int j = 0; j < 4; j++) {
        u[j][0] = *(const float4*)(row + 8 * pq + 32 * j);
        u[j][1] = *(const float4*)(row + 8 * pq + 32 * j + 4);
        #pragma unroll
        for (int h2 = 0; h2 < 2; h2++) {
            const float4 f = u[j][h2];
            s  += f.x + f.y + f.z + f.w;
            s2 += f.x * f.x + f.y * f.y + f.z * f.z + f.w * f.w;
        }
    }
    s  += __shfl_xor_sync(0xffffffffu, s, 1);  s  += __shfl_xor_sync(0xffffffffu, s, 2);
    s2 += __shfl_xor_sync(0xffffffffu, s2, 1); s2 += __shfl_xor_sync(0xffffffffu, s2, 2);
    float mean = s * (1.f / P_);
    float var  = s2 * (1.f / P_) - mean * mean;
    float rs   = rsqrtf(var + 1e-5f);

    // normalize * w + b -> tf32 smem
    #pragma unroll
    for (int j = 0; j < 4; j++) {
        int c0 = 8 * pq + 32 * j;
        #pragma unroll
        for (int h2 = 0; h2 < 2; h2++) {
            const float4 wv = *(const float4*)(w + c0 + 4 * h2);
            const float4 bv = *(const float4*)(b + c0 + 4 * h2);
            const float4 f  = u[j][h2];
            uint4 pkt;
            pkt.x = f2tf((f.x - mean) * rs * wv.x + bv.x);
            pkt.y = f2tf((f.y - mean) * rs * wv.y + bv.y);
            pkt.z = f2tf((f.z - mean) * rs * wv.z + bv.z);
            pkt.w = f2tf((f.w - mean) * rs * wv.w + bv.w);
            *(uint4*)&As[r * 140 + c0 + 4 * h2] = pkt;
        }
    }
    __syncthreads();

    // mma: warp -> 16 rows x 8 heads
    int g = lane >> 2, t = lane & 3;
    int wm = (warp & 3) * 16;       // row offset 0/16/32/48
    int hh = (warp >> 2) * 8;       // head offset 0/8
    float acc[4] = {0.f, 0.f, 0.f, 0.f};
    #pragma unroll
    for (int k8 = 0; k8 < 16; k8++) {
        int k = k8 * 8;
        uint32_t a[4] = {As[(wm + g) * 140 + k + t],     As[(wm + g + 8) * 140 + k + t],
                         As[(wm + g) * 140 + k + t + 4], As[(wm + g + 8) * 140 + k + t + 4]};
        uint32_t bb[2] = {Bs[(k + t) * 24 + hh + g], Bs[(k + t + 4) * 24 + hh + g]};
        mma_tf32(acc, a, bb);
    }

    int pr0 = p0 + wm + g, pr1 = pr0 + 8;
    float be0 = __ldg(beta + pr0), be1 = __ldg(beta + pr1);
    int h0 = hh + 2 * t;
    bias[(size_t)(h0)     * NN + pr0] = acc[0] + be0;
    bias[(size_t)(h0 + 1) * NN + pr0] = acc[1] + be0;
    bias[(size_t)(h0)     * NN + pr1] = acc[2] + be1;
    bias[(size_t)(h0 + 1) * NN + pr1] = acc[3] + be1;
}

// ---------------- flash attention (tf32 mma), 32 q-rows / 2 warps ----------------
// smem strides conflict-free per fragment pattern:
//   Q,K stride 52 (bank 20g+t), V stride 56 (bank 24t+g), P stride 68 (bank 4g+t)
#define AQ(r,c) smQ[(r)*52+(c)]
#define AK(r,c) smK[(r)*52+(c)]
#define AV(r,c) smV[(r)*56+(c)]
#define AP(r,c) smP[(r)*68+(c)]
#define ATTN_SMEM ((32*52 + 64*52 + 64*56 + 32*68)*4)

__global__ __launch_bounds__(64) void attn_tf32(const float* __restrict__ q,
                                                const float* __restrict__ k,
                                                const float* __restrict__ v,
                                                const float* __restrict__ bias,
                                                const float* __restrict__ gt,
                                                float* __restrict__ o) {
    extern __shared__ uint32_t sm[];
    uint32_t* smQ = sm;
    uint32_t* smK = smQ + 32 * 52;
    uint32_t* smV = smK + 64 * 52;
    uint32_t* smP = smV + 64 * 56;

    int h  = blockIdx.y;
    int q0 = blockIdx.x * 32;
    int tid = threadIdx.x, lane = tid & 31, warp = tid >> 5;
    int g = lane >> 2, t = lane & 3;
    int wm = warp * 16;

    // load Q tile (32 x 48) as tf32
    #pragma unroll
    for (int it = 0; it < 6; it++) {
        int idx = tid + it * 64;
        int r = idx / 12, c4 = idx % 12;
        float4 v4 = *(const float4*)(q + (size_t)(q0 + r) * A_ + h * D_ + c4 * 4);
        AQ(r, c4 * 4 + 0) = f2tf(v4.x); AQ(r, c4 * 4 + 1) = f2tf(v4.y);
        AQ(r, c4 * 4 + 2) = f2tf(v4.z); AQ(r, c4 * 4 + 3) = f2tf(v4.w);
    }

    float m0 = -1e30f, m1 = -1e30f, l0 = 0.f, l1 = 0.f;
    float oacc[6][4];
    #pragma unroll
    for (int dt = 0; dt < 6; dt++)
        #pragma unroll
        for (int e = 0; e < 4; e++) oacc[dt][e] = 0.f;

    const float scale = 0.144337567f;   // 1/sqrt(48)

    for (int j0 = 0; j0 < N_; j0 += 64) {
        __syncthreads();
        #pragma unroll
        for (int it = 0; it < 12; it++) {
            int idx = tid + it * 64;
            int r = idx / 12, c4 = idx % 12;
            float4 kv = *(const float4*)(k + (size_t)(j0 + r) * A_ + h * D_ + c4 * 4);
            AK(r, c4 * 4 + 0) = f2tf(kv.x); AK(r, c4 * 4 + 1) = f2tf(kv.y);
            AK(r, c4 * 4 + 2) = f2tf(kv.z); AK(r, c4 * 4 + 3) = f2tf(kv.w);
            float4 vv = *(const float4*)(v + (size_t)(j0 + r) * A_ + h * D_ + c4 * 4);
            AV(r, c4 * 4 + 0) = f2tf(vv.x); AV(r, c4 * 4 + 1) = f2tf(vv.y);
            AV(r, c4 * 4 + 2) = f2tf(vv.z); AV(r, c4 * 4 + 3) = f2tf(vv.w);
        }
        __syncthreads();

        // S = Q K^T  (warp: 16 rows x 64 keys)
        float sacc[8][4];
        #pragma unroll
        for (int nt = 0; nt < 8; nt++)
            #pragma unroll
            for (int e = 0; e < 4; e++) sacc[nt][e] = 0.f;

        #pragma unroll
        for (int k8 = 0; k8 < 48; k8 += 8) {
            uint32_t a[4] = {AQ(wm + g, k8 + t),     AQ(wm + g + 8, k8 + t),
                             AQ(wm + g, k8 + t + 4), AQ(wm + g + 8, k8 + t + 4)};
            #pragma unroll
            for (int nt = 0; nt < 8; nt++) {
                uint32_t b[2] = {AK(nt * 8 + g, k8 + t), AK(nt * 8 + g, k8 + t + 4)};
                mma_tf32(sacc[nt], a, b);
            }
        }

        // bias + scale at accumulator positions (float2 loads)
        const float* bp0 = bias + (size_t)h * NN + (size_t)(q0 + wm + g) * N_ + j0;
        const float* bp1 = bp0 + 8 * N_;
        #pragma unroll
        for (int nt = 0; nt < 8; nt++) {
            int c = nt * 8 + 2 * t;
            float2 b0 = *(const float2*)(bp0 + c);
            float2 b1 = *(const float2*)(bp1 + c);
            sacc[nt][0] = sacc[nt][0] * scale + b0.x;
            sacc[nt][1] = sacc[nt][1] * scale + b0.y;
            sacc[nt][2] = sacc[nt][2] * scale + b1.x;
            sacc[nt][3] = sacc[nt][3] * scale + b1.y;
        }

        // online softmax (rows wm+g and wm+g+8; quad-local reduction)
        float mx0 = -1e30f, mx1 = -1e30f;
        #pragma unroll
        for (int nt = 0; nt < 8; nt++) {
            mx0 = fmaxf(mx0, fmaxf(sacc[nt][0], sacc[nt][1]));
            mx1 = fmaxf(mx1, fmaxf(sacc[nt][2], sacc[nt][3]));
        }
        mx0 = fmaxf(mx0, __shfl_xor_sync(0xffffffffu, mx0, 1));
        mx0 = fmaxf(mx0, __shfl_xor_sync(0xffffffffu, mx0, 2));
        mx1 = fmaxf(mx1, __shfl_xor_sync(0xffffffffu, mx1, 1));
        mx1 = fmaxf(mx1, __shfl_xor_sync(0xffffffffu, mx1, 2));
        float mn0 = fmaxf(m0, mx0), mn1 = fmaxf(m1, mx1);
        float cr0 = __expf(m0 - mn0), cr1 = __expf(m1 - mn1);
        m0 = mn0; m1 = mn1;

        float s0 = 0.f, s1 = 0.f;
        #pragma unroll
        for (int nt = 0; nt < 8; nt++) {
            float p00 = __expf(sacc[nt][0] - mn0);
            float p01 = __expf(sacc[nt][1] - mn0);
            float p10 = __expf(sacc[nt][2] - mn1);
            float p11 = __expf(sacc[nt][3] - mn1);
            s0 += p00 + p01; s1 += p10 + p11;
            int c = nt * 8 + 2 * t;
            AP(wm + g, c)         = f2tf(p00);
            AP(wm + g, c + 1)     = f2tf(p01);
            AP(wm + g + 8, c)     = f2tf(p10);
            AP(wm + g + 8, c + 1) = f2tf(p11);
        }
        s0 += __shfl_xor_sync(0xffffffffu, s0, 1);
        s0 += __shfl_xor_sync(0xffffffffu, s0, 2);
        s1 += __shfl_xor_sync(0xffffffffu, s1, 1);
        s1 += __shfl_xor_sync(0xffffffffu, s1, 2);
        l0 = l0 * cr0 + s0;
        l1 = l1 * cr1 + s1;

        #pragma unroll
        for (int dt = 0; dt < 6; dt++) {
            oacc[dt][0] *= cr0; oacc[dt][1] *= cr0;
            oacc[dt][2] *= cr1; oacc[dt][3] *= cr1;
        }
        __syncwarp();

        // O += P V  (warp-private P)
        #pragma unroll
        for (int k8 = 0; k8 < 64; k8 += 8) {
            uint32_t a[4] = {AP(wm + g, k8 + t),     AP(wm + g + 8, k8 + t),
                             AP(wm + g, k8 + t + 4), AP(wm + g + 8, k8 + t + 4)};
            #pragma unroll
            for (int dt = 0; dt < 6; dt++) {
                uint32_t b[2] = {AV(k8 + t, dt * 8 + g), AV(k8 + t + 4, dt * 8 + g)};
                mma_tf32(oacc[dt], a, b);
            }
        }
    }

    // epilogue: normalize + gate
    float inv0 = 1.f / l0, inv1 = 1.f / l1;
    int r0 = q0 + wm + g, r1 = r0 + 8;
    #pragma unroll
    for (int dt = 0; dt < 6; dt++) {
        int d = dt * 8 + 2 * t;
        size_t i00 = (size_t)r0 * A_ + h * D_ + d;
        size_t i10 = (size_t)r1 * A_ + h * D_ + d;
        o[i00]     = oacc[dt][0] * inv0 * gt[i00];
        o[i00 + 1] = oacc[dt][1] * inv0 * gt[i00 + 1];
        o[i10]     = oacc[dt][2] * inv1 * gt[i10];
        o[i10 + 1] = oacc[dt][3] * inv1 * gt[i10 + 1];
    }
}

// ---------------- launch ----------------
extern "C" void kernel_launch(void* const* d_in, const int* in_sizes, int n_in,
                              void* d_out, int out_size) {
    const float* a       = (const float*)d_in[0];
    const float* s       = (const float*)d_in[1];
    const float* pair    = (const float*)d_in[2];
    const float* beta    = (const float*)d_in[3];
    const float* ln_s_w  = (const float*)d_in[4];
    const float* gamma_w = (const float*)d_in[5];
    const float* gamma_b = (const float*)d_in[6];
    const float* shift_w = (const float*)d_in[7];
    const float* Wq      = (const float*)d_in[8];
    const float* bq      = (const float*)d_in[9];
    const float* Wk      = (const float*)d_in[10];
    const float* Wv      = (const float*)d_in[11];
    const float* ln_p_w  = (const float*)d_in[12];
    const float* ln_p_b  = (const float*)d_in[13];
    const float* Wb      = (const float*)d_in[14];
    const float* Wg      = (const float*)d_in[15];
    const float* Wp      = (const float*)d_in[16];
    const float* Wout    = (const float*)d_in[17];
    const float* bout    = (const float*)d_in[18];
    float* out = (float*)d_out;

    float *p_sn, *p_an, *p_a2, *p_q, *p_k, *p_v, *p_gt, *p_bias, *p_o, *p_gate;
    cudaGetSymbolAddress((void**)&p_sn,   d_sn);
    cudaGetSymbolAddress((void**)&p_an,   d_an);
    cudaGetSymbolAddress((void**)&p_a2,   d_a2);
    cudaGetSymbolAddress((void**)&p_q,    d_q);
    cudaGetSymbolAddress((void**)&p_k,    d_k);
    cudaGetSymbolAddress((void**)&p_v,    d_v);
    cudaGetSymbolAddress((void**)&p_gt,   d_gt);
    cudaGetSymbolAddress((void**)&p_bias, d_bias);
    cudaGetSymbolAddress((void**)&p_o,    d_o);
    cudaGetSymbolAddress((void**)&p_gate, d_gate);

    cudaFuncSetAttribute(attn_tf32, cudaFuncAttributeMaxDynamicSharedMemorySize, ATTN_SMEM);

    dim3 g2(A_ / 64, N_ / 64);          // 12 x 12
    dim3 gz(A_ / 64, N_ / 64, 4);       // QKVG

    pairbias_mma<<<NN / 64, 256>>>(pair, beta, ln_p_w, ln_p_b, Wb, p_bias);
    ln2_kernel<<<dim3(N_, 2), 256>>>(s, ln_s_w, p_sn, a, p_an);
    adaln_tf32<<<g2, 256>>>(p_sn, gamma_w, gamma_b, shift_w, p_an, p_a2);
    qkvg_tf32<<<gz, 256>>>(p_a2, Wq, bq, Wk, Wv, Wg, p_q, p_k, p_v, p_gt);
    gemm_tf32<2><<<g2, 256>>>(s, Wout, p_gate, S_, A_, bout, nullptr);
    dim3 ga(N_ / 32, H_);
    attn_tf32<<<ga, 64, ATTN_SMEM>>>(p_q, p_k, p_v, p_bias, p_gt, p_o);
    gemm_tf32<4><<<g2, 256>>>(p_o, Wp, out, A_, A_, nullptr, p_gate);
}

// round 7
// speedup vs baseline: 6.8520x; 1.0658x over previous
#include <cuda_runtime.h>
#include <math.h>
#include <stdint.h>

#define N_  768
#define A_  768
#define S_  384
#define P_  128
#define H_  16
#define D_  48
#define NN  (N_*N_)

// ---------------- scratch (no allocations allowed) ----------------
__device__ float d_sn [N_*S_];
__device__ float d_an [N_*A_];
__device__ float d_a2 [N_*A_];
__device__ float d_q  [N_*A_];
__device__ float d_k  [N_*A_];
__device__ float d_v  [N_*A_];
__device__ float d_gt [N_*A_];
__device__ float d_bias[H_*NN];         // [H][N][N]
__device__ float d_o  [N_*A_];
__device__ float d_gate[N_*A_];

// ---------------- helpers ----------------
__device__ __forceinline__ uint32_t f2tf(float f) {
    uint32_t u;
    asm("cvt.rna.tf32.f32 %0, %1;" : "=r"(u) : "f"(f));
    return u;
}
__device__ __forceinline__ void mma_tf32(float* c, const uint32_t* a, const uint32_t* b) {
    asm volatile("mma.sync.aligned.m16n8k8.row.col.f32.tf32.tf32.f32 "
                 "{%0,%1,%2,%3}, {%4,%5,%6,%7}, {%8,%9}, {%0,%1,%2,%3};"
                 : "+f"(c[0]), "+f"(c[1]), "+f"(c[2]), "+f"(c[3])
                 : "r"(a[0]), "r"(a[1]), "r"(a[2]), "r"(a[3]), "r"(b[0]), "r"(b[1]));
}
__device__ __forceinline__ float sigm(float x) { return 1.f / (1.f + __expf(-x)); }

// ---------------- merged row LayerNorm (s and a in one launch) ----------------
__global__ __launch_bounds__(256) void ln2_kernel(const float* __restrict__ sx,
                                                  const float* __restrict__ lnw,
                                                  float* __restrict__ sny,
                                                  const float* __restrict__ ax,
                                                  float* __restrict__ any) {
    const float* x; const float* w; float* y; int COLS;
    if (blockIdx.y == 0) { x = sx; w = lnw;     y = sny; COLS = S_; }
    else                 { x = ax; w = nullptr; y = any; COLS = A_; }
    int row = blockIdx.x;
    const float* xr = x + (size_t)row * COLS;
    float s = 0.f, s2 = 0.f;
    for (int c = threadIdx.x; c < COLS; c += blockDim.x) {
        float v = xr[c]; s += v; s2 += v * v;
    }
    __shared__ float red[64];
    #pragma unroll
    for (int o = 16; o; o >>= 1) {
        s  += __shfl_xor_sync(0xffffffffu, s,  o);
        s2 += __shfl_xor_sync(0xffffffffu, s2, o);
    }
    int wid = threadIdx.x >> 5, lid = threadIdx.x & 31;
    if (lid == 0) { red[wid] = s; red[wid + 32] = s2; }
    __syncthreads();
    if (wid == 0) {
        s  = (lid < 8) ? red[lid]      : 0.f;
        s2 = (lid < 8) ? red[lid + 32] : 0.f;
        #pragma unroll
        for (int o = 4; o; o >>= 1) {
            s  += __shfl_xor_sync(0xffffffffu, s,  o);
            s2 += __shfl_xor_sync(0xffffffffu, s2, o);
        }
        if (lid == 0) { red[0] = s; red[1] = s2; }
    }
    __syncthreads();
    float mean = red[0] / COLS;
    float var  = red[1] / COLS - mean * mean;
    float rs   = rsqrtf(var + 1e-5f);
    float* yr = y + (size_t)row * COLS;
    for (int c = threadIdx.x; c < COLS; c += blockDim.x) {
        float v = (xr[c] - mean) * rs;
        if (w) v *= w[c];
        yr[c] = v;
    }
}

// ---------------- generic tf32 GEMM (standalone, for out-proj) ----------------
// EPI: 2=sigmoid(x+bias) 4=x*C2
template<int EPI>
__global__ __launch_bounds__(256) void gemm_tf32(const float* __restrict__ A,
                                                 const float* __restrict__ B,
                                                 float* __restrict__ C,
                                                 int K, int Nn,
                                                 const float* __restrict__ bias,
                                                 const float* __restrict__ C2) {
    __shared__ __align__(16) uint32_t As[64][36];
    __shared__ __align__(16) uint32_t Bs[32][72];
    int m0 = blockIdx.y * 64, n0 = blockIdx.x * 64;
    int tid = threadIdx.x, lane = tid & 31, warp = tid >> 5;
    int wm = (warp & 3) * 16, wn = (warp >> 2) * 32;
    int g = lane >> 2, t = lane & 3;

    int am = tid >> 3, akq = tid & 7;
    int bk = tid >> 4, bn4 = tid & 15;

    float4 pa[2], pb[2];
    #pragma unroll
    for (int it = 0; it < 2; it++) {
        pa[it] = *(const float4*)(A + (size_t)(m0 + am + it * 32) * K + akq * 4);
        pb[it] = *(const float4*)(B + (size_t)(bk + it * 16) * Nn + n0 + bn4 * 4);
    }
    float acc[4][4];
    #pragma unroll
    for (int i = 0; i < 4; i++)
        #pragma unroll
        for (int j = 0; j < 4; j++) acc[i][j] = 0.f;

    for (int kt = 0; kt < K; kt += 32) {
        __syncthreads();
        #pragma unroll
        for (int it = 0; it < 2; it++) {
            uint32_t* ap = &As[am + it * 32][akq * 4];
            ap[0] = f2tf(pa[it].x); ap[1] = f2tf(pa[it].y);
            ap[2] = f2tf(pa[it].z); ap[3] = f2tf(pa[it].w);
            uint32_t* bp = &Bs[bk + it * 16][bn4 * 4];
            bp[0] = f2tf(pb[it].x); bp[1] = f2tf(pb[it].y);
            bp[2] = f2tf(pb[it].z); bp[3] = f2tf(pb[it].w);
        }
        __syncthreads();
        if (kt + 32 < K) {
            #pragma unroll
            for (int it = 0; it < 2; it++) {
                pa[it] = *(const float4*)(A + (size_t)(m0 + am + it * 32) * K + kt + 32 + akq * 4);
                pb[it] = *(const float4*)(B + (size_t)(kt + 32 + bk + it * 16) * Nn + n0 + bn4 * 4);
            }
        }
        #pragma unroll
        for (int k8 = 0; k8 < 32; k8 += 8) {
            uint32_t a[4] = {As[wm + g][k8 + t],     As[wm + g + 8][k8 + t],
                             As[wm + g][k8 + t + 4], As[wm + g + 8][k8 + t + 4]};
            #pragma unroll
            for (int nt = 0; nt < 4; nt++) {
                uint32_t b[2] = {Bs[k8 + t][wn + nt * 8 + g], Bs[k8 + t + 4][wn + nt * 8 + g]};
                mma_tf32(acc[nt], a, b);
            }
        }
    }
    #pragma unroll
    for (int nt = 0; nt < 4; nt++) {
        int col = n0 + wn + nt * 8 + t * 2;
        #pragma unroll
        for (int half = 0; half < 2; half++) {
            int row = m0 + wm + g + half * 8;
            float v0 = acc[nt][half * 2 + 0], v1 = acc[nt][half * 2 + 1];
            if (EPI == 2) { v0 = sigm(v0 + bias[col]); v1 = sigm(v1 + bias[col + 1]); }
            if (EPI == 4) { v0 *= C2[(size_t)row * Nn + col]; v1 *= C2[(size_t)row * Nn + col + 1]; }
            C[(size_t)row * Nn + col]     = v0;
            C[(size_t)row * Nn + col + 1] = v1;
        }
    }
}

// ---------------- fused AdaLN ----------------
__global__ __launch_bounds__(256) void adaln_tf32(const float* __restrict__ SN,
                                                  const float* __restrict__ Wgam,
                                                  const float* __restrict__ gb,
                                                  const float* __restrict__ Wsh,
                                                  const float* __restrict__ AN,
                                                  float* __restrict__ A2) {
    __shared__ __align__(16) uint32_t As[64][36];
    __shared__ __align__(16) uint32_t B1s[32][72];
    __shared__ __align__(16) uint32_t B2s[32][72];
    const int K = S_, Nn = A_;
    int m0 = blockIdx.y * 64, n0 = blockIdx.x * 64;
    int tid = threadIdx.x, lane = tid & 31, warp = tid >> 5;
    int wm = (warp & 3) * 16, wn = (warp >> 2) * 32;
    int g = lane >> 2, t = lane & 3;

    int am = tid >> 3, akq = tid & 7;
    int bk = tid >> 4, bn4 = tid & 15;

    float4 pa[2], pb1[2], pb2[2];
    #pragma unroll
    for (int it = 0; it < 2; it++) {
        pa[it]  = *(const float4*)(SN   + (size_t)(m0 + am + it * 32) * K + akq * 4);
        pb1[it] = *(const float4*)(Wgam + (size_t)(bk + it * 16) * Nn + n0 + bn4 * 4);
        pb2[it] = *(const float4*)(Wsh  + (size_t)(bk + it * 16) * Nn + n0 + bn4 * 4);
    }
    float acc1[4][4], acc2[4][4];
    #pragma unroll
    for (int i = 0; i < 4; i++)
        #pragma unroll
        for (int j = 0; j < 4; j++) { acc1[i][j] = 0.f; acc2[i][j] = 0.f; }

    for (int kt = 0; kt < K; kt += 32) {
        __syncthreads();
        #pragma unroll
        for (int it = 0; it < 2; it++) {
            uint32_t* ap = &As[am + it * 32][akq * 4];
            ap[0] = f2tf(pa[it].x); ap[1] = f2tf(pa[it].y);
            ap[2] = f2tf(pa[it].z); ap[3] = f2tf(pa[it].w);
            uint32_t* b1 = &B1s[bk + it * 16][bn4 * 4];
            b1[0] = f2tf(pb1[it].x); b1[1] = f2tf(pb1[it].y);
            b1[2] = f2tf(pb1[it].z); b1[3] = f2tf(pb1[it].w);
            uint32_t* b2 = &B2s[bk + it * 16][bn4 * 4];
            b2[0] = f2tf(pb2[it].x); b2[1] = f2tf(pb2[it].y);
            b2[2] = f2tf(pb2[it].z); b2[3] = f2tf(pb2[it].w);
        }
        __syncthreads();
        if (kt + 32 < K) {
            #pragma unroll
            for (int it = 0; it < 2; it++) {
                pa[it]  = *(const float4*)(SN   + (size_t)(m0 + am + it * 32) * K + kt + 32 + akq * 4);
                pb1[it] = *(const float4*)(Wgam + (size_t)(kt + 32 + bk + it * 16) * Nn + n0 + bn4 * 4);
                pb2[it] = *(const float4*)(Wsh  + (size_t)(kt + 32 + bk + it * 16) * Nn + n0 + bn4 * 4);
            }
        }
        #pragma unroll
        for (int k8 = 0; k8 < 32; k8 += 8) {
            uint32_t a[4] = {As[wm + g][k8 + t],     As[wm + g + 8][k8 + t],
                             As[wm + g][k8 + t + 4], As[wm + g + 8][k8 + t + 4]};
            #pragma unroll
            for (int nt = 0; nt < 4; nt++) {
                uint32_t b1[2] = {B1s[k8 + t][wn + nt * 8 + g], B1s[k8 + t + 4][wn + nt * 8 + g]};
                mma_tf32(acc1[nt], a, b1);
                uint32_t b2[2] = {B2s[k8 + t][wn + nt * 8 + g], B2s[k8 + t + 4][wn + nt * 8 + g]};
                mma_tf32(acc2[nt], a, b2);
            }
        }
    }
    #pragma unroll
    for (int nt = 0; nt < 4; nt++) {
        int col = n0 + wn + nt * 8 + t * 2;
        #pragma unroll
        for (int half = 0; half < 2; half++) {
            int row = m0 + wm + g + half * 8;
            #pragma unroll
            for (int e = 0; e < 2; e++) {
                float gv = sigm(acc1[nt][half * 2 + e] + gb[col + e]);
                float a2 = gv * AN[(size_t)row * Nn + col + e] + acc2[nt][half * 2 + e];
                A2[(size_t)row * Nn + col + e] = a2;
            }
        }
    }
}

// ============================================================================
//  FUSED MID KERNEL: blockIdx.x ∈ [0,144) qkvg4 | [144,288) gate | [288,9504) pairbias
// ============================================================================

// --- role 1: QKVG, A staged once, 4 B matrices ---
__device__ __noinline__ void qkvg4_body(uint32_t* shm, int bx, int by,
                                        const float* __restrict__ A2,
                                        const float* __restrict__ Wq, const float* __restrict__ bq,
                                        const float* __restrict__ Wk, const float* __restrict__ Wv,
                                        const float* __restrict__ Wg,
                                        float* __restrict__ oq, float* __restrict__ ok,
                                        float* __restrict__ ov, float* __restrict__ og) {
    uint32_t* As = shm;                 // [64][36]
    uint32_t* Bs = shm + 64 * 36;       // [4][32][72]
    const int K = A_, Nn = A_;
    const float* Bp[4] = {Wq, Wk, Wv, Wg};
    float* Cp[4] = {oq, ok, ov, og};

    int m0 = by * 64, n0 = bx * 64;
    int tid = threadIdx.x, lane = tid & 31, warp = tid >> 5;
    int wm = (warp & 3) * 16, wn = (warp >> 2) * 32;
    int g = lane >> 2, t = lane & 3;
    int am = tid >> 3, akq = tid & 7;
    int bk = tid >> 4, bn4 = tid & 15;

    float4 pa[2], pb[4][2];
    #pragma unroll
    for (int it = 0; it < 2; it++) {
        pa[it] = *(const float4*)(A2 + (size_t)(m0 + am + it * 32) * K + akq * 4);
        #pragma unroll
        for (int z = 0; z < 4; z++)
            pb[z][it] = *(const float4*)(Bp[z] + (size_t)(bk + it * 16) * Nn + n0 + bn4 * 4);
    }
    float acc[4][4][4];
    #pragma unroll
    for (int z = 0; z < 4; z++)
        #pragma unroll
        for (int i = 0; i < 4; i++)
            #pragma unroll
            for (int j = 0; j < 4; j++) acc[z][i][j] = 0.f;

    for (int kt = 0; kt < K; kt += 32) {
        __syncthreads();
        #pragma unroll
        for (int it = 0; it < 2; it++) {
            uint32_t* ap = &As[(am + it * 32) * 36 + akq * 4];
            ap[0] = f2tf(pa[it].x); ap[1] = f2tf(pa[it].y);
            ap[2] = f2tf(pa[it].z); ap[3] = f2tf(pa[it].w);
            #pragma unroll
            for (int z = 0; z < 4; z++) {
                uint32_t* bp = &Bs[z * 32 * 72 + (bk + it * 16) * 72 + bn4 * 4];
                bp[0] = f2tf(pb[z][it].x); bp[1] = f2tf(pb[z][it].y);
                bp[2] = f2tf(pb[z][it].z); bp[3] = f2tf(pb[z][it].w);
            }
        }
        __syncthreads();
        if (kt + 32 < K) {
            #pragma unroll
            for (int it = 0; it < 2; it++) {
                pa[it] = *(const float4*)(A2 + (size_t)(m0 + am + it * 32) * K + kt + 32 + akq * 4);
                #pragma unroll
                for (int z = 0; z < 4; z++)
                    pb[z][it] = *(const float4*)(Bp[z] + (size_t)(kt + 32 + bk + it * 16) * Nn + n0 + bn4 * 4);
            }
        }
        #pragma unroll
        for (int k8 = 0; k8 < 32; k8 += 8) {
            uint32_t a[4] = {As[(wm + g) * 36 + k8 + t],     As[(wm + g + 8) * 36 + k8 + t],
                             As[(wm + g) * 36 + k8 + t + 4], As[(wm + g + 8) * 36 + k8 + t + 4]};
            #pragma unroll
            for (int z = 0; z < 4; z++) {
                #pragma unroll
                for (int nt = 0; nt < 4; nt++) {
                    uint32_t b[2] = {Bs[z * 32 * 72 + (k8 + t) * 72 + wn + nt * 8 + g],
                                     Bs[z * 32 * 72 + (k8 + t + 4) * 72 + wn + nt * 8 + g]};
                    mma_tf32(acc[z][nt], a, b);
                }
            }
        }
    }
    #pragma unroll
    for (int z = 0; z < 4; z++) {
        #pragma unroll
        for (int nt = 0; nt < 4; nt++) {
            int col = n0 + wn + nt * 8 + t * 2;
            #pragma unroll
            for (int half = 0; half < 2; half++) {
                int row = m0 + wm + g + half * 8;
                #pragma unroll
                for (int e = 0; e < 2; e++) {
                    float v = acc[z][nt][half * 2 + e];
                    if (z == 0) v += bq[col + e];
                    if (z == 3) v = sigm(v);
                    Cp[z][(size_t)row * Nn + col + e] = v;
                }
            }
        }
    }
}

// --- role 2: gate GEMM sigmoid(s @ Wout + bout) ---
__device__ __noinline__ void gate_body(uint32_t* shm, int bx, int by,
                                       const float* __restrict__ A,
                                       const float* __restrict__ B,
                                       const float* __restrict__ bias,
                                       float* __restrict__ C) {
    uint32_t* As = shm;             // [64][36]
    uint32_t* Bs = shm + 64 * 36;   // [32][72]
    const int K = S_, Nn = A_;
    int m0 = by * 64, n0 = bx * 64;
    int tid = threadIdx.x, lane = tid & 31, warp = tid >> 5;
    int wm = (warp & 3) * 16, wn = (warp >> 2) * 32;
    int g = lane >> 2, t = lane & 3;
    int am = tid >> 3, akq = tid & 7;
    int bk = tid >> 4, bn4 = tid & 15;

    float4 pa[2], pb[2];
    #pragma unroll
    for (int it = 0; it < 2; it++) {
        pa[it] = *(const float4*)(A + (size_t)(m0 + am + it * 32) * K + akq * 4);
        pb[it] = *(const float4*)(B + (size_t)(bk + it * 16) * Nn + n0 + bn4 * 4);
    }
    float acc[4][4];
    #pragma unroll
    for (int i = 0; i < 4; i++)
        #pragma unroll
        for (int j = 0; j < 4; j++) acc[i][j] = 0.f;

    for (int kt = 0; kt < K; kt += 32) {
        __syncthreads();
        #pragma unroll
        for (int it = 0; it < 2; it++) {
            uint32_t* ap = &As[(am + it * 32) * 36 + akq * 4];
            ap[0] = f2tf(pa[it].x); ap[1] = f2tf(pa[it].y);
            ap[2] = f2tf(pa[it].z); ap[3] = f2tf(pa[it].w);
            uint32_t* bp = &Bs[(bk + it * 16) * 72 + bn4 * 4];
            bp[0] = f2tf(pb[it].x); bp[1] = f2tf(pb[it].y);
            bp[2] = f2tf(pb[it].z); bp[3] = f2tf(pb[it].w);
        }
        __syncthreads();
        if (kt + 32 < K) {
            #pragma unroll
            for (int it = 0; it < 2; it++) {
                pa[it] = *(const float4*)(A + (size_t)(m0 + am + it * 32) * K + kt + 32 + akq * 4);
                pb[it] = *(const float4*)(B + (size_t)(kt + 32 + bk + it * 16) * Nn + n0 + bn4 * 4);
            }
        }
        #pragma unroll
        for (int k8 = 0; k8 < 32; k8 += 8) {
            uint32_t a[4] = {As[(wm + g) * 36 + k8 + t],     As[(wm + g + 8) * 36 + k8 + t],
                             As[(wm + g) * 36 + k8 + t + 4], As[(wm + g + 8) * 36 + k8 + t + 4]};
            #pragma unroll
            for (int nt = 0; nt < 4; nt++) {
                uint32_t b[2] = {Bs[(k8 + t) * 72 + wn + nt * 8 + g],
                                 Bs[(k8 + t + 4) * 72 + wn + nt * 8 + g]};
                mma_tf32(acc[nt], a, b);
            }
        }
    }
    #pragma unroll
    for (int nt = 0; nt < 4; nt++) {
        int col = n0 + wn + nt * 8 + t * 2;
        #pragma unroll
        for (int half = 0; half < 2; half++) {
            int row = m0 + wm + g + half * 8;
            float v0 = sigm(acc[nt][half * 2 + 0] + bias[col]);
            float v1 = sigm(acc[nt][half * 2 + 1] + bias[col + 1]);
            C[(size_t)row * Nn + col]     = v0;
            C[(size_t)row * Nn + col + 1] = v1;
        }
    }
}

// --- role 3: pairbias (LN + 128->16 proj + beta), mma ---
__device__ __noinline__ void pairbias_body(uint32_t* shm, int pbid,
                                           const float* __restrict__ pair,
                                           const float* __restrict__ beta,
                                           const float* __restrict__ w,
                                           const float* __restrict__ b,
                                           const float* __restrict__ Wb,
                                           float* __restrict__ bias) {
    uint32_t* As = shm;             // [64*140]
    uint32_t* Bs = shm + 64 * 140;  // [128*24]

    int tid = threadIdx.x, lane = tid & 31, warp = tid >> 5;
    int r  = tid >> 2;
    int pq = tid & 3;
    int p0 = pbid * 64;

    for (int i = tid; i < P_ * H_; i += 256) {
        int kk = i >> 4, nn = i & 15;
        Bs[kk * 24 + nn] = f2tf(__ldg(Wb + i));
    }

    const float* row = pair + (size_t)(p0 + r) * P_;
    float4 u[4][2];
    float s = 0.f, s2 = 0.f;
    #pragma unroll
    for (int j = 0; j < 4; j++) {
        u[j][0] = *(const float4*)(row + 8 * pq + 32 * j);
        u[j][1] = *(const float4*)(row + 8 * pq + 32 * j + 4);
        #pragma unroll
        for (int h2 = 0; h2 < 2; h2++) {
            const float4 f = u[j][h2];
            s  += f.x + f.y + f.z + f.w;
            s2 += f.x * f.x + f.y * f.y + f.z * f.z + f.w * f.w;
        }
    }
    s  += __shfl_xor_sync(0xffffffffu, s, 1);  s  += __shfl_xor_sync(0xffffffffu, s, 2);
    s2 += __shfl_xor_sync(0xffffffffu, s2, 1); s2 += __shfl_xor_sync(0xffffffffu, s2, 2);
    float mean = s * (1.f / P_);
    float var  = s2 * (1.f / P_) - mean * mean;
    float rs   = rsqrtf(var + 1e-5f);

    #pragma unroll
    for (int j = 0; j < 4; j++) {
        int c0 = 8 * pq + 32 * j;
        #pragma unroll
        for (int h2 = 0; h2 < 2; h2++) {
            const float4 wv = *(const float4*)(w + c0 + 4 * h2);
            const float4 bv = *(const float4*)(b + c0 + 4 * h2);
            const float4 f  = u[j][h2];
            uint4 pkt;
            pkt.x = f2tf((f.x - mean) * rs * wv.x + bv.x);
            pkt.y = f2tf((f.y - mean) * rs * wv.y + bv.y);
            pkt.z = f2tf((f.z - mean) * rs * wv.z + bv.z);
            pkt.w = f2tf((f.w - mean) * rs * wv.w + bv.w);
            *(uint4*)&As[r * 140 + c0 + 4 * h2] = pkt;
        }
    }
    __syncthreads();

    int g = lane >> 2, t = lane & 3;
    int wm = (warp & 3) * 16;
    int hh = (warp >> 2) * 8;
    float acc[4] = {0.f, 0.f, 0.f, 0.f};
    #pragma unroll
    for (int k8 = 0; k8 < 16; k8++) {
        int k = k8 * 8;
        uint32_t a[4] = {As[(wm + g) * 140 + k + t],     As[(wm + g + 8) * 140 + k + t],
                         As[(wm + g) * 140 + k + t + 4], As[(wm + g + 8) * 140 + k + t + 4]};
        uint32_t bb[2] = {Bs[(k + t) * 24 + hh + g], Bs[(k + t + 4) * 24 + hh + g]};
        mma_tf32(acc, a, bb);
    }

    int pr0 = p0 + wm + g, pr1 = pr0 + 8;
    float be0 = __ldg(beta + pr0), be1 = __ldg(beta + pr1);
    int h0 = hh + 2 * t;
    bias[(size_t)(h0)     * NN + pr0] = acc[0] + be0;
    bias[(size_t)(h0 + 1) * NN + pr0] = acc[1] + be0;
    bias[(size_t)(h0)     * NN + pr1] = acc[2] + be1;
    bias[(size_t)(h0 + 1) * NN + pr1] = acc[3] + be1;
}

#define FUSED_SMEM ((64*140 + 128*24)*4)   // 48128 B (union max)

__global__ __launch_bounds__(256) void fused_mid(
    const float* __restrict__ A2,
    const float* __restrict__ Wq, const float* __restrict__ bq,
    const float* __restrict__ Wk, const float* __restrict__ Wv,
    const float* __restrict__ Wg,
    float* __restrict__ oq, float* __restrict__ ok,
    float* __restrict__ ov, float* __restrict__ og,
    const float* __restrict__ sIn, const float* __restrict__ Wout,
    const float* __restrict__ bout, float* __restrict__ gate,
    const float* __restrict__ pair, const float* __restrict__ beta,
    const float* __restrict__ lnpw, const float* __restrict__ lnpb,
    const float* __restrict__ Wb, float* __restrict__ bias) {
    extern __shared__ __align__(16) uint32_t shm[];
    int bx = blockIdx.x;
    if (bx < 144) {
        qkvg4_body(shm, bx % 12, bx / 12, A2, Wq, bq, Wk, Wv, Wg, oq, ok, ov, og);
    } else if (bx < 288) {
        int i = bx - 144;
        gate_body(shm, i % 12, i / 12, sIn, Wout, bout, gate);
    } else {
        pairbias_body(shm, bx - 288, pair, beta, lnpw, lnpb, Wb, bias);
    }
}

// ---------------- flash attention (tf32 mma), 32 q-rows / 2 warps ----------------
#define AQ(r,c) smQ[(r)*52+(c)]
#define AK(r,c) smK[(r)*52+(c)]
#define AV(r,c) smV[(r)*56+(c)]
#define AP(r,c) smP[(r)*68+(c)]
#define ATTN_SMEM ((32*52 + 64*52 + 64*56 + 32*68)*4)

__global__ __launch_bounds__(64) void attn_tf32(const float* __restrict__ q,
                                                const float* __restrict__ k,
                                                const float* __restrict__ v,
                                                const float* __restrict__ bias,
                                                const float* __restrict__ gt,
                                                float* __restrict__ o) {
    extern __shared__ uint32_t sm[];
    uint32_t* smQ = sm;
    uint32_t* smK = smQ + 32 * 52;
    uint32_t* smV = smK + 64 * 52;
    uint32_t* smP = smV + 64 * 56;

    int h  = blockIdx.y;
    int q0 = blockIdx.x * 32;
    int tid = threadIdx.x, lane = tid & 31, warp = tid >> 5;
    int g = lane >> 2, t = lane & 3;
    int wm = warp * 16;

    #pragma unroll
    for (int it = 0; it < 6; it++) {
        int idx = tid + it * 64;
        int r = idx / 12, c4 = idx % 12;
        float4 v4 = *(const float4*)(q + (size_t)(q0 + r) * A_ + h * D_ + c4 * 4);
        AQ(r, c4 * 4 + 0) = f2tf(v4.x); AQ(r, c4 * 4 + 1) = f2tf(v4.y);
        AQ(r, c4 * 4 + 2) = f2tf(v4.z); AQ(r, c4 * 4 + 3) = f2tf(v4.w);
    }

    float m0 = -1e30f, m1 = -1e30f, l0 = 0.f, l1 = 0.f;
    float oacc[6][4];
    #pragma unroll
    for (int dt = 0; dt < 6; dt++)
        #pragma unroll
        for (int e = 0; e < 4; e++) oacc[dt][e] = 0.f;

    const float scale = 0.144337567f;

    for (int j0 = 0; j0 < N_; j0 += 64) {
        __syncthreads();
        #pragma unroll
        for (int it = 0; it < 12; it++) {
            int idx = tid + it * 64;
            int r = idx / 12, c4 = idx % 12;
            float4 kv = *(const float4*)(k + (size_t)(j0 + r) * A_ + h * D_ + c4 * 4);
            AK(r, c4 * 4 + 0) = f2tf(kv.x); AK(r, c4 * 4 + 1) = f2tf(kv.y);
            AK(r, c4 * 4 + 2) = f2tf(kv.z); AK(r, c4 * 4 + 3) = f2tf(kv.w);
            float4 vv = *(const float4*)(v + (size_t)(j0 + r) * A_ + h * D_ + c4 * 4);
            AV(r, c4 * 4 + 0) = f2tf(vv.x); AV(r, c4 * 4 + 1) = f2tf(vv.y);
            AV(r, c4 * 4 + 2) = f2tf(vv.z); AV(r, c4 * 4 + 3) = f2tf(vv.w);
        }
        __syncthreads();

        float sacc[8][4];
        #pragma unroll
        for (int nt = 0; nt < 8; nt++)
            #pragma unroll
            for (int e = 0; e < 4; e++) sacc[nt][e] = 0.f;

        #pragma unroll
        for (int k8 = 0; k8 < 48; k8 += 8) {
            uint32_t a[4] = {AQ(wm + g, k8 + t),     AQ(wm + g + 8, k8 + t),
                             AQ(wm + g, k8 + t + 4), AQ(wm + g + 8, k8 + t + 4)};
            #pragma unroll
            for (int nt = 0; nt < 8; nt++) {
                uint32_t b[2] = {AK(nt * 8 + g, k8 + t), AK(nt * 8 + g, k8 + t + 4)};
                mma_tf32(sacc[nt], a, b);
            }
        }

        const float* bp0 = bias + (size_t)h * NN + (size_t)(q0 + wm + g) * N_ + j0;
        const float* bp1 = bp0 + 8 * N_;
        #pragma unroll
        for (int nt = 0; nt < 8; nt++) {
            int c = nt * 8 + 2 * t;
            float2 b0 = *(const float2*)(bp0 + c);
            float2 b1 = *(const float2*)(bp1 + c);
            sacc[nt][0] = sacc[nt][0] * scale + b0.x;
            sacc[nt][1] = sacc[nt][1] * scale + b0.y;
            sacc[nt][2] = sacc[nt][2] * scale + b1.x;
            sacc[nt][3] = sacc[nt][3] * scale + b1.y;
        }

        float mx0 = -1e30f, mx1 = -1e30f;
        #pragma unroll
        for (int nt = 0; nt < 8; nt++) {
            mx0 = fmaxf(mx0, fmaxf(sacc[nt][0], sacc[nt][1]));
            mx1 = fmaxf(mx1, fmaxf(sacc[nt][2], sacc[nt][3]));
        }
        mx0 = fmaxf(mx0, __shfl_xor_sync(0xffffffffu, mx0, 1));
        mx0 = fmaxf(mx0, __shfl_xor_sync(0xffffffffu, mx0, 2));
        mx1 = fmaxf(mx1, __shfl_xor_sync(0xffffffffu, mx1, 1));
        mx1 = fmaxf(mx1, __shfl_xor_sync(0xffffffffu, mx1, 2));
        float mn0 = fmaxf(m0, mx0), mn1 = fmaxf(m1, mx1);
        float cr0 = __expf(m0 - mn0), cr1 = __expf(m1 - mn1);
        m0 = mn0; m1 = mn1;

        float s0 = 0.f, s1 = 0.f;
        #pragma unroll
        for (int nt = 0; nt < 8; nt++) {
            float p00 = __expf(sacc[nt][0] - mn0);
            float p01 = __expf(sacc[nt][1] - mn0);
            float p10 = __expf(sacc[nt][2] - mn1);
            float p11 = __expf(sacc[nt][3] - mn1);
            s0 += p00 + p01; s1 += p10 + p11;
            int c = nt * 8 + 2 * t;
            AP(wm + g, c)         = f2tf(p00);
            AP(wm + g, c + 1)     = f2tf(p01);
            AP(wm + g + 8, c)     = f2tf(p10);
            AP(wm + g + 8, c + 1) = f2tf(p11);
        }
        s0 += __shfl_xor_sync(0xffffffffu, s0, 1);
        s0 += __shfl_xor_sync(0xffffffffu, s0, 2);
        s1 += __shfl_xor_sync(0xffffffffu, s1, 1);
        s1 += __shfl_xor_sync(0xffffffffu, s1, 2);
        l0 = l0 * cr0 + s0;
        l1 = l1 * cr1 + s1;

        #pragma unroll
        for (int dt = 0; dt < 6; dt++) {
            oacc[dt][0] *= cr0; oacc[dt][1] *= cr0;
            oacc[dt][2] *= cr1; oacc[dt][3] *= cr1;
        }
        __syncwarp();

        #pragma unroll
        for (int k8 = 0; k8 < 64; k8 += 8) {
            uint32_t a[4] = {AP(wm + g, k8 + t),     AP(wm + g + 8, k8 + t),
                             AP(wm + g, k8 + t + 4), AP(wm + g + 8, k8 + t + 4)};
            #pragma unroll
            for (int dt = 0; dt < 6; dt++) {
                uint32_t b[2] = {AV(k8 + t, dt * 8 + g), AV(k8 + t + 4, dt * 8 + g)};
                mma_tf32(oacc[dt], a, b);
            }
        }
    }

    float inv0 = 1.f / l0, inv1 = 1.f / l1;
    int r0 = q0 + wm + g, r1 = r0 + 8;
    #pragma unroll
    for (int dt = 0; dt < 6; dt++) {
        int d = dt * 8 + 2 * t;
        size_t i00 = (size_t)r0 * A_ + h * D_ + d;
        size_t i10 = (size_t)r1 * A_ + h * D_ + d;
        o[i00]     = oacc[dt][0] * inv0 * gt[i00];
        o[i00 + 1] = oacc[dt][1] * inv0 * gt[i00 + 1];
        o[i10]     = oacc[dt][2] * inv1 * gt[i10];
        o[i10 + 1] = oacc[dt][3] * inv1 * gt[i10 + 1];
    }
}

// ---------------- launch ----------------
extern "C" void kernel_launch(void* const* d_in, const int* in_sizes, int n_in,
                              void* d_out, int out_size) {
    const float* a       = (const float*)d_in[0];
    const float* s       = (const float*)d_in[1];
    const float* pair    = (const float*)d_in[2];
    const float* beta    = (const float*)d_in[3];
    const float* ln_s_w  = (const float*)d_in[4];
    const float* gamma_w = (const float*)d_in[5];
    const float* gamma_b = (const float*)d_in[6];
    const float* shift_w = (const float*)d_in[7];
    const float* Wq      = (const float*)d_in[8];
    const float* bq      = (const float*)d_in[9];
    const float* Wk      = (const float*)d_in[10];
    const float* Wv      = (const float*)d_in[11];
    const float* ln_p_w  = (const float*)d_in[12];
    const float* ln_p_b  = (const float*)d_in[13];
    const float* Wb      = (const float*)d_in[14];
    const float* Wg      = (const float*)d_in[15];
    const float* Wp      = (const float*)d_in[16];
    const float* Wout    = (const float*)d_in[17];
    const float* bout    = (const float*)d_in[18];
    float* out = (float*)d_out;

    float *p_sn, *p_an, *p_a2, *p_q, *p_k, *p_v, *p_gt, *p_bias, *p_o, *p_gate;
    cudaGetSymbolAddress((void**)&p_sn,   d_sn);
    cudaGetSymbolAddress((void**)&p_an,   d_an);
    cudaGetSymbolAddress((void**)&p_a2,   d_a2);
    cudaGetSymbolAddress((void**)&p_q,    d_q);
    cudaGetSymbolAddress((void**)&p_k,    d_k);
    cudaGetSymbolAddress((void**)&p_v,    d_v);
    cudaGetSymbolAddress((void**)&p_gt,   d_gt);
    cudaGetSymbolAddress((void**)&p_bias, d_bias);
    cudaGetSymbolAddress((void**)&p_o,    d_o);
    cudaGetSymbolAddress((void**)&p_gate, d_gate);

    cudaFuncSetAttribute(attn_tf32,  cudaFuncAttributeMaxDynamicSharedMemorySize, ATTN_SMEM);
    cudaFuncSetAttribute(fused_mid,  cudaFuncAttributeMaxDynamicSharedMemorySize, FUSED_SMEM);

    dim3 g2(A_ / 64, N_ / 64);

    ln2_kernel<<<dim3(N_, 2), 256>>>(s, ln_s_w, p_sn, a, p_an);
    adaln_tf32<<<g2, 256>>>(p_sn, gamma_w, gamma_b, shift_w, p_an, p_a2);
    fused_mid<<<288 + NN / 64, 256, FUSED_SMEM>>>(
        p_a2, Wq, bq, Wk, Wv, Wg, p_q, p_k, p_v, p_gt,
        s, Wout, bout, p_gate,
        pair, beta, ln_p_w, ln_p_b, Wb, p_bias);
    dim3 ga(N_ / 32, H_);
    attn_tf32<<<ga, 64, ATTN_SMEM>>>(p_q, p_k, p_v, p_bias, p_gt, p_o);
    gemm_tf32<4><<<g2, 256>>>(p_o, Wp, out, A_, A_, nullptr, p_gate);
}

// round 8
// speedup vs baseline: 7.5276x; 1.0986x over previous
#include <cuda_runtime.h>
#include <math.h>
#include <stdint.h>

#define N_  768
#define A_  768
#define S_  384
#define P_  128
#define H_  16
#define D_  48
#define NN  (N_*N_)

// ---------------- scratch (no allocations allowed) ----------------
__device__ float d_sn [N_*S_];
__device__ float d_an [N_*A_];
__device__ float d_a2 [N_*A_];
__device__ float d_q  [N_*A_];
__device__ float d_k  [N_*A_];
__device__ float d_v  [N_*A_];
__device__ float d_gt [N_*A_];
__device__ float d_bias[H_*NN];         // [H][N][N]
__device__ float d_o  [N_*A_];
__device__ float d_gate[N_*A_];
__device__ float d_opart[2*N_*A_];      // split-KV unnormalized partials
__device__ float2 d_ml[2*H_*N_];        // (m, l) per split/head/row

// ---------------- helpers ----------------
__device__ __forceinline__ uint32_t f2tf(float f) {
    uint32_t u;
    asm("cvt.rna.tf32.f32 %0, %1;" : "=r"(u) : "f"(f));
    return u;
}
__device__ __forceinline__ void mma_tf32(float* c, const uint32_t* a, const uint32_t* b) {
    asm volatile("mma.sync.aligned.m16n8k8.row.col.f32.tf32.tf32.f32 "
                 "{%0,%1,%2,%3}, {%4,%5,%6,%7}, {%8,%9}, {%0,%1,%2,%3};"
                 : "+f"(c[0]), "+f"(c[1]), "+f"(c[2]), "+f"(c[3])
                 : "r"(a[0]), "r"(a[1]), "r"(a[2]), "r"(a[3]), "r"(b[0]), "r"(b[1]));
}
__device__ __forceinline__ float sigm(float x) { return 1.f / (1.f + __expf(-x)); }

// ---------------- merged row LayerNorm (s and a in one launch) ----------------
__global__ __launch_bounds__(256) void ln2_kernel(const float* __restrict__ sx,
                                                  const float* __restrict__ lnw,
                                                  float* __restrict__ sny,
                                                  const float* __restrict__ ax,
                                                  float* __restrict__ any) {
    const float* x; const float* w; float* y; int COLS;
    if (blockIdx.y == 0) { x = sx; w = lnw;     y = sny; COLS = S_; }
    else                 { x = ax; w = nullptr; y = any; COLS = A_; }
    int row = blockIdx.x;
    const float* xr = x + (size_t)row * COLS;
    float s = 0.f, s2 = 0.f;
    for (int c = threadIdx.x; c < COLS; c += blockDim.x) {
        float v = xr[c]; s += v; s2 += v * v;
    }
    __shared__ float red[64];
    #pragma unroll
    for (int o = 16; o; o >>= 1) {
        s  += __shfl_xor_sync(0xffffffffu, s,  o);
        s2 += __shfl_xor_sync(0xffffffffu, s2, o);
    }
    int wid = threadIdx.x >> 5, lid = threadIdx.x & 31;
    if (lid == 0) { red[wid] = s; red[wid + 32] = s2; }
    __syncthreads();
    if (wid == 0) {
        s  = (lid < 8) ? red[lid]      : 0.f;
        s2 = (lid < 8) ? red[lid + 32] : 0.f;
        #pragma unroll
        for (int o = 4; o; o >>= 1) {
            s  += __shfl_xor_sync(0xffffffffu, s,  o);
            s2 += __shfl_xor_sync(0xffffffffu, s2, o);
        }
        if (lid == 0) { red[0] = s; red[1] = s2; }
    }
    __syncthreads();
    float mean = red[0] / COLS;
    float var  = red[1] / COLS - mean * mean;
    float rs   = rsqrtf(var + 1e-5f);
    float* yr = y + (size_t)row * COLS;
    for (int c = threadIdx.x; c < COLS; c += blockDim.x) {
        float v = (xr[c] - mean) * rs;
        if (w) v *= w[c];
        yr[c] = v;
    }
}

// ---------------- generic tf32 GEMM (standalone, for out-proj) ----------------
// EPI: 4=x*C2
template<int EPI>
__global__ __launch_bounds__(256) void gemm_tf32(const float* __restrict__ A,
                                                 const float* __restrict__ B,
                                                 float* __restrict__ C,
                                                 int K, int Nn,
                                                 const float* __restrict__ bias,
                                                 const float* __restrict__ C2) {
    __shared__ __align__(16) uint32_t As[64][36];
    __shared__ __align__(16) uint32_t Bs[32][72];
    int m0 = blockIdx.y * 64, n0 = blockIdx.x * 64;
    int tid = threadIdx.x, lane = tid & 31, warp = tid >> 5;
    int wm = (warp & 3) * 16, wn = (warp >> 2) * 32;
    int g = lane >> 2, t = lane & 3;

    int am = tid >> 3, akq = tid & 7;
    int bk = tid >> 4, bn4 = tid & 15;

    float4 pa[2], pb[2];
    #pragma unroll
    for (int it = 0; it < 2; it++) {
        pa[it] = *(const float4*)(A + (size_t)(m0 + am + it * 32) * K + akq * 4);
        pb[it] = *(const float4*)(B + (size_t)(bk + it * 16) * Nn + n0 + bn4 * 4);
    }
    float acc[4][4];
    #pragma unroll
    for (int i = 0; i < 4; i++)
        #pragma unroll
        for (int j = 0; j < 4; j++) acc[i][j] = 0.f;

    for (int kt = 0; kt < K; kt += 32) {
        __syncthreads();
        #pragma unroll
        for (int it = 0; it < 2; it++) {
            uint32_t* ap = &As[am + it * 32][akq * 4];
            ap[0] = f2tf(pa[it].x); ap[1] = f2tf(pa[it].y);
            ap[2] = f2tf(pa[it].z); ap[3] = f2tf(pa[it].w);
            uint32_t* bp = &Bs[bk + it * 16][bn4 * 4];
            bp[0] = f2tf(pb[it].x); bp[1] = f2tf(pb[it].y);
            bp[2] = f2tf(pb[it].z); bp[3] = f2tf(pb[it].w);
        }
        __syncthreads();
        if (kt + 32 < K) {
            #pragma unroll
            for (int it = 0; it < 2; it++) {
                pa[it] = *(const float4*)(A + (size_t)(m0 + am + it * 32) * K + kt + 32 + akq * 4);
                pb[it] = *(const float4*)(B + (size_t)(kt + 32 + bk + it * 16) * Nn + n0 + bn4 * 4);
            }
        }
        #pragma unroll
        for (int k8 = 0; k8 < 32; k8 += 8) {
            uint32_t a[4] = {As[wm + g][k8 + t],     As[wm + g + 8][k8 + t],
                             As[wm + g][k8 + t + 4], As[wm + g + 8][k8 + t + 4]};
            #pragma unroll
            for (int nt = 0; nt < 4; nt++) {
                uint32_t b[2] = {Bs[k8 + t][wn + nt * 8 + g], Bs[k8 + t + 4][wn + nt * 8 + g]};
                mma_tf32(acc[nt], a, b);
            }
        }
    }
    #pragma unroll
    for (int nt = 0; nt < 4; nt++) {
        int col = n0 + wn + nt * 8 + t * 2;
        #pragma unroll
        for (int half = 0; half < 2; half++) {
            int row = m0 + wm + g + half * 8;
            float v0 = acc[nt][half * 2 + 0], v1 = acc[nt][half * 2 + 1];
            if (EPI == 4) { v0 *= C2[(size_t)row * Nn + col]; v1 *= C2[(size_t)row * Nn + col + 1]; }
            C[(size_t)row * Nn + col]     = v0;
            C[(size_t)row * Nn + col + 1] = v1;
        }
    }
}

// ---------------- fused AdaLN ----------------
__global__ __launch_bounds__(256) void adaln_tf32(const float* __restrict__ SN,
                                                  const float* __restrict__ Wgam,
                                                  const float* __restrict__ gb,
                                                  const float* __restrict__ Wsh,
                                                  const float* __restrict__ AN,
                                                  float* __restrict__ A2) {
    __shared__ __align__(16) uint32_t As[64][36];
    __shared__ __align__(16) uint32_t B1s[32][72];
    __shared__ __align__(16) uint32_t B2s[32][72];
    const int K = S_, Nn = A_;
    int m0 = blockIdx.y * 64, n0 = blockIdx.x * 64;
    int tid = threadIdx.x, lane = tid & 31, warp = tid >> 5;
    int wm = (warp & 3) * 16, wn = (warp >> 2) * 32;
    int g = lane >> 2, t = lane & 3;

    int am = tid >> 3, akq = tid & 7;
    int bk = tid >> 4, bn4 = tid & 15;

    float4 pa[2], pb1[2], pb2[2];
    #pragma unroll
    for (int it = 0; it < 2; it++) {
        pa[it]  = *(const float4*)(SN   + (size_t)(m0 + am + it * 32) * K + akq * 4);
        pb1[it] = *(const float4*)(Wgam + (size_t)(bk + it * 16) * Nn + n0 + bn4 * 4);
        pb2[it] = *(const float4*)(Wsh  + (size_t)(bk + it * 16) * Nn + n0 + bn4 * 4);
    }
    float acc1[4][4], acc2[4][4];
    #pragma unroll
    for (int i = 0; i < 4; i++)
        #pragma unroll
        for (int j = 0; j < 4; j++) { acc1[i][j] = 0.f; acc2[i][j] = 0.f; }

    for (int kt = 0; kt < K; kt += 32) {
        __syncthreads();
        #pragma unroll
        for (int it = 0; it < 2; it++) {
            uint32_t* ap = &As[am + it * 32][akq * 4];
            ap[0] = f2tf(pa[it].x); ap[1] = f2tf(pa[it].y);
            ap[2] = f2tf(pa[it].z); ap[3] = f2tf(pa[it].w);
            uint32_t* b1 = &B1s[bk + it * 16][bn4 * 4];
            b1[0] = f2tf(pb1[it].x); b1[1] = f2tf(pb1[it].y);
            b1[2] = f2tf(pb1[it].z); b1[3] = f2tf(pb1[it].w);
            uint32_t* b2 = &B2s[bk + it * 16][bn4 * 4];
            b2[0] = f2tf(pb2[it].x); b2[1] = f2tf(pb2[it].y);
            b2[2] = f2tf(pb2[it].z); b2[3] = f2tf(pb2[it].w);
        }
        __syncthreads();
        if (kt + 32 < K) {
            #pragma unroll
            for (int it = 0; it < 2; it++) {
                pa[it]  = *(const float4*)(SN   + (size_t)(m0 + am + it * 32) * K + kt + 32 + akq * 4);
                pb1[it] = *(const float4*)(Wgam + (size_t)(kt + 32 + bk + it * 16) * Nn + n0 + bn4 * 4);
                pb2[it] = *(const float4*)(Wsh  + (size_t)(kt + 32 + bk + it * 16) * Nn + n0 + bn4 * 4);
            }
        }
        #pragma unroll
        for (int k8 = 0; k8 < 32; k8 += 8) {
            uint32_t a[4] = {As[wm + g][k8 + t],     As[wm + g + 8][k8 + t],
                             As[wm + g][k8 + t + 4], As[wm + g + 8][k8 + t + 4]};
            #pragma unroll
            for (int nt = 0; nt < 4; nt++) {
                uint32_t b1[2] = {B1s[k8 + t][wn + nt * 8 + g], B1s[k8 + t + 4][wn + nt * 8 + g]};
                mma_tf32(acc1[nt], a, b1);
                uint32_t b2[2] = {B2s[k8 + t][wn + nt * 8 + g], B2s[k8 + t + 4][wn + nt * 8 + g]};
                mma_tf32(acc2[nt], a, b2);
            }
        }
    }
    #pragma unroll
    for (int nt = 0; nt < 4; nt++) {
        int col = n0 + wn + nt * 8 + t * 2;
        #pragma unroll
        for (int half = 0; half < 2; half++) {
            int row = m0 + wm + g + half * 8;
            #pragma unroll
            for (int e = 0; e < 2; e++) {
                float gv = sigm(acc1[nt][half * 2 + e] + gb[col + e]);
                float a2 = gv * AN[(size_t)row * Nn + col + e] + acc2[nt][half * 2 + e];
                A2[(size_t)row * Nn + col + e] = a2;
            }
        }
    }
}

// ============================================================================
//  FUSED MID KERNEL: blockIdx.x ∈ [0,144) qkvg4 | [144,288) gate | [288,9504) pairbias
// ============================================================================

__device__ __noinline__ void qkvg4_body(uint32_t* shm, int bx, int by,
                                        const float* __restrict__ A2,
                                        const float* __restrict__ Wq, const float* __restrict__ bq,
                                        const float* __restrict__ Wk, const float* __restrict__ Wv,
                                        const float* __restrict__ Wg,
                                        float* __restrict__ oq, float* __restrict__ ok,
                                        float* __restrict__ ov, float* __restrict__ og) {
    uint32_t* As = shm;
    uint32_t* Bs = shm + 64 * 36;
    const int K = A_, Nn = A_;
    const float* Bp[4] = {Wq, Wk, Wv, Wg};
    float* Cp[4] = {oq, ok, ov, og};

    int m0 = by * 64, n0 = bx * 64;
    int tid = threadIdx.x, lane = tid & 31, warp = tid >> 5;
    int wm = (warp & 3) * 16, wn = (warp >> 2) * 32;
    int g = lane >> 2, t = lane & 3;
    int am = tid >> 3, akq = tid & 7;
    int bk = tid >> 4, bn4 = tid & 15;

    float4 pa[2], pb[4][2];
    #pragma unroll
    for (int it = 0; it < 2; it++) {
        pa[it] = *(const float4*)(A2 + (size_t)(m0 + am + it * 32) * K + akq * 4);
        #pragma unroll
        for (int z = 0; z < 4; z++)
            pb[z][it] = *(const float4*)(Bp[z] + (size_t)(bk + it * 16) * Nn + n0 + bn4 * 4);
    }
    float acc[4][4][4];
    #pragma unroll
    for (int z = 0; z < 4; z++)
        #pragma unroll
        for (int i = 0; i < 4; i++)
            #pragma unroll
            for (int j = 0; j < 4; j++) acc[z][i][j] = 0.f;

    for (int kt = 0; kt < K; kt += 32) {
        __syncthreads();
        #pragma unroll
        for (int it = 0; it < 2; it++) {
            uint32_t* ap = &As[(am + it * 32) * 36 + akq * 4];
            ap[0] = f2tf(pa[it].x); ap[1] = f2tf(pa[it].y);
            ap[2] = f2tf(pa[it].z); ap[3] = f2tf(pa[it].w);
            #pragma unroll
            for (int z = 0; z < 4; z++) {
                uint32_t* bp = &Bs[z * 32 * 72 + (bk + it * 16) * 72 + bn4 * 4];
                bp[0] = f2tf(pb[z][it].x); bp[1] = f2tf(pb[z][it].y);
                bp[2] = f2tf(pb[z][it].z); bp[3] = f2tf(pb[z][it].w);
            }
        }
        __syncthreads();
        if (kt + 32 < K) {
            #pragma unroll
            for (int it = 0; it < 2; it++) {
                pa[it] = *(const float4*)(A2 + (size_t)(m0 + am + it * 32) * K + kt + 32 + akq * 4);
                #pragma unroll
                for (int z = 0; z < 4; z++)
                    pb[z][it] = *(const float4*)(Bp[z] + (size_t)(kt + 32 + bk + it * 16) * Nn + n0 + bn4 * 4);
            }
        }
        #pragma unroll
        for (int k8 = 0; k8 < 32; k8 += 8) {
            uint32_t a[4] = {As[(wm + g) * 36 + k8 + t],     As[(wm + g + 8) * 36 + k8 + t],
                             As[(wm + g) * 36 + k8 + t + 4], As[(wm + g + 8) * 36 + k8 + t + 4]};
            #pragma unroll
            for (int z = 0; z < 4; z++) {
                #pragma unroll
                for (int nt = 0; nt < 4; nt++) {
                    uint32_t b[2] = {Bs[z * 32 * 72 + (k8 + t) * 72 + wn + nt * 8 + g],
                                     Bs[z * 32 * 72 + (k8 + t + 4) * 72 + wn + nt * 8 + g]};
                    mma_tf32(acc[z][nt], a, b);
                }
            }
        }
    }
    #pragma unroll
    for (int z = 0; z < 4; z++) {
        #pragma unroll
        for (int nt = 0; nt < 4; nt++) {
            int col = n0 + wn + nt * 8 + t * 2;
            #pragma unroll
            for (int half = 0; half < 2; half++) {
                int row = m0 + wm + g + half * 8;
                #pragma unroll
                for (int e = 0; e < 2; e++) {
                    float v = acc[z][nt][half * 2 + e];
                    if (z == 0) v += bq[col + e];
                    if (z == 3) v = sigm(v);
                    Cp[z][(size_t)row * Nn + col + e] = v;
                }
            }
        }
    }
}

__device__ __noinline__ void gate_body(uint32_t* shm, int bx, int by,
                                       const float* __restrict__ A,
                                       const float* __restrict__ B,
                                       const float* __restrict__ bias,
                                       float* __restrict__ C) {
    uint32_t* As = shm;
    uint32_t* Bs = shm + 64 * 36;
    const int K = S_, Nn = A_;
    int m0 = by * 64, n0 = bx * 64;
    int tid = threadIdx.x, lane = tid & 31, warp = tid >> 5;
    int wm = (warp & 3) * 16, wn = (warp >> 2) * 32;
    int g = lane >> 2, t = lane & 3;
    int am = tid >> 3, akq = tid & 7;
    int bk = tid >> 4, bn4 = tid & 15;

    float4 pa[2], pb[2];
    #pragma unroll
    for (int it = 0; it < 2; it++) {
        pa[it] = *(const float4*)(A + (size_t)(m0 + am + it * 32) * K + akq * 4);
        pb[it] = *(const float4*)(B + (size_t)(bk + it * 16) * Nn + n0 + bn4 * 4);
    }
    float acc[4][4];
    #pragma unroll
    for (int i = 0; i < 4; i++)
        #pragma unroll
        for (int j = 0; j < 4; j++) acc[i][j] = 0.f;

    for (int kt = 0; kt < K; kt += 32) {
        __syncthreads();
        #pragma unroll
        for (int it = 0; it < 2; it++) {
            uint32_t* ap = &As[(am + it * 32) * 36 + akq * 4];
            ap[0] = f2tf(pa[it].x); ap[1] = f2tf(pa[it].y);
            ap[2] = f2tf(pa[it].z); ap[3] = f2tf(pa[it].w);
            uint32_t* bp = &Bs[(bk + it * 16) * 72 + bn4 * 4];
            bp[0] = f2tf(pb[it].x); bp[1] = f2tf(pb[it].y);
            bp[2] = f2tf(pb[it].z); bp[3] = f2tf(pb[it].w);
        }
        __syncthreads();
        if (kt + 32 < K) {
            #pragma unroll
            for (int it = 0; it < 2; it++) {
                pa[it] = *(const float4*)(A + (size_t)(m0 + am + it * 32) * K + kt + 32 + akq * 4);
                pb[it] = *(const float4*)(B + (size_t)(kt + 32 + bk + it * 16) * Nn + n0 + bn4 * 4);
            }
        }
        #pragma unroll
        for (int k8 = 0; k8 < 32; k8 += 8) {
            uint32_t a[4] = {As[(wm + g) * 36 + k8 + t],     As[(wm + g + 8) * 36 + k8 + t],
                             As[(wm + g) * 36 + k8 + t + 4], As[(wm + g + 8) * 36 + k8 + t + 4]};
            #pragma unroll
            for (int nt = 0; nt < 4; nt++) {
                uint32_t b[2] = {Bs[(k8 + t) * 72 + wn + nt * 8 + g],
                                 Bs[(k8 + t + 4) * 72 + wn + nt * 8 + g]};
                mma_tf32(acc[nt], a, b);
            }
        }
    }
    #pragma unroll
    for (int nt = 0; nt < 4; nt++) {
        int col = n0 + wn + nt * 8 + t * 2;
        #pragma unroll
        for (int half = 0; half < 2; half++) {
            int row = m0 + wm + g + half * 8;
            float v0 = sigm(acc[nt][half * 2 + 0] + bias[col]);
            float v1 = sigm(acc[nt][half * 2 + 1] + bias[col + 1]);
            C[(size_t)row * Nn + col]     = v0;
            C[(size_t)row * Nn + col + 1] = v1;
        }
    }
}

__device__ __noinline__ void pairbias_body(uint32_t* shm, int pbid,
                                           const float* __restrict__ pair,
                                           const float* __restrict__ beta,
                                           const float* __restrict__ w,
                                           const float* __restrict__ b,
                                           const float* __restrict__ Wb,
                                           float* __restrict__ bias) {
    uint32_t* As = shm;
    uint32_t* Bs = shm + 64 * 140;

    int tid = threadIdx.x, lane = tid & 31, warp = tid >> 5;
    int r  = tid >> 2;
    int pq = tid & 3;
    int p0 = pbid * 64;

    for (int i = tid; i < P_ * H_; i += 256) {
        int kk = i >> 4, nn = i & 15;
        Bs[kk * 24 + nn] = f2tf(__ldg(Wb + i));
    }

    const float* row = pair + (size_t)(p0 + r) * P_;
    float4 u[4][2];
    float s = 0.f, s2 = 0.f;
    #pragma unroll
    for (int j = 0; j < 4; j++) {
        u[j][0] = *(const float4*)(row + 8 * pq + 32 * j);
        u[j][1] = *(const float4*)(row + 8 * pq + 32 * j + 4);
        #pragma unroll
        for (int h2 = 0; h2 < 2; h2++) {
            const float4 f = u[j][h2];
            s  += f.x + f.y + f.z + f.w;
            s2 += f.x * f.x + f.y * f.y + f.z * f.z + f.w * f.w;
        }
    }
    s  += __shfl_xor_sync(0xffffffffu, s, 1);  s  += __shfl_xor_sync(0xffffffffu, s, 2);
    s2 += __shfl_xor_sync(0xffffffffu, s2, 1); s2 += __shfl_xor_sync(0xffffffffu, s2, 2);
    float mean = s * (1.f / P_);
    float var  = s2 * (1.f / P_) - mean * mean;
    float rs   = rsqrtf(var + 1e-5f);

    #pragma unroll
    for (int j = 0; j < 4; j++) {
        int c0 = 8 * pq + 32 * j;
        #pragma unroll
        for (int h2 = 0; h2 < 2; h2++) {
            const float4 wv = *(const float4*)(w + c0 + 4 * h2);
            const float4 bv = *(const float4*)(b + c0 + 4 * h2);
            const float4 f  = u[j][h2];
            uint4 pkt;
            pkt.x = f2tf((f.x - mean) * rs * wv.x + bv.x);
            pkt.y = f2tf((f.y - mean) * rs * wv.y + bv.y);
            pkt.z = f2tf((f.z - mean) * rs * wv.z + bv.z);
            pkt.w = f2tf((f.w - mean) * rs * wv.w + bv.w);
            *(uint4*)&As[r * 140 + c0 + 4 * h2] = pkt;
        }
    }
    __syncthreads();

    int g = lane >> 2, t = lane & 3;
    int wm = (warp & 3) * 16;
    int hh = (warp >> 2) * 8;
    float acc[4] = {0.f, 0.f, 0.f, 0.f};
    #pragma unroll
    for (int k8 = 0; k8 < 16; k8++) {
        int k = k8 * 8;
        uint32_t a[4] = {As[(wm + g) * 140 + k + t],     As[(wm + g + 8) * 140 + k + t],
                         As[(wm + g) * 140 + k + t + 4], As[(wm + g + 8) * 140 + k + t + 4]};
        uint32_t bb[2] = {Bs[(k + t) * 24 + hh + g], Bs[(k + t + 4) * 24 + hh + g]};
        mma_tf32(acc, a, bb);
    }

    int pr0 = p0 + wm + g, pr1 = pr0 + 8;
    float be0 = __ldg(beta + pr0), be1 = __ldg(beta + pr1);
    int h0 = hh + 2 * t;
    bias[(size_t)(h0)     * NN + pr0] = acc[0] + be0;
    bias[(size_t)(h0 + 1) * NN + pr0] = acc[1] + be0;
    bias[(size_t)(h0)     * NN + pr1] = acc[2] + be1;
    bias[(size_t)(h0 + 1) * NN + pr1] = acc[3] + be1;
}

#define FUSED_SMEM ((64*140 + 128*24)*4)

__global__ __launch_bounds__(256) void fused_mid(
    const float* __restrict__ A2,
    const float* __restrict__ Wq, const float* __restrict__ bq,
    const float* __restrict__ Wk, const float* __restrict__ Wv,
    const float* __restrict__ Wg,
    float* __restrict__ oq, float* __restrict__ ok,
    float* __restrict__ ov, float* __restrict__ og,
    const float* __restrict__ sIn, const float* __restrict__ Wout,
    const float* __restrict__ bout, float* __restrict__ gate,
    const float* __restrict__ pair, const float* __restrict__ beta,
    const float* __restrict__ lnpw, const float* __restrict__ lnpb,
    const float* __restrict__ Wb, float* __restrict__ bias) {
    extern __shared__ __align__(16) uint32_t shm[];
    int bx = blockIdx.x;
    if (bx < 144) {
        qkvg4_body(shm, bx % 12, bx / 12, A2, Wq, bq, Wk, Wv, Wg, oq, ok, ov, og);
    } else if (bx < 288) {
        int i = bx - 144;
        gate_body(shm, i % 12, i / 12, sIn, Wout, bout, gate);
    } else {
        pairbias_body(shm, bx - 288, pair, beta, lnpw, lnpb, Wb, bias);
    }
}

// ---------------- flash attention, split-KV x2, 64 q-rows / 4 warps ----------------
// Q,K stride 52 (bank 20g+t), V stride 56 (bank 24t+g), P stride 68 (bank 4g+t)
#define AQ(r,c) smQ[(r)*52+(c)]
#define AK(r,c) smK[(r)*52+(c)]
#define AV(r,c) smV[(r)*56+(c)]
#define AP(r,c) smP[(r)*68+(c)]
#define ATTN_SMEM (64*(52+52+56+68)*4)

__global__ __launch_bounds__(128) void attn_tf32(const float* __restrict__ q,
                                                 const float* __restrict__ k,
                                                 const float* __restrict__ v,
                                                 const float* __restrict__ bias,
                                                 float* __restrict__ opart,
                                                 float2* __restrict__ mlv) {
    extern __shared__ uint32_t sm[];
    uint32_t* smQ = sm;
    uint32_t* smK = smQ + 64 * 52;
    uint32_t* smV = smK + 64 * 52;
    uint32_t* smP = smV + 64 * 56;

    int h  = blockIdx.y;
    int q0 = blockIdx.x * 64;
    int sidx = blockIdx.z;
    int s0 = sidx * (N_ / 2);
    int tid = threadIdx.x, lane = tid & 31, warp = tid >> 5;
    int g = lane >> 2, t = lane & 3;
    int wm = warp * 16;

    // load Q tile (64 x 48) as tf32
    #pragma unroll
    for (int it = 0; it < 6; it++) {
        int idx = tid + it * 128;
        int r = idx / 12, c4 = idx % 12;
        float4 v4 = *(const float4*)(q + (size_t)(q0 + r) * A_ + h * D_ + c4 * 4);
        AQ(r, c4 * 4 + 0) = f2tf(v4.x); AQ(r, c4 * 4 + 1) = f2tf(v4.y);
        AQ(r, c4 * 4 + 2) = f2tf(v4.z); AQ(r, c4 * 4 + 3) = f2tf(v4.w);
    }

    float m0 = -1e30f, m1 = -1e30f, l0 = 0.f, l1 = 0.f;
    float oacc[6][4];
    #pragma unroll
    for (int dt = 0; dt < 6; dt++)
        #pragma unroll
        for (int e = 0; e < 4; e++) oacc[dt][e] = 0.f;

    const float scale = 0.144337567f;   // 1/sqrt(48)

    for (int j0 = s0; j0 < s0 + N_ / 2; j0 += 64) {
        __syncthreads();

        // prefetch bias into registers early (overlaps with K/V load + QK mma)
        const float* bp0 = bias + (size_t)h * NN + (size_t)(q0 + wm + g) * N_ + j0;
        const float* bp1 = bp0 + 8 * N_;
        float2 bpre0[8], bpre1[8];
        #pragma unroll
        for (int nt = 0; nt < 8; nt++) {
            bpre0[nt] = *(const float2*)(bp0 + nt * 8 + 2 * t);
            bpre1[nt] = *(const float2*)(bp1 + nt * 8 + 2 * t);
        }

        #pragma unroll
        for (int it = 0; it < 6; it++) {
            int idx = tid + it * 128;
            int r = idx / 12, c4 = idx % 12;
            float4 kv = *(const float4*)(k + (size_t)(j0 + r) * A_ + h * D_ + c4 * 4);
            AK(r, c4 * 4 + 0) = f2tf(kv.x); AK(r, c4 * 4 + 1) = f2tf(kv.y);
            AK(r, c4 * 4 + 2) = f2tf(kv.z); AK(r, c4 * 4 + 3) = f2tf(kv.w);
            float4 vv = *(const float4*)(v + (size_t)(j0 + r) * A_ + h * D_ + c4 * 4);
            AV(r, c4 * 4 + 0) = f2tf(vv.x); AV(r, c4 * 4 + 1) = f2tf(vv.y);
            AV(r, c4 * 4 + 2) = f2tf(vv.z); AV(r, c4 * 4 + 3) = f2tf(vv.w);
        }
        __syncthreads();

        float sacc[8][4];
        #pragma unroll
        for (int nt = 0; nt < 8; nt++)
            #pragma unroll
            for (int e = 0; e < 4; e++) sacc[nt][e] = 0.f;

        #pragma unroll
        for (int k8 = 0; k8 < 48; k8 += 8) {
            uint32_t a[4] = {AQ(wm + g, k8 + t),     AQ(wm + g + 8, k8 + t),
                             AQ(wm + g, k8 + t + 4), AQ(wm + g + 8, k8 + t + 4)};
            #pragma unroll
            for (int nt = 0; nt < 8; nt++) {
                uint32_t b[2] = {AK(nt * 8 + g, k8 + t), AK(nt * 8 + g, k8 + t + 4)};
                mma_tf32(sacc[nt], a, b);
            }
        }

        #pragma unroll
        for (int nt = 0; nt < 8; nt++) {
            sacc[nt][0] = sacc[nt][0] * scale + bpre0[nt].x;
            sacc[nt][1] = sacc[nt][1] * scale + bpre0[nt].y;
            sacc[nt][2] = sacc[nt][2] * scale + bpre1[nt].x;
            sacc[nt][3] = sacc[nt][3] * scale + bpre1[nt].y;
        }

        float mx0 = -1e30f, mx1 = -1e30f;
        #pragma unroll
        for (int nt = 0; nt < 8; nt++) {
            mx0 = fmaxf(mx0, fmaxf(sacc[nt][0], sacc[nt][1]));
            mx1 = fmaxf(mx1, fmaxf(sacc[nt][2], sacc[nt][3]));
        }
        mx0 = fmaxf(mx0, __shfl_xor_sync(0xffffffffu, mx0, 1));
        mx0 = fmaxf(mx0, __shfl_xor_sync(0xffffffffu, mx0, 2));
        mx1 = fmaxf(mx1, __shfl_xor_sync(0xffffffffu, mx1, 1));
        mx1 = fmaxf(mx1, __shfl_xor_sync(0xffffffffu, mx1, 2));
        float mn0 = fmaxf(m0, mx0), mn1 = fmaxf(m1, mx1);
        float cr0 = __expf(m0 - mn0), cr1 = __expf(m1 - mn1);
        m0 = mn0; m1 = mn1;

        float s0r = 0.f, s1r = 0.f;
        #pragma unroll
        for (int nt = 0; nt < 8; nt++) {
            float p00 = __expf(sacc[nt][0] - mn0);
            float p01 = __expf(sacc[nt][1] - mn0);
            float p10 = __expf(sacc[nt][2] - mn1);
            float p11 = __expf(sacc[nt][3] - mn1);
            s0r += p00 + p01; s1r += p10 + p11;
            int c = nt * 8 + 2 * t;
            AP(wm + g, c)         = f2tf(p00);
            AP(wm + g, c + 1)     = f2tf(p01);
            AP(wm + g + 8, c)     = f2tf(p10);
            AP(wm + g + 8, c + 1) = f2tf(p11);
        }
        s0r += __shfl_xor_sync(0xffffffffu, s0r, 1);
        s0r += __shfl_xor_sync(0xffffffffu, s0r, 2);
        s1r += __shfl_xor_sync(0xffffffffu, s1r, 1);
        s1r += __shfl_xor_sync(0xffffffffu, s1r, 2);
        l0 = l0 * cr0 + s0r;
        l1 = l1 * cr1 + s1r;

        #pragma unroll
        for (int dt = 0; dt < 6; dt++) {
            oacc[dt][0] *= cr0; oacc[dt][1] *= cr0;
            oacc[dt][2] *= cr1; oacc[dt][3] *= cr1;
        }
        __syncwarp();

        #pragma unroll
        for (int k8 = 0; k8 < 64; k8 += 8) {
            uint32_t a[4] = {AP(wm + g, k8 + t),     AP(wm + g + 8, k8 + t),
                             AP(wm + g, k8 + t + 4), AP(wm + g + 8, k8 + t + 4)};
            #pragma unroll
            for (int dt = 0; dt < 6; dt++) {
                uint32_t b[2] = {AV(k8 + t, dt * 8 + g), AV(k8 + t + 4, dt * 8 + g)};
                mma_tf32(oacc[dt], a, b);
            }
        }
    }

    // epilogue: store unnormalized partials + (m, l)
    float* op = opart + (size_t)sidx * N_ * A_;
    int r0 = q0 + wm + g, r1 = r0 + 8;
    #pragma unroll
    for (int dt = 0; dt < 6; dt++) {
        int d = dt * 8 + 2 * t;
        size_t i00 = (size_t)r0 * A_ + h * D_ + d;
        size_t i10 = (size_t)r1 * A_ + h * D_ + d;
        op[i00]     = oacc[dt][0];
        op[i00 + 1] = oacc[dt][1];
        op[i10]     = oacc[dt][2];
        op[i10 + 1] = oacc[dt][3];
    }
    if (t == 0) {
        mlv[(size_t)sidx * H_ * N_ + h * N_ + r0] = make_float2(m0, l0);
        mlv[(size_t)sidx * H_ * N_ + h * N_ + r1] = make_float2(m1, l1);
    }
}

// ---------------- merge split-KV partials + gate ----------------
__global__ __launch_bounds__(256) void attn_merge(const float* __restrict__ op,
                                                  const float2* __restrict__ ml,
                                                  const float* __restrict__ gt,
                                                  float* __restrict__ o) {
    int idx = blockIdx.x * 256 + threadIdx.x;      // 147456 float4s
    int n  = idx / 192;
    int c4 = idx - n * 192;
    int h  = c4 / 12;
    float2 ml1 = ml[h * N_ + n];
    float2 ml2 = ml[H_ * N_ + h * N_ + n];
    float m  = fmaxf(ml1.x, ml2.x);
    float w1 = __expf(ml1.x - m), w2 = __expf(ml2.x - m);
    float inv = 1.f / (w1 * ml1.y + w2 * ml2.y);
    size_t off = (size_t)n * A_ + c4 * 4;
    const float4 a1 = *(const float4*)(op + off);
    const float4 a2 = *(const float4*)(op + (size_t)N_ * A_ + off);
    const float4 g4 = *(const float4*)(gt + off);
    float4 r;
    r.x = (w1 * a1.x + w2 * a2.x) * inv * g4.x;
    r.y = (w1 * a1.y + w2 * a2.y) * inv * g4.y;
    r.z = (w1 * a1.z + w2 * a2.z) * inv * g4.z;
    r.w = (w1 * a1.w + w2 * a2.w) * inv * g4.w;
    *(float4*)(o + off) = r;
}

// ---------------- launch ----------------
extern "C" void kernel_launch(void* const* d_in, const int* in_sizes, int n_in,
                              void* d_out, int out_size) {
    const float* a       = (const float*)d_in[0];
    const float* s       = (const float*)d_in[1];
    const float* pair    = (const float*)d_in[2];
    const float* beta    = (const float*)d_in[3];
    const float* ln_s_w  = (const float*)d_in[4];
    const float* gamma_w = (const float*)d_in[5];
    const float* gamma_b = (const float*)d_in[6];
    const float* shift_w = (const float*)d_in[7];
    const float* Wq      = (const float*)d_in[8];
    const float* bq      = (const float*)d_in[9];
    const float* Wk      = (const float*)d_in[10];
    const float* Wv      = (const float*)d_in[11];
    const float* ln_p_w  = (const float*)d_in[12];
    const float* ln_p_b  = (const float*)d_in[13];
    const float* Wb      = (const float*)d_in[14];
    const float* Wg      = (const float*)d_in[15];
    const float* Wp      = (const float*)d_in[16];
    const float* Wout    = (const float*)d_in[17];
    const float* bout    = (const float*)d_in[18];
    float* out = (float*)d_out;

    float *p_sn, *p_an, *p_a2, *p_q, *p_k, *p_v, *p_gt, *p_bias, *p_o, *p_gate, *p_opart;
    float2 *p_ml;
    cudaGetSymbolAddress((void**)&p_sn,    d_sn);
    cudaGetSymbolAddress((void**)&p_an,    d_an);
    cudaGetSymbolAddress((void**)&p_a2,    d_a2);
    cudaGetSymbolAddress((void**)&p_q,     d_q);
    cudaGetSymbolAddress((void**)&p_k,     d_k);
    cudaGetSymbolAddress((void**)&p_v,     d_v);
    cudaGetSymbolAddress((void**)&p_gt,    d_gt);
    cudaGetSymbolAddress((void**)&p_bias,  d_bias);
    cudaGetSymbolAddress((void**)&p_o,     d_o);
    cudaGetSymbolAddress((void**)&p_gate,  d_gate);
    cudaGetSymbolAddress((void**)&p_opart, d_opart);
    cudaGetSymbolAddress((void**)&p_ml,    d_ml);

    cudaFuncSetAttribute(attn_tf32,  cudaFuncAttributeMaxDynamicSharedMemorySize, ATTN_SMEM);
    cudaFuncSetAttribute(fused_mid,  cudaFuncAttributeMaxDynamicSharedMemorySize, FUSED_SMEM);

    dim3 g2(A_ / 64, N_ / 64);

    ln2_kernel<<<dim3(N_, 2), 256>>>(s, ln_s_w, p_sn, a, p_an);
    adaln_tf32<<<g2, 256>>>(p_sn, gamma_w, gamma_b, shift_w, p_an, p_a2);
    fused_mid<<<288 + NN / 64, 256, FUSED_SMEM>>>(
        p_a2, Wq, bq, Wk, Wv, Wg, p_q, p_k, p_v, p_gt,
        s, Wout, bout, p_gate,
        pair, beta, ln_p_w, ln_p_b, Wb, p_bias);
    dim3 ga(N_ / 64, H_, 2);
    attn_tf32<<<ga, 128, ATTN_SMEM>>>(p_q, p_k, p_v, p_bias, p_opart, p_ml);
    attn_merge<<<576, 256>>>(p_opart, p_ml, p_gt, p_o);
    gemm_tf32<4><<<g2, 256>>>(p_o, Wp, out, A_, A_, nullptr, p_gate);
}

// round 9
// speedup vs baseline: 7.9587x; 1.0573x over previous
#include <cuda_runtime.h>
#include <math.h>
#include <stdint.h>

#define N_  768
#define A_  768
#define S_  384
#define P_  128
#define H_  16
#define D_  48
#define NN  (N_*N_)

// ---------------- scratch (no allocations allowed) ----------------
__device__ float d_sn [N_*S_];
__device__ float d_an [N_*A_];
__device__ float d_a2 [N_*A_];
__device__ float d_q  [N_*A_];
__device__ float d_k  [N_*A_];
__device__ float d_v  [N_*A_];
__device__ float d_gt [N_*A_];
__device__ float d_bias[H_*NN];         // [H][N][N]
__device__ float d_o  [N_*A_];
__device__ float d_gate[N_*A_];
__device__ float d_opart[2*N_*A_];      // split-KV unnormalized partials
__device__ float2 d_ml[2*H_*N_];        // (m, l) per split/head/row

// ---------------- helpers ----------------
__device__ __forceinline__ uint32_t f2tf(float f) {
    uint32_t u;
    asm("cvt.rna.tf32.f32 %0, %1;" : "=r"(u) : "f"(f));
    return u;
}
__device__ __forceinline__ void mma_tf32(float* c, const uint32_t* a, const uint32_t* b) {
    asm volatile("mma.sync.aligned.m16n8k8.row.col.f32.tf32.tf32.f32 "
                 "{%0,%1,%2,%3}, {%4,%5,%6,%7}, {%8,%9}, {%0,%1,%2,%3};"
                 : "+f"(c[0]), "+f"(c[1]), "+f"(c[2]), "+f"(c[3])
                 : "r"(a[0]), "r"(a[1]), "r"(a[2]), "r"(a[3]), "r"(b[0]), "r"(b[1]));
}
__device__ __forceinline__ float sigm(float x) { return 1.f / (1.f + __expf(-x)); }

// ---------------- merged row LayerNorm (s and a in one launch) ----------------
__global__ __launch_bounds__(256) void ln2_kernel(const float* __restrict__ sx,
                                                  const float* __restrict__ lnw,
                                                  float* __restrict__ sny,
                                                  const float* __restrict__ ax,
                                                  float* __restrict__ any) {
    const float* x; const float* w; float* y; int COLS;
    if (blockIdx.y == 0) { x = sx; w = lnw;     y = sny; COLS = S_; }
    else                 { x = ax; w = nullptr; y = any; COLS = A_; }
    int row = blockIdx.x;
    const float* xr = x + (size_t)row * COLS;
    float s = 0.f, s2 = 0.f;
    for (int c = threadIdx.x; c < COLS; c += blockDim.x) {
        float v = xr[c]; s += v; s2 += v * v;
    }
    __shared__ float red[64];
    #pragma unroll
    for (int o = 16; o; o >>= 1) {
        s  += __shfl_xor_sync(0xffffffffu, s,  o);
        s2 += __shfl_xor_sync(0xffffffffu, s2, o);
    }
    int wid = threadIdx.x >> 5, lid = threadIdx.x & 31;
    if (lid == 0) { red[wid] = s; red[wid + 32] = s2; }
    __syncthreads();
    if (wid == 0) {
        s  = (lid < 8) ? red[lid]      : 0.f;
        s2 = (lid < 8) ? red[lid + 32] : 0.f;
        #pragma unroll
        for (int o = 4; o; o >>= 1) {
            s  += __shfl_xor_sync(0xffffffffu, s,  o);
            s2 += __shfl_xor_sync(0xffffffffu, s2, o);
        }
        if (lid == 0) { red[0] = s; red[1] = s2; }
    }
    __syncthreads();
    float mean = red[0] / COLS;
    float var  = red[1] / COLS - mean * mean;
    float rs   = rsqrtf(var + 1e-5f);
    float* yr = y + (size_t)row * COLS;
    for (int c = threadIdx.x; c < COLS; c += blockDim.x) {
        float v = (xr[c] - mean) * rs;
        if (w) v *= w[c];
        yr[c] = v;
    }
}

// ---------------- generic tf32 GEMM (standalone, for out-proj) ----------------
template<int EPI>
__global__ __launch_bounds__(256) void gemm_tf32(const float* __restrict__ A,
                                                 const float* __restrict__ B,
                                                 float* __restrict__ C,
                                                 int K, int Nn,
                                                 const float* __restrict__ bias,
                                                 const float* __restrict__ C2) {
    __shared__ __align__(16) uint32_t As[64][36];
    __shared__ __align__(16) uint32_t Bs[32][72];
    int m0 = blockIdx.y * 64, n0 = blockIdx.x * 64;
    int tid = threadIdx.x, lane = tid & 31, warp = tid >> 5;
    int wm = (warp & 3) * 16, wn = (warp >> 2) * 32;
    int g = lane >> 2, t = lane & 3;

    int am = tid >> 3, akq = tid & 7;
    int bk = tid >> 4, bn4 = tid & 15;

    float4 pa[2], pb[2];
    #pragma unroll
    for (int it = 0; it < 2; it++) {
        pa[it] = *(const float4*)(A + (size_t)(m0 + am + it * 32) * K + akq * 4);
        pb[it] = *(const float4*)(B + (size_t)(bk + it * 16) * Nn + n0 + bn4 * 4);
    }
    float acc[4][4];
    #pragma unroll
    for (int i = 0; i < 4; i++)
        #pragma unroll
        for (int j = 0; j < 4; j++) acc[i][j] = 0.f;

    for (int kt = 0; kt < K; kt += 32) {
        __syncthreads();
        #pragma unroll
        for (int it = 0; it < 2; it++) {
            uint32_t* ap = &As[am + it * 32][akq * 4];
            ap[0] = f2tf(pa[it].x); ap[1] = f2tf(pa[it].y);
            ap[2] = f2tf(pa[it].z); ap[3] = f2tf(pa[it].w);
            uint32_t* bp = &Bs[bk + it * 16][bn4 * 4];
            bp[0] = f2tf(pb[it].x); bp[1] = f2tf(pb[it].y);
            bp[2] = f2tf(pb[it].z); bp[3] = f2tf(pb[it].w);
        }
        __syncthreads();
        if (kt + 32 < K) {
            #pragma unroll
            for (int it = 0; it < 2; it++) {
                pa[it] = *(const float4*)(A + (size_t)(m0 + am + it * 32) * K + kt + 32 + akq * 4);
                pb[it] = *(const float4*)(B + (size_t)(kt + 32 + bk + it * 16) * Nn + n0 + bn4 * 4);
            }
        }
        #pragma unroll
        for (int k8 = 0; k8 < 32; k8 += 8) {
            uint32_t a[4] = {As[wm + g][k8 + t],     As[wm + g + 8][k8 + t],
                             As[wm + g][k8 + t + 4], As[wm + g + 8][k8 + t + 4]};
            #pragma unroll
            for (int nt = 0; nt < 4; nt++) {
                uint32_t b[2] = {Bs[k8 + t][wn + nt * 8 + g], Bs[k8 + t + 4][wn + nt * 8 + g]};
                mma_tf32(acc[nt], a, b);
            }
        }
    }
    #pragma unroll
    for (int nt = 0; nt < 4; nt++) {
        int col = n0 + wn + nt * 8 + t * 2;
        #pragma unroll
        for (int half = 0; half < 2; half++) {
            int row = m0 + wm + g + half * 8;
            float v0 = acc[nt][half * 2 + 0], v1 = acc[nt][half * 2 + 1];
            if (EPI == 4) { v0 *= C2[(size_t)row * Nn + col]; v1 *= C2[(size_t)row * Nn + col + 1]; }
            C[(size_t)row * Nn + col]     = v0;
            C[(size_t)row * Nn + col + 1] = v1;
        }
    }
}

// ---------------- fused AdaLN ----------------
__global__ __launch_bounds__(256) void adaln_tf32(const float* __restrict__ SN,
                                                  const float* __restrict__ Wgam,
                                                  const float* __restrict__ gb,
                                                  const float* __restrict__ Wsh,
                                                  const float* __restrict__ AN,
                                                  float* __restrict__ A2) {
    __shared__ __align__(16) uint32_t As[64][36];
    __shared__ __align__(16) uint32_t B1s[32][72];
    __shared__ __align__(16) uint32_t B2s[32][72];
    const int K = S_, Nn = A_;
    int m0 = blockIdx.y * 64, n0 = blockIdx.x * 64;
    int tid = threadIdx.x, lane = tid & 31, warp = tid >> 5;
    int wm = (warp & 3) * 16, wn = (warp >> 2) * 32;
    int g = lane >> 2, t = lane & 3;

    int am = tid >> 3, akq = tid & 7;
    int bk = tid >> 4, bn4 = tid & 15;

    float4 pa[2], pb1[2], pb2[2];
    #pragma unroll
    for (int it = 0; it < 2; it++) {
        pa[it]  = *(const float4*)(SN   + (size_t)(m0 + am + it * 32) * K + akq * 4);
        pb1[it] = *(const float4*)(Wgam + (size_t)(bk + it * 16) * Nn + n0 + bn4 * 4);
        pb2[it] = *(const float4*)(Wsh  + (size_t)(bk + it * 16) * Nn + n0 + bn4 * 4);
    }
    float acc1[4][4], acc2[4][4];
    #pragma unroll
    for (int i = 0; i < 4; i++)
        #pragma unroll
        for (int j = 0; j < 4; j++) { acc1[i][j] = 0.f; acc2[i][j] = 0.f; }

    for (int kt = 0; kt < K; kt += 32) {
        __syncthreads();
        #pragma unroll
        for (int it = 0; it < 2; it++) {
            uint32_t* ap = &As[am + it * 32][akq * 4];
            ap[0] = f2tf(pa[it].x); ap[1] = f2tf(pa[it].y);
            ap[2] = f2tf(pa[it].z); ap[3] = f2tf(pa[it].w);
            uint32_t* b1 = &B1s[bk + it * 16][bn4 * 4];
            b1[0] = f2tf(pb1[it].x); b1[1] = f2tf(pb1[it].y);
            b1[2] = f2tf(pb1[it].z); b1[3] = f2tf(pb1[it].w);
            uint32_t* b2 = &B2s[bk + it * 16][bn4 * 4];
            b2[0] = f2tf(pb2[it].x); b2[1] = f2tf(pb2[it].y);
            b2[2] = f2tf(pb2[it].z); b2[3] = f2tf(pb2[it].w);
        }
        __syncthreads();
        if (kt + 32 < K) {
            #pragma unroll
            for (int it = 0; it < 2; it++) {
                pa[it]  = *(const float4*)(SN   + (size_t)(m0 + am + it * 32) * K + kt + 32 + akq * 4);
                pb1[it] = *(const float4*)(Wgam + (size_t)(kt + 32 + bk + it * 16) * Nn + n0 + bn4 * 4);
                pb2[it] = *(const float4*)(Wsh  + (size_t)(kt + 32 + bk + it * 16) * Nn + n0 + bn4 * 4);
            }
        }
        #pragma unroll
        for (int k8 = 0; k8 < 32; k8 += 8) {
            uint32_t a[4] = {As[wm + g][k8 + t],     As[wm + g + 8][k8 + t],
                             As[wm + g][k8 + t + 4], As[wm + g + 8][k8 + t + 4]};
            #pragma unroll
            for (int nt = 0; nt < 4; nt++) {
                uint32_t b1[2] = {B1s[k8 + t][wn + nt * 8 + g], B1s[k8 + t + 4][wn + nt * 8 + g]};
                mma_tf32(acc1[nt], a, b1);
                uint32_t b2[2] = {B2s[k8 + t][wn + nt * 8 + g], B2s[k8 + t + 4][wn + nt * 8 + g]};
                mma_tf32(acc2[nt], a, b2);
            }
        }
    }
    #pragma unroll
    for (int nt = 0; nt < 4; nt++) {
        int col = n0 + wn + nt * 8 + t * 2;
        #pragma unroll
        for (int half = 0; half < 2; half++) {
            int row = m0 + wm + g + half * 8;
            #pragma unroll
            for (int e = 0; e < 2; e++) {
                float gv = sigm(acc1[nt][half * 2 + e] + gb[col + e]);
                float a2 = gv * AN[(size_t)row * Nn + col + e] + acc2[nt][half * 2 + e];
                A2[(size_t)row * Nn + col + e] = a2;
            }
        }
    }
}

// ============================================================================
//  FUSED MID KERNEL
//  blockIdx.x: [0,144) qkvg2{Wq,Wk} | [144,288) qkvg2{Wv,Wg} | [288,432) gate
//              | [432,1024) persistent pairbias (592 blocks, grid-stride)
// ============================================================================

// --- qkvg2: A staged once, 2 B matrices ---
__device__ __noinline__ void qkvg2_body(uint32_t* shm, int bx, int by, int zp,
                                        const float* __restrict__ A2,
                                        const float* __restrict__ bq,
                                        const float* __restrict__ B0,
                                        const float* __restrict__ B1,
                                        float* __restrict__ C0,
                                        float* __restrict__ C1) {
    uint32_t* As  = shm;                // [64][36]
    uint32_t* Bs0 = shm + 64 * 36;      // [32][72]
    uint32_t* Bs1 = Bs0 + 32 * 72;      // [32][72]
    const int K = A_, Nn = A_;

    int m0 = by * 64, n0 = bx * 64;
    int tid = threadIdx.x, lane = tid & 31, warp = tid >> 5;
    int wm = (warp & 3) * 16, wn = (warp >> 2) * 32;
    int g = lane >> 2, t = lane & 3;
    int am = tid >> 3, akq = tid & 7;
    int bk = tid >> 4, bn4 = tid & 15;

    float4 pa[2], pb0[2], pb1[2];
    #pragma unroll
    for (int it = 0; it < 2; it++) {
        pa[it]  = *(const float4*)(A2 + (size_t)(m0 + am + it * 32) * K + akq * 4);
        pb0[it] = *(const float4*)(B0 + (size_t)(bk + it * 16) * Nn + n0 + bn4 * 4);
        pb1[it] = *(const float4*)(B1 + (size_t)(bk + it * 16) * Nn + n0 + bn4 * 4);
    }
    float acc0[4][4], acc1[4][4];
    #pragma unroll
    for (int i = 0; i < 4; i++)
        #pragma unroll
        for (int j = 0; j < 4; j++) { acc0[i][j] = 0.f; acc1[i][j] = 0.f; }

    for (int kt = 0; kt < K; kt += 32) {
        __syncthreads();
        #pragma unroll
        for (int it = 0; it < 2; it++) {
            uint32_t* ap = &As[(am + it * 32) * 36 + akq * 4];
            ap[0] = f2tf(pa[it].x); ap[1] = f2tf(pa[it].y);
            ap[2] = f2tf(pa[it].z); ap[3] = f2tf(pa[it].w);
            uint32_t* b0 = &Bs0[(bk + it * 16) * 72 + bn4 * 4];
            b0[0] = f2tf(pb0[it].x); b0[1] = f2tf(pb0[it].y);
            b0[2] = f2tf(pb0[it].z); b0[3] = f2tf(pb0[it].w);
            uint32_t* b1 = &Bs1[(bk + it * 16) * 72 + bn4 * 4];
            b1[0] = f2tf(pb1[it].x); b1[1] = f2tf(pb1[it].y);
            b1[2] = f2tf(pb1[it].z); b1[3] = f2tf(pb1[it].w);
        }
        __syncthreads();
        if (kt + 32 < K) {
            #pragma unroll
            for (int it = 0; it < 2; it++) {
                pa[it]  = *(const float4*)(A2 + (size_t)(m0 + am + it * 32) * K + kt + 32 + akq * 4);
                pb0[it] = *(const float4*)(B0 + (size_t)(kt + 32 + bk + it * 16) * Nn + n0 + bn4 * 4);
                pb1[it] = *(const float4*)(B1 + (size_t)(kt + 32 + bk + it * 16) * Nn + n0 + bn4 * 4);
            }
        }
        #pragma unroll
        for (int k8 = 0; k8 < 32; k8 += 8) {
            uint32_t a[4] = {As[(wm + g) * 36 + k8 + t],     As[(wm + g + 8) * 36 + k8 + t],
                             As[(wm + g) * 36 + k8 + t + 4], As[(wm + g + 8) * 36 + k8 + t + 4]};
            #pragma unroll
            for (int nt = 0; nt < 4; nt++) {
                uint32_t b0[2] = {Bs0[(k8 + t) * 72 + wn + nt * 8 + g],
                                  Bs0[(k8 + t + 4) * 72 + wn + nt * 8 + g]};
                mma_tf32(acc0[nt], a, b0);
                uint32_t b1[2] = {Bs1[(k8 + t) * 72 + wn + nt * 8 + g],
                                  Bs1[(k8 + t + 4) * 72 + wn + nt * 8 + g]};
                mma_tf32(acc1[nt], a, b1);
            }
        }
    }
    #pragma unroll
    for (int nt = 0; nt < 4; nt++) {
        int col = n0 + wn + nt * 8 + t * 2;
        #pragma unroll
        for (int half = 0; half < 2; half++) {
            int row = m0 + wm + g + half * 8;
            #pragma unroll
            for (int e = 0; e < 2; e++) {
                float v0 = acc0[nt][half * 2 + e];
                float v1 = acc1[nt][half * 2 + e];
                if (zp == 0) v0 += bq[col + e];     // q gets bias
                if (zp == 1) v1 = sigm(v1);         // g gets sigmoid
                C0[(size_t)row * Nn + col + e] = v0;
                C1[(size_t)row * Nn + col + e] = v1;
            }
        }
    }
}

// --- gate GEMM sigmoid(s @ Wout + bout) ---
__device__ __noinline__ void gate_body(uint32_t* shm, int bx, int by,
                                       const float* __restrict__ A,
                                       const float* __restrict__ B,
                                       const float* __restrict__ bias,
                                       float* __restrict__ C) {
    uint32_t* As = shm;
    uint32_t* Bs = shm + 64 * 36;
    const int K = S_, Nn = A_;
    int m0 = by * 64, n0 = bx * 64;
    int tid = threadIdx.x, lane = tid & 31, warp = tid >> 5;
    int wm = (warp & 3) * 16, wn = (warp >> 2) * 32;
    int g = lane >> 2, t = lane & 3;
    int am = tid >> 3, akq = tid & 7;
    int bk = tid >> 4, bn4 = tid & 15;

    float4 pa[2], pb[2];
    #pragma unroll
    for (int it = 0; it < 2; it++) {
        pa[it] = *(const float4*)(A + (size_t)(m0 + am + it * 32) * K + akq * 4);
        pb[it] = *(const float4*)(B + (size_t)(bk + it * 16) * Nn + n0 + bn4 * 4);
    }
    float acc[4][4];
    #pragma unroll
    for (int i = 0; i < 4; i++)
        #pragma unroll
        for (int j = 0; j < 4; j++) acc[i][j] = 0.f;

    for (int kt = 0; kt < K; kt += 32) {
        __syncthreads();
        #pragma unroll
        for (int it = 0; it < 2; it++) {
            uint32_t* ap = &As[(am + it * 32) * 36 + akq * 4];
            ap[0] = f2tf(pa[it].x); ap[1] = f2tf(pa[it].y);
            ap[2] = f2tf(pa[it].z); ap[3] = f2tf(pa[it].w);
            uint32_t* bp = &Bs[(bk + it * 16) * 72 + bn4 * 4];
            bp[0] = f2tf(pb[it].x); bp[1] = f2tf(pb[it].y);
            bp[2] = f2tf(pb[it].z); bp[3] = f2tf(pb[it].w);
        }
        __syncthreads();
        if (kt + 32 < K) {
            #pragma unroll
            for (int it = 0; it < 2; it++) {
                pa[it] = *(const float4*)(A + (size_t)(m0 + am + it * 32) * K + kt + 32 + akq * 4);
                pb[it] = *(const float4*)(B + (size_t)(kt + 32 + bk + it * 16) * Nn + n0 + bn4 * 4);
            }
        }
        #pragma unroll
        for (int k8 = 0; k8 < 32; k8 += 8) {
            uint32_t a[4] = {As[(wm + g) * 36 + k8 + t],     As[(wm + g + 8) * 36 + k8 + t],
                             As[(wm + g) * 36 + k8 + t + 4], As[(wm + g + 8) * 36 + k8 + t + 4]};
            #pragma unroll
            for (int nt = 0; nt < 4; nt++) {
                uint32_t b[2] = {Bs[(k8 + t) * 72 + wn + nt * 8 + g],
                                 Bs[(k8 + t + 4) * 72 + wn + nt * 8 + g]};
                mma_tf32(acc[nt], a, b);
            }
        }
    }
    #pragma unroll
    for (int nt = 0; nt < 4; nt++) {
        int col = n0 + wn + nt * 8 + t * 2;
        #pragma unroll
        for (int half = 0; half < 2; half++) {
            int row = m0 + wm + g + half * 8;
            float v0 = sigm(acc[nt][half * 2 + 0] + bias[col]);
            float v1 = sigm(acc[nt][half * 2 + 1] + bias[col + 1]);
            C[(size_t)row * Nn + col]     = v0;
            C[(size_t)row * Nn + col + 1] = v1;
        }
    }
}

// --- pairbias: PERSISTENT + register-prefetch pipeline ---
__device__ __noinline__ void pairbias_body(uint32_t* shm, int blk, int nblk,
                                           const float* __restrict__ pair,
                                           const float* __restrict__ beta,
                                           const float* __restrict__ w,
                                           const float* __restrict__ b,
                                           const float* __restrict__ Wb,
                                           float* __restrict__ bias) {
    uint32_t* As = shm;             // [64*140]
    uint32_t* Bs = shm + 64 * 140;  // [128*24]

    int tid = threadIdx.x, lane = tid & 31, warp = tid >> 5;
    int r  = tid >> 2;
    int pq = tid & 3;
    int g = lane >> 2, t = lane & 3;
    int wm = (warp & 3) * 16;
    int hh = (warp >> 2) * 8;
    const int NT = NN / 64;         // 9216 tiles

    // Wb -> Bs once per block
    for (int i = tid; i < P_ * H_; i += 256) {
        int kk = i >> 4, nn = i & 15;
        Bs[kk * 24 + nn] = f2tf(__ldg(Wb + i));
    }

    int tile = blk;
    float4 u[4][2];
    {
        const float* row = pair + ((size_t)tile * 64 + r) * P_;
        #pragma unroll
        for (int j = 0; j < 4; j++) {
            u[j][0] = *(const float4*)(row + 8 * pq + 32 * j);
            u[j][1] = *(const float4*)(row + 8 * pq + 32 * j + 4);
        }
    }

    bool first = true;
    for (; tile < NT; tile += nblk) {
        int tn = tile + nblk;
        // prefetch next tile into registers (overlaps LN/mma/stores below)
        float4 un[4][2];
        if (tn < NT) {
            const float* rown = pair + ((size_t)tn * 64 + r) * P_;
            #pragma unroll
            for (int j = 0; j < 4; j++) {
                un[j][0] = *(const float4*)(rown + 8 * pq + 32 * j);
                un[j][1] = *(const float4*)(rown + 8 * pq + 32 * j + 4);
            }
        }
        int p0 = tile * 64;
        float be0 = __ldg(beta + p0 + wm + g);
        float be1 = __ldg(beta + p0 + wm + g + 8);

        // LN stats
        float s = 0.f, s2 = 0.f;
        #pragma unroll
        for (int j = 0; j < 4; j++)
            #pragma unroll
            for (int h2 = 0; h2 < 2; h2++) {
                const float4 f = u[j][h2];
                s  += f.x + f.y + f.z + f.w;
                s2 += f.x * f.x + f.y * f.y + f.z * f.z + f.w * f.w;
            }
        s  += __shfl_xor_sync(0xffffffffu, s, 1);  s  += __shfl_xor_sync(0xffffffffu, s, 2);
        s2 += __shfl_xor_sync(0xffffffffu, s2, 1); s2 += __shfl_xor_sync(0xffffffffu, s2, 2);
        float mean = s * (1.f / P_);
        float var  = s2 * (1.f / P_) - mean * mean;
        float rs   = rsqrtf(var + 1e-5f);

        if (!first) __syncthreads();   // prev iter's mma must finish before As overwrite

        // normalize * w + b -> tf32 smem
        #pragma unroll
        for (int j = 0; j < 4; j++) {
            int c0 = 8 * pq + 32 * j;
            #pragma unroll
            for (int h2 = 0; h2 < 2; h2++) {
                const float4 wv = *(const float4*)(w + c0 + 4 * h2);
                const float4 bv = *(const float4*)(b + c0 + 4 * h2);
                const float4 f  = u[j][h2];
                uint4 pkt;
                pkt.x = f2tf((f.x - mean) * rs * wv.x + bv.x);
                pkt.y = f2tf((f.y - mean) * rs * wv.y + bv.y);
                pkt.z = f2tf((f.z - mean) * rs * wv.z + bv.z);
                pkt.w = f2tf((f.w - mean) * rs * wv.w + bv.w);
                *(uint4*)&As[r * 140 + c0 + 4 * h2] = pkt;
            }
        }
        __syncthreads();

        // mma: warp -> 16 rows x 8 heads
        float acc[4] = {0.f, 0.f, 0.f, 0.f};
        #pragma unroll
        for (int k8 = 0; k8 < 16; k8++) {
            int k = k8 * 8;
            uint32_t a[4] = {As[(wm + g) * 140 + k + t],     As[(wm + g + 8) * 140 + k + t],
                             As[(wm + g) * 140 + k + t + 4], As[(wm + g + 8) * 140 + k + t + 4]};
            uint32_t bb[2] = {Bs[(k + t) * 24 + hh + g], Bs[(k + t + 4) * 24 + hh + g]};
            mma_tf32(acc, a, bb);
        }

        int pr0 = p0 + wm + g, pr1 = pr0 + 8;
        int h0 = hh + 2 * t;
        bias[(size_t)(h0)     * NN + pr0] = acc[0] + be0;
        bias[(size_t)(h0 + 1) * NN + pr0] = acc[1] + be0;
        bias[(size_t)(h0)     * NN + pr1] = acc[2] + be1;
        bias[(size_t)(h0 + 1) * NN + pr1] = acc[3] + be1;

        first = false;
        #pragma unroll
        for (int j = 0; j < 4; j++) {
            u[j][0] = un[j][0]; u[j][1] = un[j][1];
        }
    }
}

#define FUSED_SMEM ((64*140 + 128*24)*4)
#define NPB 592

__global__ __launch_bounds__(256) void fused_mid(
    const float* __restrict__ A2,
    const float* __restrict__ Wq, const float* __restrict__ bq,
    const float* __restrict__ Wk, const float* __restrict__ Wv,
    const float* __restrict__ Wg,
    float* __restrict__ oq, float* __restrict__ ok,
    float* __restrict__ ov, float* __restrict__ og,
    const float* __restrict__ sIn, const float* __restrict__ Wout,
    const float* __restrict__ bout, float* __restrict__ gate,
    const float* __restrict__ pair, const float* __restrict__ beta,
    const float* __restrict__ lnpw, const float* __restrict__ lnpb,
    const float* __restrict__ Wb, float* __restrict__ bias) {
    extern __shared__ __align__(16) uint32_t shm[];
    int bx = blockIdx.x;
    if (bx < 144) {
        qkvg2_body(shm, bx % 12, bx / 12, 0, A2, bq, Wq, Wk, oq, ok);
    } else if (bx < 288) {
        int i = bx - 144;
        qkvg2_body(shm, i % 12, i / 12, 1, A2, bq, Wv, Wg, ov, og);
    } else if (bx < 432) {
        int i = bx - 288;
        gate_body(shm, i % 12, i / 12, sIn, Wout, bout, gate);
    } else {
        pairbias_body(shm, bx - 432, NPB, pair, beta, lnpw, lnpb, Wb, bias);
    }
}

// ---------------- flash attention, split-KV x2, 64 q-rows / 4 warps ----------------
#define AQ(r,c) smQ[(r)*52+(c)]
#define AK(r,c) smK[(r)*52+(c)]
#define AV(r,c) smV[(r)*56+(c)]
#define AP(r,c) smP[(r)*68+(c)]
#define ATTN_SMEM (64*(52+52+56+68)*4)

__global__ __launch_bounds__(128) void attn_tf32(const float* __restrict__ q,
                                                 const float* __restrict__ k,
                                                 const float* __restrict__ v,
                                                 const float* __restrict__ bias,
                                                 float* __restrict__ opart,
                                                 float2* __restrict__ mlv) {
    extern __shared__ uint32_t sm[];
    uint32_t* smQ = sm;
    uint32_t* smK = smQ + 64 * 52;
    uint32_t* smV = smK + 64 * 52;
    uint32_t* smP = smV + 64 * 56;

    int h  = blockIdx.y;
    int q0 = blockIdx.x * 64;
    int sidx = blockIdx.z;
    int s0 = sidx * (N_ / 2);
    int tid = threadIdx.x, lane = tid & 31, warp = tid >> 5;
    int g = lane >> 2, t = lane & 3;
    int wm = warp * 16;

    #pragma unroll
    for (int it = 0; it < 6; it++) {
        int idx = tid + it * 128;
        int r = idx / 12, c4 = idx % 12;
        float4 v4 = *(const float4*)(q + (size_t)(q0 + r) * A_ + h * D_ + c4 * 4);
        AQ(r, c4 * 4 + 0) = f2tf(v4.x); AQ(r, c4 * 4 + 1) = f2tf(v4.y);
        AQ(r, c4 * 4 + 2) = f2tf(v4.z); AQ(r, c4 * 4 + 3) = f2tf(v4.w);
    }

    float m0 = -1e30f, m1 = -1e30f, l0 = 0.f, l1 = 0.f;
    float oacc[6][4];
    #pragma unroll
    for (int dt = 0; dt < 6; dt++)
        #pragma unroll
        for (int e = 0; e < 4; e++) oacc[dt][e] = 0.f;

    const float scale = 0.144337567f;

    for (int j0 = s0; j0 < s0 + N_ / 2; j0 += 64) {
        __syncthreads();

        const float* bp0 = bias + (size_t)h * NN + (size_t)(q0 + wm + g) * N_ + j0;
        const float* bp1 = bp0 + 8 * N_;
        float2 bpre0[8], bpre1[8];
        #pragma unroll
        for (int nt = 0; nt < 8; nt++) {
            bpre0[nt] = *(const float2*)(bp0 + nt * 8 + 2 * t);
            bpre1[nt] = *(const float2*)(bp1 + nt * 8 + 2 * t);
        }

        #pragma unroll
        for (int it = 0; it < 6; it++) {
            int idx = tid + it * 128;
            int r = idx / 12, c4 = idx % 12;
            float4 kv = *(const float4*)(k + (size_t)(j0 + r) * A_ + h * D_ + c4 * 4);
            AK(r, c4 * 4 + 0) = f2tf(kv.x); AK(r, c4 * 4 + 1) = f2tf(kv.y);
            AK(r, c4 * 4 + 2) = f2tf(kv.z); AK(r, c4 * 4 + 3) = f2tf(kv.w);
            float4 vv = *(const float4*)(v + (size_t)(j0 + r) * A_ + h * D_ + c4 * 4);
            AV(r, c4 * 4 + 0) = f2tf(vv.x); AV(r, c4 * 4 + 1) = f2tf(vv.y);
            AV(r, c4 * 4 + 2) = f2tf(vv.z); AV(r, c4 * 4 + 3) = f2tf(vv.w);
        }
        __syncthreads();

        float sacc[8][4];
        #pragma unroll
        for (int nt = 0; nt < 8; nt++)
            #pragma unroll
            for (int e = 0; e < 4; e++) sacc[nt][e] = 0.f;

        #pragma unroll
        for (int k8 = 0; k8 < 48; k8 += 8) {
            uint32_t a[4] = {AQ(wm + g, k8 + t),     AQ(wm + g + 8, k8 + t),
                             AQ(wm + g, k8 + t + 4), AQ(wm + g + 8, k8 + t + 4)};
            #pragma unroll
            for (int nt = 0; nt < 8; nt++) {
                uint32_t b[2] = {AK(nt * 8 + g, k8 + t), AK(nt * 8 + g, k8 + t + 4)};
                mma_tf32(sacc[nt], a, b);
            }
        }

        #pragma unroll
        for (int nt = 0; nt < 8; nt++) {
            sacc[nt][0] = sacc[nt][0] * scale + bpre0[nt].x;
            sacc[nt][1] = sacc[nt][1] * scale + bpre0[nt].y;
            sacc[nt][2] = sacc[nt][2] * scale + bpre1[nt].x;
            sacc[nt][3] = sacc[nt][3] * scale + bpre1[nt].y;
        }

        float mx0 = -1e30f, mx1 = -1e30f;
        #pragma unroll
        for (int nt = 0; nt < 8; nt++) {
            mx0 = fmaxf(mx0, fmaxf(sacc[nt][0], sacc[nt][1]));
            mx1 = fmaxf(mx1, fmaxf(sacc[nt][2], sacc[nt][3]));
        }
        mx0 = fmaxf(mx0, __shfl_xor_sync(0xffffffffu, mx0, 1));
        mx0 = fmaxf(mx0, __shfl_xor_sync(0xffffffffu, mx0, 2));
        mx1 = fmaxf(mx1, __shfl_xor_sync(0xffffffffu, mx1, 1));
        mx1 = fmaxf(mx1, __shfl_xor_sync(0xffffffffu, mx1, 2));
        float mn0 = fmaxf(m0, mx0), mn1 = fmaxf(m1, mx1);
        float cr0 = __expf(m0 - mn0), cr1 = __expf(m1 - mn1);
        m0 = mn0; m1 = mn1;

        float s0r = 0.f, s1r = 0.f;
        #pragma unroll
        for (int nt = 0; nt < 8; nt++) {
            float p00 = __expf(sacc[nt][0] - mn0);
            float p01 = __expf(sacc[nt][1] - mn0);
            float p10 = __expf(sacc[nt][2] - mn1);
            float p11 = __expf(sacc[nt][3] - mn1);
            s0r += p00 + p01; s1r += p10 + p11;
            int c = nt * 8 + 2 * t;
            AP(wm + g, c)         = f2tf(p00);
            AP(wm + g, c + 1)     = f2tf(p01);
            AP(wm + g + 8, c)     = f2tf(p10);
            AP(wm + g + 8, c + 1) = f2tf(p11);
        }
        s0r += __shfl_xor_sync(0xffffffffu, s0r, 1);
        s0r += __shfl_xor_sync(0xffffffffu, s0r, 2);
        s1r += __shfl_xor_sync(0xffffffffu, s1r, 1);
        s1r += __shfl_xor_sync(0xffffffffu, s1r, 2);
        l0 = l0 * cr0 + s0r;
        l1 = l1 * cr1 + s1r;

        #pragma unroll
        for (int dt = 0; dt < 6; dt++) {
            oacc[dt][0] *= cr0; oacc[dt][1] *= cr0;
            oacc[dt][2] *= cr1; oacc[dt][3] *= cr1;
        }
        __syncwarp();

        #pragma unroll
        for (int k8 = 0; k8 < 64; k8 += 8) {
            uint32_t a[4] = {AP(wm + g, k8 + t),     AP(wm + g + 8, k8 + t),
                             AP(wm + g, k8 + t + 4), AP(wm + g + 8, k8 + t + 4)};
            #pragma unroll
            for (int dt = 0; dt < 6; dt++) {
                uint32_t b[2] = {AV(k8 + t, dt * 8 + g), AV(k8 + t + 4, dt * 8 + g)};
                mma_tf32(oacc[dt], a, b);
            }
        }
    }

    float* op = opart + (size_t)sidx * N_ * A_;
    int r0 = q0 + wm + g, r1 = r0 + 8;
    #pragma unroll
    for (int dt = 0; dt < 6; dt++) {
        int d = dt * 8 + 2 * t;
        size_t i00 = (size_t)r0 * A_ + h * D_ + d;
        size_t i10 = (size_t)r1 * A_ + h * D_ + d;
        op[i00]     = oacc[dt][0];
        op[i00 + 1] = oacc[dt][1];
        op[i10]     = oacc[dt][2];
        op[i10 + 1] = oacc[dt][3];
    }
    if (t == 0) {
        mlv[(size_t)sidx * H_ * N_ + h * N_ + r0] = make_float2(m0, l0);
        mlv[(size_t)sidx * H_ * N_ + h * N_ + r1] = make_float2(m1, l1);
    }
}

// ---------------- merge split-KV partials + gate ----------------
__global__ __launch_bounds__(256) void attn_merge(const float* __restrict__ op,
                                                  const float2* __restrict__ ml,
                                                  const float* __restrict__ gt,
                                                  float* __restrict__ o) {
    int idx = blockIdx.x * 256 + threadIdx.x;
    int n  = idx / 192;
    int c4 = idx - n * 192;
    int h  = c4 / 12;
    float2 ml1 = ml[h * N_ + n];
    float2 ml2 = ml[H_ * N_ + h * N_ + n];
    float m  = fmaxf(ml1.x, ml2.x);
    float w1 = __expf(ml1.x - m), w2 = __expf(ml2.x - m);
    float inv = 1.f / (w1 * ml1.y + w2 * ml2.y);
    size_t off = (size_t)n * A_ + c4 * 4;
    const float4 a1 = *(const float4*)(op + off);
    const float4 a2 = *(const float4*)(op + (size_t)N_ * A_ + off);
    const float4 g4 = *(const float4*)(gt + off);
    float4 r;
    r.x = (w1 * a1.x + w2 * a2.x) * inv * g4.x;
    r.y = (w1 * a1.y + w2 * a2.y) * inv * g4.y;
    r.z = (w1 * a1.z + w2 * a2.z) * inv * g4.z;
    r.w = (w1 * a1.w + w2 * a2.w) * inv * g4.w;
    *(float4*)(o + off) = r;
}

// ---------------- launch ----------------
extern "C" void kernel_launch(void* const* d_in, const int* in_sizes, int n_in,
                              void* d_out, int out_size) {
    const float* a       = (const float*)d_in[0];
    const float* s       = (const float*)d_in[1];
    const float* pair    = (const float*)d_in[2];
    const float* beta    = (const float*)d_in[3];
    const float* ln_s_w  = (const float*)d_in[4];
    const float* gamma_w = (const float*)d_in[5];
    const float* gamma_b = (const float*)d_in[6];
    const float* shift_w = (const float*)d_in[7];
    const float* Wq      = (const float*)d_in[8];
    const float* bq      = (const float*)d_in[9];
    const float* Wk      = (const float*)d_in[10];
    const float* Wv      = (const float*)d_in[11];
    const float* ln_p_w  = (const float*)d_in[12];
    const float* ln_p_b  = (const float*)d_in[13];
    const float* Wb      = (const float*)d_in[14];
    const float* Wg      = (const float*)d_in[15];
    const float* Wp      = (const float*)d_in[16];
    const float* Wout    = (const float*)d_in[17];
    const float* bout    = (const float*)d_in[18];
    float* out = (float*)d_out;

    float *p_sn, *p_an, *p_a2, *p_q, *p_k, *p_v, *p_gt, *p_bias, *p_o, *p_gate, *p_opart;
    float2 *p_ml;
    cudaGetSymbolAddress((void**)&p_sn,    d_sn);
    cudaGetSymbolAddress((void**)&p_an,    d_an);
    cudaGetSymbolAddress((void**)&p_a2,    d_a2);
    cudaGetSymbolAddress((void**)&p_q,     d_q);
    cudaGetSymbolAddress((void**)&p_k,     d_k);
    cudaGetSymbolAddress((void**)&p_v,     d_v);
    cudaGetSymbolAddress((void**)&p_gt,    d_gt);
    cudaGetSymbolAddress((void**)&p_bias,  d_bias);
    cudaGetSymbolAddress((void**)&p_o,     d_o);
    cudaGetSymbolAddress((void**)&p_gate,  d_gate);
    cudaGetSymbolAddress((void**)&p_opart, d_opart);
    cudaGetSymbolAddress((void**)&p_ml,    d_ml);

    cudaFuncSetAttribute(attn_tf32,  cudaFuncAttributeMaxDynamicSharedMemorySize, ATTN_SMEM);
    cudaFuncSetAttribute(fused_mid,  cudaFuncAttributeMaxDynamicSharedMemorySize, FUSED_SMEM);

    dim3 g2(A_ / 64, N_ / 64);

    ln2_kernel<<<dim3(N_, 2), 256>>>(s, ln_s_w, p_sn, a, p_an);
    adaln_tf32<<<g2, 256>>>(p_sn, gamma_w, gamma_b, shift_w, p_an, p_a2);
    fused_mid<<<432 + NPB, 256, FUSED_SMEM>>>(
        p_a2, Wq, bq, Wk, Wv, Wg, p_q, p_k, p_v, p_gt,
        s, Wout, bout, p_gate,
        pair, beta, ln_p_w, ln_p_b, Wb, p_bias);
    dim3 ga(N_ / 64, H_, 2);
    attn_tf32<<<ga, 128, ATTN_SMEM>>>(p_q, p_k, p_v, p_bias, p_opart, p_ml);
    attn_merge<<<576, 256>>>(p_opart, p_ml, p_gt, p_o);
    gemm_tf32<4><<<g2, 256>>>(p_o, Wp, out, A_, A_, nullptr, p_gate);
}